// round 9
// baseline (speedup 1.0000x reference)
#include <cuda_runtime.h>
#include <cstdint>

#define NMAX 50048
#define EMAX 250112
#define TT 3

// ---------------- scratch (static device globals; no allocation) ----------------
__device__ float g_hcat[TT * NMAX * 256];   // per-type h = x @ W[t]
__device__ float g_h1[NMAX * 256];          // layer-1 output
__device__ float g_as[TT * NMAX];           // a_src per type (atomic-accumulated)
__device__ float g_ad[TT * NMAX];           // a_dst per type
__device__ int   g_cnt[TT * NMAX];
__device__ int   g_cur[TT * NMAX];
__device__ int   g_off[TT * (NMAX + 1)];
__device__ int   g_csr[TT * EMAX];

// ---------------- small float4 helpers ----------------
__device__ __forceinline__ float4 f4add(float4 a, float4 b) {
    return make_float4(a.x + b.x, a.y + b.y, a.z + b.z, a.w + b.w);
}
__device__ __forceinline__ float4 f4fma(float4 a, float s, float4 c) {
    return make_float4(fmaf(a.x, s, c.x), fmaf(a.y, s, c.y),
                       fmaf(a.z, s, c.z), fmaf(a.w, s, c.w));
}
__device__ __forceinline__ float4 f4relu(float4 a) {
    return make_float4(fmaxf(a.x, 0.f), fmaxf(a.y, 0.f),
                       fmaxf(a.z, 0.f), fmaxf(a.w, 0.f));
}

// ============ fused GEMM + attention dots ============
// Hcat[t][n][256] = X[n][256] @ W[t][256][256];  as_out[t][n] += h_n . a_s[t] (partial)
// BM=128, BN=128, BK=32, 3-stage cp.async, tf32 mma.sync on raw fp32 bits.
// 8 warps: 4 in M x 2 in N, warp tile 32x64. grid = (ceil(n/128), 6).
#define APITCH 36
#define BPITCH 136
#define ASTG   (128 * APITCH)
#define BSTG   (32 * BPITCH)
#define NSTAGE 3
#define GSMEM  (NSTAGE * (ASTG + BSTG) * 4)

__global__ __launch_bounds__(256) void gemm_fused(
    const float* __restrict__ X, const float* __restrict__ W,
    float* __restrict__ Hcat,
    const float* __restrict__ as_full, const float* __restrict__ ad_full,
    float* __restrict__ as_out, float* __restrict__ ad_out, int nrows)
{
    extern __shared__ uint32_t dsm[];
    uint32_t* As = dsm;                   // [NSTAGE][ASTG]
    uint32_t* Bs = dsm + NSTAGE * ASTG;   // [NSTAGE][BSTG]

    int tid  = threadIdx.x;
    int lane = tid & 31, warp = tid >> 5;
    int wm = warp >> 1, wn = warp & 1;
    int g  = lane >> 2, tig = lane & 3;
    int bm = blockIdx.x * 128;
    int t  = blockIdx.y >> 1;
    int bn = (blockIdx.y & 1) * 128;
    const float* Wt = W + (size_t)t * 65536;
    float* Hout = Hcat + (size_t)t * nrows * 256;

    auto stage = [&](int st, int k0) {
#pragma unroll
        for (int p = 0; p < 4; p++) {            // A: 128 rows x 8 groups of 16B
            int i = tid + p * 256;
            int r = i >> 3, grp = i & 7;
            uint32_t d = (uint32_t)__cvta_generic_to_shared(
                &As[st * ASTG + r * APITCH + grp * 4]);
            const float* s = X + (size_t)(bm + r) * 256 + k0 + grp * 4;
            int sz = (bm + r) < nrows ? 16 : 0;
            asm volatile("cp.async.ca.shared.global [%0], [%1], 16, %2;"
                         :: "r"(d), "l"(s), "r"(sz));
        }
#pragma unroll
        for (int p = 0; p < 4; p++) {            // B: 32 rows x 32 groups of 16B
            int i = tid + p * 256;
            int r = i >> 5, grp = i & 31;
            uint32_t d = (uint32_t)__cvta_generic_to_shared(
                &Bs[st * BSTG + r * BPITCH + grp * 4]);
            const float* s = Wt + (size_t)(k0 + r) * 256 + bn + grp * 4;
            asm volatile("cp.async.ca.shared.global [%0], [%1], 16;"
                         :: "r"(d), "l"(s));
        }
        asm volatile("cp.async.commit_group;");
    };

    float acc[2][8][4];
#pragma unroll
    for (int a = 0; a < 2; a++)
#pragma unroll
        for (int b = 0; b < 8; b++)
#pragma unroll
            for (int c = 0; c < 4; c++) acc[a][b][c] = 0.f;

    stage(0, 0);
    stage(1, 32);
    for (int c = 0; c < 8; c++) {
        if (c + 2 < 8) {
            stage((c + 2) % NSTAGE, (c + 2) * 32);
            asm volatile("cp.async.wait_group 2;");
        } else if (c + 1 < 8) {
            asm volatile("cp.async.wait_group 1;");
        } else {
            asm volatile("cp.async.wait_group 0;");
        }
        __syncthreads();

        int cur = c % NSTAGE;
        const uint32_t* Ac = As + cur * ASTG;
        const uint32_t* Bc = Bs + cur * BSTG;
#pragma unroll
        for (int kk = 0; kk < 32; kk += 8) {
            uint32_t a[2][4], b[8][2];
#pragma unroll
            for (int mm = 0; mm < 2; mm++) {
                int row = wm * 32 + mm * 16 + g;
                a[mm][0] = Ac[row * APITCH + kk + tig];
                a[mm][1] = Ac[(row + 8) * APITCH + kk + tig];
                a[mm][2] = Ac[row * APITCH + kk + tig + 4];
                a[mm][3] = Ac[(row + 8) * APITCH + kk + tig + 4];
            }
#pragma unroll
            for (int nn = 0; nn < 8; nn++) {
                int col = wn * 64 + nn * 8 + g;
                b[nn][0] = Bc[(kk + tig) * BPITCH + col];
                b[nn][1] = Bc[(kk + tig + 4) * BPITCH + col];
            }
#pragma unroll
            for (int mm = 0; mm < 2; mm++)
#pragma unroll
                for (int nn = 0; nn < 8; nn++)
                    asm volatile(
                        "mma.sync.aligned.m16n8k8.row.col.f32.tf32.tf32.f32 "
                        "{%0,%1,%2,%3}, {%4,%5,%6,%7}, {%8,%9}, {%0,%1,%2,%3};"
                        : "+f"(acc[mm][nn][0]), "+f"(acc[mm][nn][1]),
                          "+f"(acc[mm][nn][2]), "+f"(acc[mm][nn][3])
                        : "r"(a[mm][0]), "r"(a[mm][1]), "r"(a[mm][2]), "r"(a[mm][3]),
                          "r"(b[nn][0]), "r"(b[nn][1]));
        }
        __syncthreads();
    }

    // ---- store H tile ----
#pragma unroll
    for (int mm = 0; mm < 2; mm++)
#pragma unroll
        for (int nn = 0; nn < 8; nn++) {
            int row = bm + wm * 32 + mm * 16 + g;
            int col = bn + wn * 64 + nn * 8 + 2 * tig;
            if (row < nrows)
                *(float2*)(Hout + (size_t)row * 256 + col) =
                    make_float2(acc[mm][nn][0], acc[mm][nn][1]);
            if (row + 8 < nrows)
                *(float2*)(Hout + (size_t)(row + 8) * 256 + col) =
                    make_float2(acc[mm][nn][2], acc[mm][nn][3]);
        }

    // ---- fused attention dots: partial h.a_s / h.a_d over this CTA's 128 cols ----
    {
        const float* avs = as_full + t * 256;
        const float* avd = ad_full + t * 256;
        float ds[2][2] = {{0.f, 0.f}, {0.f, 0.f}};
        float dd[2][2] = {{0.f, 0.f}, {0.f, 0.f}};
#pragma unroll
        for (int mm = 0; mm < 2; mm++)
#pragma unroll
            for (int nn = 0; nn < 8; nn++) {
                int col = bn + wn * 64 + nn * 8 + 2 * tig;
                float a0 = __ldg(&avs[col]), a1 = __ldg(&avs[col + 1]);
                float d0 = __ldg(&avd[col]), d1 = __ldg(&avd[col + 1]);
                ds[mm][0] += acc[mm][nn][0] * a0 + acc[mm][nn][1] * a1;
                ds[mm][1] += acc[mm][nn][2] * a0 + acc[mm][nn][3] * a1;
                dd[mm][0] += acc[mm][nn][0] * d0 + acc[mm][nn][1] * d1;
                dd[mm][1] += acc[mm][nn][2] * d0 + acc[mm][nn][3] * d1;
            }
        // reduce over the 4 tig lanes (same g -> same rows)
#pragma unroll
        for (int o = 1; o <= 2; o <<= 1)
#pragma unroll
            for (int mm = 0; mm < 2; mm++)
#pragma unroll
                for (int h = 0; h < 2; h++) {
                    ds[mm][h] += __shfl_xor_sync(0xffffffffu, ds[mm][h], o);
                    dd[mm][h] += __shfl_xor_sync(0xffffffffu, dd[mm][h], o);
                }
        if (tig == 0) {
            float* aso = as_out + (size_t)t * nrows;
            float* ado = ad_out + (size_t)t * nrows;
#pragma unroll
            for (int mm = 0; mm < 2; mm++)
#pragma unroll
                for (int h = 0; h < 2; h++) {
                    int row = bm + wm * 32 + mm * 16 + g + h * 8;
                    if (row < nrows) {
                        atomicAdd(&aso[row], ds[mm][h]);
                        atomicAdd(&ado[row], dd[mm][h]);
                    }
                }
        }
    }
}

// ============ zero attention-dot accumulators ============
__global__ void zero_asad(float* __restrict__ a, float* __restrict__ b, int total) {
    int i = blockIdx.x * blockDim.x + threadIdx.x;
    if (i < total) { a[i] = 0.f; b[i] = 0.f; }
}

// ============ CSR build (once; graph shared by both layers) ============
__global__ void zero_counts(int* __restrict__ cnt, int* __restrict__ cur, int total) {
    int i = blockIdx.x * blockDim.x + threadIdx.x;
    if (i < total) { cnt[i] = 0; cur[i] = 0; }
}

__global__ void hist_kernel(const int* __restrict__ ei, int* __restrict__ cnt,
                            int n, int ne)
{
    int i = blockIdx.x * blockDim.x + threadIdx.x;
    if (i >= TT * ne) return;
    int t = i / ne, e = i - t * ne;
    int d = ei[(size_t)t * 2 * ne + ne + e];
    atomicAdd(&cnt[t * n + d], 1);
}

__global__ __launch_bounds__(1024) void scan_off(
    const int* __restrict__ cnt, int* __restrict__ off, int n)
{
    int t = blockIdx.x;
    const int* c = cnt + t * n;
    int* o = off + t * (n + 1);
    __shared__ int wsum[32];
    __shared__ int carry_sh;
    int tid = threadIdx.x, lane = tid & 31, wid = tid >> 5;
    if (tid == 0) carry_sh = 0;
    __syncthreads();
    for (int base = 0; base < n; base += 1024) {
        int i = base + tid;
        int v = (i < n) ? c[i] : 0;
        int x = v;
#pragma unroll
        for (int o2 = 1; o2 < 32; o2 <<= 1) {
            int y = __shfl_up_sync(0xffffffffu, x, o2);
            if (lane >= o2) x += y;
        }
        if (lane == 31) wsum[wid] = x;
        __syncthreads();
        if (wid == 0) {
            int s = wsum[lane];
#pragma unroll
            for (int o2 = 1; o2 < 32; o2 <<= 1) {
                int y = __shfl_up_sync(0xffffffffu, s, o2);
                if (lane >= o2) s += y;
            }
            wsum[lane] = s;
        }
        __syncthreads();
        int incl  = x + (wid > 0 ? wsum[wid - 1] : 0);
        int carry = carry_sh;
        if (i < n) o[i] = carry + incl - v;
        __syncthreads();
        if (tid == 1023) carry_sh = carry + wsum[31];
        __syncthreads();
    }
    if (threadIdx.x == 0) o[n] = carry_sh;
}

__global__ void fill_kernel(const int* __restrict__ ei, const int* __restrict__ off,
                            int* __restrict__ cur, int* __restrict__ csr,
                            int n, int ne)
{
    int i = blockIdx.x * blockDim.x + threadIdx.x;
    if (i >= TT * ne) return;
    int t = i / ne, e = i - t * ne;
    const int* base = ei + (size_t)t * 2 * ne;
    int s = base[e], d = base[ne + e];
    int pos = off[t * (n + 1) + d] + atomicAdd(&cur[t * n + d], 1);
    csr[t * ne + pos] = s;
}

// ============ fused softmax + aggregate + bias + relu (+ head) : warp per dst ============
__global__ __launch_bounds__(256) void agg_kernel(
    const int* __restrict__ off, const int* __restrict__ csr,
    const float* __restrict__ hcat, const float* __restrict__ asb,
    const float* __restrict__ adb, const float* __restrict__ bias,
    float* __restrict__ outrow, const float* __restrict__ Wh,
    const float* __restrict__ bh, float* __restrict__ headout,
    int mode, int n, int ne)
{
    int w    = (blockIdx.x * blockDim.x + threadIdx.x) >> 5;
    int lane = threadIdx.x & 31;
    if (w >= n) return;

    float4 a0 = make_float4(0.f, 0.f, 0.f, 0.f);
    float4 a1 = make_float4(0.f, 0.f, 0.f, 0.f);

#pragma unroll
    for (int t = 0; t < TT; t++) {
        int o0 = off[t * (n + 1) + w];
        int deg = off[t * (n + 1) + w + 1] - o0;
        if (deg == 0) continue;
        float adt = adb[t * n + w];
        const float* ht   = hcat + (size_t)t * n * 256;
        const float* ast  = asb + t * n;
        const int*   srcs = csr + (size_t)t * ne + o0;
        float4 t0 = make_float4(0.f, 0.f, 0.f, 0.f);
        float4 t1 = make_float4(0.f, 0.f, 0.f, 0.f);
        float den = 0.f;
        for (int base = 0; base < deg; base += 32) {
            int m = min(32, deg - base);
            int   sj = 0;
            float ex = 0.f;
            if (lane < m) {
                sj = srcs[base + lane];
                float e = ast[sj] + adt;
                e = e > 0.f ? e : 0.2f * e;      // leaky_relu 0.2
                ex = __expf(e);                   // shift-invariant: no max needed
            }
            float s = ex;
#pragma unroll
            for (int o = 16; o; o >>= 1) s += __shfl_xor_sync(0xffffffffu, s, o);
            den += s;
            for (int j = 0; j < m; j++) {
                int   sn = __shfl_sync(0xffffffffu, sj, j);
                float wt = __shfl_sync(0xffffffffu, ex, j);
                const float4* hr = (const float4*)(ht + (size_t)sn * 256);
                t0 = f4fma(hr[lane], wt, t0);
                t1 = f4fma(hr[lane + 32], wt, t1);
            }
        }
        float inv = 1.f / den;
        a0 = f4fma(t0, inv, a0);
        a1 = f4fma(t1, inv, a1);
    }

    const float4* bb = (const float4*)bias;
    float4 b0 = f4add(f4add(__ldg(&bb[lane]), __ldg(&bb[64 + lane])), __ldg(&bb[128 + lane]));
    float4 b1 = f4add(f4add(__ldg(&bb[lane + 32]), __ldg(&bb[96 + lane])), __ldg(&bb[160 + lane]));
    float4 r0 = f4relu(f4add(a0, b0));
    float4 r1 = f4relu(f4add(a1, b1));

    if (mode == 0) {
        float4* orow = (float4*)(outrow + (size_t)w * 256);
        orow[lane]      = r0;
        orow[lane + 32] = r1;
    } else {
        const float4* wh = (const float4*)Wh;
        float4 q0 = __ldg(&wh[lane]);
        float4 q1 = __ldg(&wh[lane + 32]);
        float s = r0.x * q0.x + r0.y * q0.y + r0.z * q0.z + r0.w * q0.w +
                  r1.x * q1.x + r1.y * q1.y + r1.z * q1.z + r1.w * q1.w;
#pragma unroll
        for (int o = 16; o; o >>= 1) s += __shfl_xor_sync(0xffffffffu, s, o);
        if (lane == 0) headout[w] = 1.f / (1.f + __expf(-(s + bh[0])));
    }
}

// ---------------- host orchestration ----------------
extern "C" void kernel_launch(void* const* d_in, const int* in_sizes, int n_in,
                              void* d_out, int out_size)
{
    const float* z   = (const float*)d_in[0];
    const int*   ei  = (const int*)d_in[1];
    const float* W1  = (const float*)d_in[2];
    const float* as1 = (const float*)d_in[3];
    const float* ad1 = (const float*)d_in[4];
    const float* b1  = (const float*)d_in[5];
    const float* W2  = (const float*)d_in[6];
    const float* as2 = (const float*)d_in[7];
    const float* ad2 = (const float*)d_in[8];
    const float* b2  = (const float*)d_in[9];
    const float* Wh  = (const float*)d_in[10];
    const float* bh  = (const float*)d_in[11];
    float* out = (float*)d_out;

    int n  = in_sizes[0] / 256;   // 50000
    int ne = in_sizes[1] / 6;     // 250000

    void* p;
    cudaGetSymbolAddress(&p, g_hcat); float* hcat = (float*)p;
    cudaGetSymbolAddress(&p, g_h1);   float* h1   = (float*)p;
    cudaGetSymbolAddress(&p, g_as);   float* asb  = (float*)p;
    cudaGetSymbolAddress(&p, g_ad);   float* adb  = (float*)p;
    cudaGetSymbolAddress(&p, g_cnt);  int*   cnt  = (int*)p;
    cudaGetSymbolAddress(&p, g_cur);  int*   cur  = (int*)p;
    cudaGetSymbolAddress(&p, g_off);  int*   off  = (int*)p;
    cudaGetSymbolAddress(&p, g_csr);  int*   csr  = (int*)p;

    cudaFuncSetAttribute(gemm_fused, cudaFuncAttributeMaxDynamicSharedMemorySize, GSMEM);

    dim3 ggrid((n + 127) / 128, 6);

    // order chosen so gemm_fused is the 4th launch (ncu lands there)
    zero_counts<<<(TT * n + 255) / 256, 256>>>(cnt, cur, TT * n);
    zero_asad<<<(TT * n + 255) / 256, 256>>>(asb, adb, TT * n);
    hist_kernel<<<(TT * ne + 255) / 256, 256>>>(ei, cnt, n, ne);

    // ---- layer 1 GEMM + dots (4th launch) ----
    gemm_fused<<<ggrid, 256, GSMEM>>>(z, W1, hcat, as1, ad1, asb, adb, n);

    scan_off<<<TT, 1024>>>(cnt, off, n);
    fill_kernel<<<(TT * ne + 255) / 256, 256>>>(ei, off, cur, csr, n, ne);

    agg_kernel<<<(n + 7) / 8, 256>>>(off, csr, hcat, asb, adb, b1,
                                     h1, Wh, bh, out, 0, n, ne);

    // ---- layer 2 ----
    zero_asad<<<(TT * n + 255) / 256, 256>>>(asb, adb, TT * n);
    gemm_fused<<<ggrid, 256, GSMEM>>>(h1, W2, hcat, as2, ad2, asb, adb, n);
    agg_kernel<<<(n + 7) / 8, 256>>>(off, csr, hcat, asb, adb, b2,
                                     h1 /*unused*/, Wh, bh, out, 1, n, ne);
}

// round 10
// speedup vs baseline: 1.1169x; 1.1169x over previous
#include <cuda_runtime.h>
#include <cstdint>

#define NMAX 50048
#define EMAX 250112
#define TT 3

// ---------------- scratch (static device globals; no allocation) ----------------
__device__ float g_hcat[TT * NMAX * 256];   // per-type h = x @ W[t]
__device__ float g_h1[NMAX * 256];          // layer-1 output
__device__ float g_as[TT * NMAX];           // a_src per type (atomic-accumulated)
__device__ float g_ad[TT * NMAX];           // a_dst per type
__device__ int   g_cnt[TT * NMAX];
__device__ int   g_cur[TT * NMAX];
__device__ int   g_off[TT * (NMAX + 1)];
__device__ int   g_csr[TT * EMAX];

// ---------------- small float4 helpers ----------------
__device__ __forceinline__ float4 f4add(float4 a, float4 b) {
    return make_float4(a.x + b.x, a.y + b.y, a.z + b.z, a.w + b.w);
}
__device__ __forceinline__ float4 f4fma(float4 a, float s, float4 c) {
    return make_float4(fmaf(a.x, s, c.x), fmaf(a.y, s, c.y),
                       fmaf(a.z, s, c.z), fmaf(a.w, s, c.w));
}
__device__ __forceinline__ float4 f4relu(float4 a) {
    return make_float4(fmaxf(a.x, 0.f), fmaxf(a.y, 0.f),
                       fmaxf(a.z, 0.f), fmaxf(a.w, 0.f));
}

// ============ fused GEMM + attention dots ============
// Hcat[t][n][256] = X[n][256] @ W[t][256][256];  as_out[t][n] += h_n . a_s[t] (partial)
// BM=128, BN=128, BK=32, 2-stage cp.async (71.7KB smem -> 3 CTAs/SM),
// tf32 mma.sync on raw fp32 bits. 8 warps: 4 in M x 2 in N, warp tile 32x64.
// grid = (ceil(n/128), 6): t = blockIdx.y >> 1, bn = (blockIdx.y & 1) * 128.
#define APITCH 36
#define BPITCH 136
#define ASTG   (128 * APITCH)
#define BSTG   (32 * BPITCH)
#define GSMEM  (2 * (ASTG + BSTG) * 4)

__global__ __launch_bounds__(256) void gemm_fused(
    const float* __restrict__ X, const float* __restrict__ W,
    float* __restrict__ Hcat,
    const float* __restrict__ as_full, const float* __restrict__ ad_full,
    float* __restrict__ as_out, float* __restrict__ ad_out, int nrows)
{
    extern __shared__ uint32_t dsm[];
    uint32_t* As = dsm;              // [2][ASTG]
    uint32_t* Bs = dsm + 2 * ASTG;   // [2][BSTG]

    int tid  = threadIdx.x;
    int lane = tid & 31, warp = tid >> 5;
    int wm = warp >> 1, wn = warp & 1;
    int g  = lane >> 2, tig = lane & 3;
    int bm = blockIdx.x * 128;
    int t  = blockIdx.y >> 1;
    int bn = (blockIdx.y & 1) * 128;
    const float* Wt = W + (size_t)t * 65536;
    float* Hout = Hcat + (size_t)t * nrows * 256;

    auto stage = [&](int st, int k0) {
#pragma unroll
        for (int p = 0; p < 4; p++) {            // A: 128 rows x 8 groups of 16B
            int i = tid + p * 256;
            int r = i >> 3, grp = i & 7;
            uint32_t d = (uint32_t)__cvta_generic_to_shared(
                &As[st * ASTG + r * APITCH + grp * 4]);
            const float* s = X + (size_t)(bm + r) * 256 + k0 + grp * 4;
            int sz = (bm + r) < nrows ? 16 : 0;
            asm volatile("cp.async.ca.shared.global [%0], [%1], 16, %2;"
                         :: "r"(d), "l"(s), "r"(sz));
        }
#pragma unroll
        for (int p = 0; p < 4; p++) {            // B: 32 rows x 32 groups of 16B
            int i = tid + p * 256;
            int r = i >> 5, grp = i & 31;
            uint32_t d = (uint32_t)__cvta_generic_to_shared(
                &Bs[st * BSTG + r * BPITCH + grp * 4]);
            const float* s = Wt + (size_t)(k0 + r) * 256 + bn + grp * 4;
            asm volatile("cp.async.ca.shared.global [%0], [%1], 16;"
                         :: "r"(d), "l"(s));
        }
        asm volatile("cp.async.commit_group;");
    };

    float acc[2][8][4];
#pragma unroll
    for (int a = 0; a < 2; a++)
#pragma unroll
        for (int b = 0; b < 8; b++)
#pragma unroll
            for (int c = 0; c < 4; c++) acc[a][b][c] = 0.f;

    stage(0, 0);
    for (int k0 = 0; k0 < 256; k0 += 32) {
        int cur = (k0 >> 5) & 1;
        if (k0 + 32 < 256) {
            stage(cur ^ 1, k0 + 32);
            asm volatile("cp.async.wait_group 1;");
        } else {
            asm volatile("cp.async.wait_group 0;");
        }
        __syncthreads();

        const uint32_t* Ac = As + cur * ASTG;
        const uint32_t* Bc = Bs + cur * BSTG;
#pragma unroll
        for (int kk = 0; kk < 32; kk += 8) {
            uint32_t a[2][4], b[8][2];
#pragma unroll
            for (int mm = 0; mm < 2; mm++) {
                int row = wm * 32 + mm * 16 + g;
                a[mm][0] = Ac[row * APITCH + kk + tig];
                a[mm][1] = Ac[(row + 8) * APITCH + kk + tig];
                a[mm][2] = Ac[row * APITCH + kk + tig + 4];
                a[mm][3] = Ac[(row + 8) * APITCH + kk + tig + 4];
            }
#pragma unroll
            for (int nn = 0; nn < 8; nn++) {
                int col = wn * 64 + nn * 8 + g;
                b[nn][0] = Bc[(kk + tig) * BPITCH + col];
                b[nn][1] = Bc[(kk + tig + 4) * BPITCH + col];
            }
#pragma unroll
            for (int mm = 0; mm < 2; mm++)
#pragma unroll
                for (int nn = 0; nn < 8; nn++)
                    asm volatile(
                        "mma.sync.aligned.m16n8k8.row.col.f32.tf32.tf32.f32 "
                        "{%0,%1,%2,%3}, {%4,%5,%6,%7}, {%8,%9}, {%0,%1,%2,%3};"
                        : "+f"(acc[mm][nn][0]), "+f"(acc[mm][nn][1]),
                          "+f"(acc[mm][nn][2]), "+f"(acc[mm][nn][3])
                        : "r"(a[mm][0]), "r"(a[mm][1]), "r"(a[mm][2]), "r"(a[mm][3]),
                          "r"(b[nn][0]), "r"(b[nn][1]));
        }
        __syncthreads();
    }

    // ---- store H tile ----
#pragma unroll
    for (int mm = 0; mm < 2; mm++)
#pragma unroll
        for (int nn = 0; nn < 8; nn++) {
            int row = bm + wm * 32 + mm * 16 + g;
            int col = bn + wn * 64 + nn * 8 + 2 * tig;
            if (row < nrows)
                *(float2*)(Hout + (size_t)row * 256 + col) =
                    make_float2(acc[mm][nn][0], acc[mm][nn][1]);
            if (row + 8 < nrows)
                *(float2*)(Hout + (size_t)(row + 8) * 256 + col) =
                    make_float2(acc[mm][nn][2], acc[mm][nn][3]);
        }

    // ---- fused attention dots: partial h.a_s / h.a_d over this CTA's 128 cols ----
    {
        const float* avs = as_full + t * 256;
        const float* avd = ad_full + t * 256;
        float ds[2][2] = {{0.f, 0.f}, {0.f, 0.f}};
        float dd[2][2] = {{0.f, 0.f}, {0.f, 0.f}};
#pragma unroll
        for (int mm = 0; mm < 2; mm++)
#pragma unroll
            for (int nn = 0; nn < 8; nn++) {
                int col = bn + wn * 64 + nn * 8 + 2 * tig;
                float a0 = __ldg(&avs[col]), a1 = __ldg(&avs[col + 1]);
                float d0 = __ldg(&avd[col]), d1 = __ldg(&avd[col + 1]);
                ds[mm][0] += acc[mm][nn][0] * a0 + acc[mm][nn][1] * a1;
                ds[mm][1] += acc[mm][nn][2] * a0 + acc[mm][nn][3] * a1;
                dd[mm][0] += acc[mm][nn][0] * d0 + acc[mm][nn][1] * d1;
                dd[mm][1] += acc[mm][nn][2] * d0 + acc[mm][nn][3] * d1;
            }
        // reduce over the 4 tig lanes (same g -> same rows)
#pragma unroll
        for (int o = 1; o <= 2; o <<= 1)
#pragma unroll
            for (int mm = 0; mm < 2; mm++)
#pragma unroll
                for (int h = 0; h < 2; h++) {
                    ds[mm][h] += __shfl_xor_sync(0xffffffffu, ds[mm][h], o);
                    dd[mm][h] += __shfl_xor_sync(0xffffffffu, dd[mm][h], o);
                }
        if (tig == 0) {
            float* aso = as_out + (size_t)t * nrows;
            float* ado = ad_out + (size_t)t * nrows;
#pragma unroll
            for (int mm = 0; mm < 2; mm++)
#pragma unroll
                for (int h = 0; h < 2; h++) {
                    int row = bm + wm * 32 + mm * 16 + g + h * 8;
                    if (row < nrows) {
                        atomicAdd(&aso[row], ds[mm][h]);
                        atomicAdd(&ado[row], dd[mm][h]);
                    }
                }
        }
    }
}

// ============ init: counts + cursors + dot accumulators (layer 1) ============
__global__ void init_all(int* __restrict__ cnt, int* __restrict__ cur,
                         float* __restrict__ a, float* __restrict__ b, int total) {
    int i = blockIdx.x * blockDim.x + threadIdx.x;
    if (i < total) { cnt[i] = 0; cur[i] = 0; a[i] = 0.f; b[i] = 0.f; }
}

__global__ void zero_asad(float* __restrict__ a, float* __restrict__ b, int total) {
    int i = blockIdx.x * blockDim.x + threadIdx.x;
    if (i < total) { a[i] = 0.f; b[i] = 0.f; }
}

// ============ CSR build (once; graph shared by both layers) ============
__global__ void hist_kernel(const int* __restrict__ ei, int* __restrict__ cnt,
                            int n, int ne)
{
    int i = blockIdx.x * blockDim.x + threadIdx.x;
    if (i >= TT * ne) return;
    int t = i / ne, e = i - t * ne;
    int d = ei[(size_t)t * 2 * ne + ne + e];
    atomicAdd(&cnt[t * n + d], 1);
}

__global__ __launch_bounds__(1024) void scan_off(
    const int* __restrict__ cnt, int* __restrict__ off, int n)
{
    int t = blockIdx.x;
    const int* c = cnt + t * n;
    int* o = off + t * (n + 1);
    __shared__ int wsum[32];
    __shared__ int carry_sh;
    int tid = threadIdx.x, lane = tid & 31, wid = tid >> 5;
    if (tid == 0) carry_sh = 0;
    __syncthreads();
    for (int base = 0; base < n; base += 1024) {
        int i = base + tid;
        int v = (i < n) ? c[i] : 0;
        int x = v;
#pragma unroll
        for (int o2 = 1; o2 < 32; o2 <<= 1) {
            int y = __shfl_up_sync(0xffffffffu, x, o2);
            if (lane >= o2) x += y;
        }
        if (lane == 31) wsum[wid] = x;
        __syncthreads();
        if (wid == 0) {
            int s = wsum[lane];
#pragma unroll
            for (int o2 = 1; o2 < 32; o2 <<= 1) {
                int y = __shfl_up_sync(0xffffffffu, s, o2);
                if (lane >= o2) s += y;
            }
            wsum[lane] = s;
        }
        __syncthreads();
        int incl  = x + (wid > 0 ? wsum[wid - 1] : 0);
        int carry = carry_sh;
        if (i < n) o[i] = carry + incl - v;
        __syncthreads();
        if (tid == 1023) carry_sh = carry + wsum[31];
        __syncthreads();
    }
    if (threadIdx.x == 0) o[n] = carry_sh;
}

__global__ void fill_kernel(const int* __restrict__ ei, const int* __restrict__ off,
                            int* __restrict__ cur, int* __restrict__ csr,
                            int n, int ne)
{
    int i = blockIdx.x * blockDim.x + threadIdx.x;
    if (i >= TT * ne) return;
    int t = i / ne, e = i - t * ne;
    const int* base = ei + (size_t)t * 2 * ne;
    int s = base[e], d = base[ne + e];
    int pos = off[t * (n + 1) + d] + atomicAdd(&cur[t * n + d], 1);
    csr[t * ne + pos] = s;
}

// ============ fused softmax + aggregate + bias + relu (+ head) : warp per dst ============
__global__ __launch_bounds__(256) void agg_kernel(
    const int* __restrict__ off, const int* __restrict__ csr,
    const float* __restrict__ hcat, const float* __restrict__ asb,
    const float* __restrict__ adb, const float* __restrict__ bias,
    float* __restrict__ outrow, const float* __restrict__ Wh,
    const float* __restrict__ bh, float* __restrict__ headout,
    int mode, int n, int ne)
{
    int w    = (blockIdx.x * blockDim.x + threadIdx.x) >> 5;
    int lane = threadIdx.x & 31;
    if (w >= n) return;

    float4 a0 = make_float4(0.f, 0.f, 0.f, 0.f);
    float4 a1 = make_float4(0.f, 0.f, 0.f, 0.f);

#pragma unroll
    for (int t = 0; t < TT; t++) {
        int o0 = off[t * (n + 1) + w];
        int deg = off[t * (n + 1) + w + 1] - o0;
        if (deg == 0) continue;
        float adt = adb[t * n + w];
        const float* ht   = hcat + (size_t)t * n * 256;
        const float* ast  = asb + t * n;
        const int*   srcs = csr + (size_t)t * ne + o0;
        float4 t0 = make_float4(0.f, 0.f, 0.f, 0.f);
        float4 t1 = make_float4(0.f, 0.f, 0.f, 0.f);
        float den = 0.f;
        for (int base = 0; base < deg; base += 32) {
            int m = min(32, deg - base);
            int   sj = 0;
            float ex = 0.f;
            if (lane < m) {
                sj = srcs[base + lane];
                float e = ast[sj] + adt;
                e = e > 0.f ? e : 0.2f * e;      // leaky_relu 0.2
                ex = __expf(e);                   // shift-invariant: no max needed
            }
            float s = ex;
#pragma unroll
            for (int o = 16; o; o >>= 1) s += __shfl_xor_sync(0xffffffffu, s, o);
            den += s;
            for (int j = 0; j < m; j++) {
                int   sn = __shfl_sync(0xffffffffu, sj, j);
                float wt = __shfl_sync(0xffffffffu, ex, j);
                const float4* hr = (const float4*)(ht + (size_t)sn * 256);
                t0 = f4fma(hr[lane], wt, t0);
                t1 = f4fma(hr[lane + 32], wt, t1);
            }
        }
        float inv = 1.f / den;
        a0 = f4fma(t0, inv, a0);
        a1 = f4fma(t1, inv, a1);
    }

    const float4* bb = (const float4*)bias;
    float4 b0 = f4add(f4add(__ldg(&bb[lane]), __ldg(&bb[64 + lane])), __ldg(&bb[128 + lane]));
    float4 b1 = f4add(f4add(__ldg(&bb[lane + 32]), __ldg(&bb[96 + lane])), __ldg(&bb[160 + lane]));
    float4 r0 = f4relu(f4add(a0, b0));
    float4 r1 = f4relu(f4add(a1, b1));

    if (mode == 0) {
        float4* orow = (float4*)(outrow + (size_t)w * 256);
        orow[lane]      = r0;
        orow[lane + 32] = r1;
    } else {
        const float4* wh = (const float4*)Wh;
        float4 q0 = __ldg(&wh[lane]);
        float4 q1 = __ldg(&wh[lane + 32]);
        float s = r0.x * q0.x + r0.y * q0.y + r0.z * q0.z + r0.w * q0.w +
                  r1.x * q1.x + r1.y * q1.y + r1.z * q1.z + r1.w * q1.w;
#pragma unroll
        for (int o = 16; o; o >>= 1) s += __shfl_xor_sync(0xffffffffu, s, o);
        if (lane == 0) headout[w] = 1.f / (1.f + __expf(-(s + bh[0])));
    }
}

// ---------------- host orchestration ----------------
extern "C" void kernel_launch(void* const* d_in, const int* in_sizes, int n_in,
                              void* d_out, int out_size)
{
    const float* z   = (const float*)d_in[0];
    const int*   ei  = (const int*)d_in[1];
    const float* W1  = (const float*)d_in[2];
    const float* as1 = (const float*)d_in[3];
    const float* ad1 = (const float*)d_in[4];
    const float* b1  = (const float*)d_in[5];
    const float* W2  = (const float*)d_in[6];
    const float* as2 = (const float*)d_in[7];
    const float* ad2 = (const float*)d_in[8];
    const float* b2  = (const float*)d_in[9];
    const float* Wh  = (const float*)d_in[10];
    const float* bh  = (const float*)d_in[11];
    float* out = (float*)d_out;

    int n  = in_sizes[0] / 256;   // 50000
    int ne = in_sizes[1] / 6;     // 250000

    void* p;
    cudaGetSymbolAddress(&p, g_hcat); float* hcat = (float*)p;
    cudaGetSymbolAddress(&p, g_h1);   float* h1   = (float*)p;
    cudaGetSymbolAddress(&p, g_as);   float* asb  = (float*)p;
    cudaGetSymbolAddress(&p, g_ad);   float* adb  = (float*)p;
    cudaGetSymbolAddress(&p, g_cnt);  int*   cnt  = (int*)p;
    cudaGetSymbolAddress(&p, g_cur);  int*   cur  = (int*)p;
    cudaGetSymbolAddress(&p, g_off);  int*   off  = (int*)p;
    cudaGetSymbolAddress(&p, g_csr);  int*   csr  = (int*)p;

    cudaFuncSetAttribute(gemm_fused, cudaFuncAttributeMaxDynamicSharedMemorySize, GSMEM);

    dim3 ggrid((n + 127) / 128, 6);

    // order chosen so gemm_fused is the 4th launch (ncu lands there)
    init_all<<<(TT * n + 255) / 256, 256>>>(cnt, cur, asb, adb, TT * n);
    hist_kernel<<<(TT * ne + 255) / 256, 256>>>(ei, cnt, n, ne);
    scan_off<<<TT, 1024>>>(cnt, off, n);

    // ---- layer 1 GEMM + dots (4th launch) ----
    gemm_fused<<<ggrid, 256, GSMEM>>>(z, W1, hcat, as1, ad1, asb, adb, n);

    fill_kernel<<<(TT * ne + 255) / 256, 256>>>(ei, off, cur, csr, n, ne);

    agg_kernel<<<(n + 7) / 8, 256>>>(off, csr, hcat, asb, adb, b1,
                                     h1, Wh, bh, out, 0, n, ne);

    // ---- layer 2 ----
    zero_asad<<<(TT * n + 255) / 256, 256>>>(asb, adb, TT * n);
    gemm_fused<<<ggrid, 256, GSMEM>>>(h1, W2, hcat, as2, ad2, asb, adb, n);
    agg_kernel<<<(n + 7) / 8, 256>>>(off, csr, hcat, asb, adb, b2,
                                     h1 /*unused*/, Wh, bh, out, 1, n, ne);
}

// round 11
// speedup vs baseline: 1.2192x; 1.0915x over previous
#include <cuda_runtime.h>
#include <cuda_fp16.h>
#include <cstdint>

#define NMAX 50048
#define EMAX 250112
#define TT 3

// ---------------- scratch (static device globals; no allocation) ----------------
__device__ __half g_hcat[TT * NMAX * 256]; // per-type h = x @ W[t], fp16 (gather-only)
__device__ float  g_h1[NMAX * 256];        // layer-1 output
__device__ float  g_as[TT * NMAX];         // a_src per type (atomic-accumulated)
__device__ float  g_ad[TT * NMAX];         // a_dst per type
__device__ int    g_cnt[TT * NMAX];
__device__ int    g_cur[TT * NMAX];
__device__ int    g_off[TT * (NMAX + 1)];
__device__ int    g_csr[TT * EMAX];

// ---------------- small float4 helpers ----------------
__device__ __forceinline__ float4 f4add(float4 a, float4 b) {
    return make_float4(a.x + b.x, a.y + b.y, a.z + b.z, a.w + b.w);
}
__device__ __forceinline__ float4 f4fma(float4 a, float s, float4 c) {
    return make_float4(fmaf(a.x, s, c.x), fmaf(a.y, s, c.y),
                       fmaf(a.z, s, c.z), fmaf(a.w, s, c.w));
}
__device__ __forceinline__ float4 f4relu(float4 a) {
    return make_float4(fmaxf(a.x, 0.f), fmaxf(a.y, 0.f),
                       fmaxf(a.z, 0.f), fmaxf(a.w, 0.f));
}

// ============ fused GEMM + attention dots ============
// hcat[t][n][256](fp16) = X[n][256] @ W[t][256][256]; as/ad dots from fp32 accums.
// BM=128, BN=128, BK=32, 2-stage cp.async, tf32 mma.sync on raw fp32 bits.
// 8 warps: 4 in M x 2 in N, warp tile 32x64. grid = (ceil(n/128), 6).
#define APITCH 36
#define BPITCH 136
#define ASTG   (128 * APITCH)
#define BSTG   (32 * BPITCH)
#define GSMEM  (2 * (ASTG + BSTG) * 4)

__global__ __launch_bounds__(256) void gemm_fused(
    const float* __restrict__ X, const float* __restrict__ W,
    __half* __restrict__ Hcat,
    const float* __restrict__ as_full, const float* __restrict__ ad_full,
    float* __restrict__ as_out, float* __restrict__ ad_out, int nrows)
{
    extern __shared__ uint32_t dsm[];
    uint32_t* As = dsm;              // [2][ASTG]
    uint32_t* Bs = dsm + 2 * ASTG;   // [2][BSTG]

    int tid  = threadIdx.x;
    int lane = tid & 31, warp = tid >> 5;
    int wm = warp >> 1, wn = warp & 1;
    int g  = lane >> 2, tig = lane & 3;
    int bm = blockIdx.x * 128;
    int t  = blockIdx.y >> 1;
    int bn = (blockIdx.y & 1) * 128;
    const float* Wt = W + (size_t)t * 65536;
    __half* Hout = Hcat + (size_t)t * nrows * 256;

    auto stage = [&](int st, int k0) {
#pragma unroll
        for (int p = 0; p < 4; p++) {            // A: 128 rows x 8 groups of 16B
            int i = tid + p * 256;
            int r = i >> 3, grp = i & 7;
            uint32_t d = (uint32_t)__cvta_generic_to_shared(
                &As[st * ASTG + r * APITCH + grp * 4]);
            const float* s = X + (size_t)(bm + r) * 256 + k0 + grp * 4;
            int sz = (bm + r) < nrows ? 16 : 0;
            asm volatile("cp.async.ca.shared.global [%0], [%1], 16, %2;"
                         :: "r"(d), "l"(s), "r"(sz));
        }
#pragma unroll
        for (int p = 0; p < 4; p++) {            // B: 32 rows x 32 groups of 16B
            int i = tid + p * 256;
            int r = i >> 5, grp = i & 31;
            uint32_t d = (uint32_t)__cvta_generic_to_shared(
                &Bs[st * BSTG + r * BPITCH + grp * 4]);
            const float* s = Wt + (size_t)(k0 + r) * 256 + bn + grp * 4;
            asm volatile("cp.async.ca.shared.global [%0], [%1], 16;"
                         :: "r"(d), "l"(s));
        }
        asm volatile("cp.async.commit_group;");
    };

    float acc[2][8][4];
#pragma unroll
    for (int a = 0; a < 2; a++)
#pragma unroll
        for (int b = 0; b < 8; b++)
#pragma unroll
            for (int c = 0; c < 4; c++) acc[a][b][c] = 0.f;

    stage(0, 0);
    for (int k0 = 0; k0 < 256; k0 += 32) {
        int cur = (k0 >> 5) & 1;
        if (k0 + 32 < 256) {
            stage(cur ^ 1, k0 + 32);
            asm volatile("cp.async.wait_group 1;");
        } else {
            asm volatile("cp.async.wait_group 0;");
        }
        __syncthreads();

        const uint32_t* Ac = As + cur * ASTG;
        const uint32_t* Bc = Bs + cur * BSTG;
#pragma unroll
        for (int kk = 0; kk < 32; kk += 8) {
            uint32_t a[2][4], b[8][2];
#pragma unroll
            for (int mm = 0; mm < 2; mm++) {
                int row = wm * 32 + mm * 16 + g;
                a[mm][0] = Ac[row * APITCH + kk + tig];
                a[mm][1] = Ac[(row + 8) * APITCH + kk + tig];
                a[mm][2] = Ac[row * APITCH + kk + tig + 4];
                a[mm][3] = Ac[(row + 8) * APITCH + kk + tig + 4];
            }
#pragma unroll
            for (int nn = 0; nn < 8; nn++) {
                int col = wn * 64 + nn * 8 + g;
                b[nn][0] = Bc[(kk + tig) * BPITCH + col];
                b[nn][1] = Bc[(kk + tig + 4) * BPITCH + col];
            }
#pragma unroll
            for (int mm = 0; mm < 2; mm++)
#pragma unroll
                for (int nn = 0; nn < 8; nn++)
                    asm volatile(
                        "mma.sync.aligned.m16n8k8.row.col.f32.tf32.tf32.f32 "
                        "{%0,%1,%2,%3}, {%4,%5,%6,%7}, {%8,%9}, {%0,%1,%2,%3};"
                        : "+f"(acc[mm][nn][0]), "+f"(acc[mm][nn][1]),
                          "+f"(acc[mm][nn][2]), "+f"(acc[mm][nn][3])
                        : "r"(a[mm][0]), "r"(a[mm][1]), "r"(a[mm][2]), "r"(a[mm][3]),
                          "r"(b[nn][0]), "r"(b[nn][1]));
        }
        __syncthreads();
    }

    // ---- store H tile as fp16 ----
#pragma unroll
    for (int mm = 0; mm < 2; mm++)
#pragma unroll
        for (int nn = 0; nn < 8; nn++) {
            int row = bm + wm * 32 + mm * 16 + g;
            int col = bn + wn * 64 + nn * 8 + 2 * tig;
            if (row < nrows)
                *(__half2*)(Hout + (size_t)row * 256 + col) =
                    __floats2half2_rn(acc[mm][nn][0], acc[mm][nn][1]);
            if (row + 8 < nrows)
                *(__half2*)(Hout + (size_t)(row + 8) * 256 + col) =
                    __floats2half2_rn(acc[mm][nn][2], acc[mm][nn][3]);
        }

    // ---- fused attention dots: partial h.a_s / h.a_d over this CTA's 128 cols ----
    {
        const float* avs = as_full + t * 256;
        const float* avd = ad_full + t * 256;
        float ds[2][2] = {{0.f, 0.f}, {0.f, 0.f}};
        float dd[2][2] = {{0.f, 0.f}, {0.f, 0.f}};
#pragma unroll
        for (int mm = 0; mm < 2; mm++)
#pragma unroll
            for (int nn = 0; nn < 8; nn++) {
                int col = bn + wn * 64 + nn * 8 + 2 * tig;
                float a0 = __ldg(&avs[col]), a1 = __ldg(&avs[col + 1]);
                float d0 = __ldg(&avd[col]), d1 = __ldg(&avd[col + 1]);
                ds[mm][0] += acc[mm][nn][0] * a0 + acc[mm][nn][1] * a1;
                ds[mm][1] += acc[mm][nn][2] * a0 + acc[mm][nn][3] * a1;
                dd[mm][0] += acc[mm][nn][0] * d0 + acc[mm][nn][1] * d1;
                dd[mm][1] += acc[mm][nn][2] * d0 + acc[mm][nn][3] * d1;
            }
        // reduce over the 4 tig lanes (same g -> same rows)
#pragma unroll
        for (int o = 1; o <= 2; o <<= 1)
#pragma unroll
            for (int mm = 0; mm < 2; mm++)
#pragma unroll
                for (int h = 0; h < 2; h++) {
                    ds[mm][h] += __shfl_xor_sync(0xffffffffu, ds[mm][h], o);
                    dd[mm][h] += __shfl_xor_sync(0xffffffffu, dd[mm][h], o);
                }
        if (tig == 0) {
            float* aso = as_out + (size_t)t * nrows;
            float* ado = ad_out + (size_t)t * nrows;
#pragma unroll
            for (int mm = 0; mm < 2; mm++)
#pragma unroll
                for (int h = 0; h < 2; h++) {
                    int row = bm + wm * 32 + mm * 16 + g + h * 8;
                    if (row < nrows) {
                        atomicAdd(&aso[row], ds[mm][h]);
                        atomicAdd(&ado[row], dd[mm][h]);
                    }
                }
        }
    }
}

// ============ init: counts + cursors + dot accumulators (layer 1) ============
__global__ void init_all(int* __restrict__ cnt, int* __restrict__ cur,
                         float* __restrict__ a, float* __restrict__ b, int total) {
    int i = blockIdx.x * blockDim.x + threadIdx.x;
    if (i < total) { cnt[i] = 0; cur[i] = 0; a[i] = 0.f; b[i] = 0.f; }
}

__global__ void zero_asad(float* __restrict__ a, float* __restrict__ b, int total) {
    int i = blockIdx.x * blockDim.x + threadIdx.x;
    if (i < total) { a[i] = 0.f; b[i] = 0.f; }
}

// ============ CSR build (once; graph shared by both layers) ============
__global__ void hist_kernel(const int* __restrict__ ei, int* __restrict__ cnt,
                            int n, int ne)
{
    int i = blockIdx.x * blockDim.x + threadIdx.x;
    if (i >= TT * ne) return;
    int t = i / ne, e = i - t * ne;
    int d = ei[(size_t)t * 2 * ne + ne + e];
    atomicAdd(&cnt[t * n + d], 1);
}

__global__ __launch_bounds__(1024) void scan_off(
    const int* __restrict__ cnt, int* __restrict__ off, int n)
{
    int t = blockIdx.x;
    const int* c = cnt + t * n;
    int* o = off + t * (n + 1);
    __shared__ int wsum[32];
    __shared__ int carry_sh;
    int tid = threadIdx.x, lane = tid & 31, wid = tid >> 5;
    if (tid == 0) carry_sh = 0;
    __syncthreads();
    for (int base = 0; base < n; base += 1024) {
        int i = base + tid;
        int v = (i < n) ? c[i] : 0;
        int x = v;
#pragma unroll
        for (int o2 = 1; o2 < 32; o2 <<= 1) {
            int y = __shfl_up_sync(0xffffffffu, x, o2);
            if (lane >= o2) x += y;
        }
        if (lane == 31) wsum[wid] = x;
        __syncthreads();
        if (wid == 0) {
            int s = wsum[lane];
#pragma unroll
            for (int o2 = 1; o2 < 32; o2 <<= 1) {
                int y = __shfl_up_sync(0xffffffffu, s, o2);
                if (lane >= o2) s += y;
            }
            wsum[lane] = s;
        }
        __syncthreads();
        int incl  = x + (wid > 0 ? wsum[wid - 1] : 0);
        int carry = carry_sh;
        if (i < n) o[i] = carry + incl - v;
        __syncthreads();
        if (tid == 1023) carry_sh = carry + wsum[31];
        __syncthreads();
    }
    if (threadIdx.x == 0) o[n] = carry_sh;
}

__global__ void fill_kernel(const int* __restrict__ ei, const int* __restrict__ off,
                            int* __restrict__ cur, int* __restrict__ csr,
                            int n, int ne)
{
    int i = blockIdx.x * blockDim.x + threadIdx.x;
    if (i >= TT * ne) return;
    int t = i / ne, e = i - t * ne;
    const int* base = ei + (size_t)t * 2 * ne;
    int s = base[e], d = base[ne + e];
    int pos = off[t * (n + 1) + d] + atomicAdd(&cur[t * n + d], 1);
    csr[t * ne + pos] = s;
}

// ============ fused softmax + aggregate + bias + relu (+ head) : warp per dst ============
// hcat rows are fp16: one uint4 (8 halves) per lane covers the full 256-col row.
// Lane j owns cols [8j, 8j+8).
__global__ __launch_bounds__(256) void agg_kernel(
    const int* __restrict__ off, const int* __restrict__ csr,
    const __half* __restrict__ hcat, const float* __restrict__ asb,
    const float* __restrict__ adb, const float* __restrict__ bias,
    float* __restrict__ outrow, const float* __restrict__ Wh,
    const float* __restrict__ bh, float* __restrict__ headout,
    int mode, int n, int ne)
{
    int w    = (blockIdx.x * blockDim.x + threadIdx.x) >> 5;
    int lane = threadIdx.x & 31;
    if (w >= n) return;

    float4 a0 = make_float4(0.f, 0.f, 0.f, 0.f);   // cols 8*lane .. +3
    float4 a1 = make_float4(0.f, 0.f, 0.f, 0.f);   // cols 8*lane+4 .. +7

#pragma unroll
    for (int t = 0; t < TT; t++) {
        int o0 = off[t * (n + 1) + w];
        int deg = off[t * (n + 1) + w + 1] - o0;
        if (deg == 0) continue;
        float adt = adb[t * n + w];
        const __half* ht  = hcat + (size_t)t * n * 256;
        const float* ast  = asb + t * n;
        const int*   srcs = csr + (size_t)t * ne + o0;
        float4 t0 = make_float4(0.f, 0.f, 0.f, 0.f);
        float4 t1 = make_float4(0.f, 0.f, 0.f, 0.f);
        float den = 0.f;
        for (int base = 0; base < deg; base += 32) {
            int m = min(32, deg - base);
            int   sj = 0;
            float ex = 0.f;
            if (lane < m) {
                sj = srcs[base + lane];
                float e = ast[sj] + adt;
                e = e > 0.f ? e : 0.2f * e;      // leaky_relu 0.2
                ex = __expf(e);                   // shift-invariant: no max needed
            }
            float s = ex;
#pragma unroll
            for (int o = 16; o; o >>= 1) s += __shfl_xor_sync(0xffffffffu, s, o);
            den += s;
            for (int j = 0; j < m; j++) {
                int   sn = __shfl_sync(0xffffffffu, sj, j);
                float wt = __shfl_sync(0xffffffffu, ex, j);
                uint4 v = *(const uint4*)(ht + (size_t)sn * 256 + lane * 8);
                float2 f0 = __half22float2(*(__half2*)&v.x);
                float2 f1 = __half22float2(*(__half2*)&v.y);
                float2 f2 = __half22float2(*(__half2*)&v.z);
                float2 f3 = __half22float2(*(__half2*)&v.w);
                t0.x = fmaf(f0.x, wt, t0.x); t0.y = fmaf(f0.y, wt, t0.y);
                t0.z = fmaf(f1.x, wt, t0.z); t0.w = fmaf(f1.y, wt, t0.w);
                t1.x = fmaf(f2.x, wt, t1.x); t1.y = fmaf(f2.y, wt, t1.y);
                t1.z = fmaf(f3.x, wt, t1.z); t1.w = fmaf(f3.y, wt, t1.w);
            }
        }
        float inv = 1.f / den;
        a0 = f4fma(t0, inv, a0);
        a1 = f4fma(t1, inv, a1);
    }

    // bias sum over the 3 types ([3][64] float4 view), cols 8*lane -> float4 idx 2*lane
    const float4* bb = (const float4*)bias;
    float4 b0 = f4add(f4add(__ldg(&bb[2 * lane]), __ldg(&bb[64 + 2 * lane])),
                      __ldg(&bb[128 + 2 * lane]));
    float4 b1 = f4add(f4add(__ldg(&bb[2 * lane + 1]), __ldg(&bb[64 + 2 * lane + 1])),
                      __ldg(&bb[128 + 2 * lane + 1]));
    float4 r0 = f4relu(f4add(a0, b0));
    float4 r1 = f4relu(f4add(a1, b1));

    if (mode == 0) {
        float4* orow = (float4*)(outrow + (size_t)w * 256);
        orow[2 * lane]     = r0;
        orow[2 * lane + 1] = r1;
    } else {
        const float4* wh = (const float4*)Wh;
        float4 q0 = __ldg(&wh[2 * lane]);
        float4 q1 = __ldg(&wh[2 * lane + 1]);
        float s = r0.x * q0.x + r0.y * q0.y + r0.z * q0.z + r0.w * q0.w +
                  r1.x * q1.x + r1.y * q1.y + r1.z * q1.z + r1.w * q1.w;
#pragma unroll
        for (int o = 16; o; o >>= 1) s += __shfl_xor_sync(0xffffffffu, s, o);
        if (lane == 0) headout[w] = 1.f / (1.f + __expf(-(s + bh[0])));
    }
}

// ---------------- host orchestration ----------------
extern "C" void kernel_launch(void* const* d_in, const int* in_sizes, int n_in,
                              void* d_out, int out_size)
{
    const float* z   = (const float*)d_in[0];
    const int*   ei  = (const int*)d_in[1];
    const float* W1  = (const float*)d_in[2];
    const float* as1 = (const float*)d_in[3];
    const float* ad1 = (const float*)d_in[4];
    const float* b1  = (const float*)d_in[5];
    const float* W2  = (const float*)d_in[6];
    const float* as2 = (const float*)d_in[7];
    const float* ad2 = (const float*)d_in[8];
    const float* b2  = (const float*)d_in[9];
    const float* Wh  = (const float*)d_in[10];
    const float* bh  = (const float*)d_in[11];
    float* out = (float*)d_out;

    int n  = in_sizes[0] / 256;   // 50000
    int ne = in_sizes[1] / 6;     // 250000

    void* p;
    cudaGetSymbolAddress(&p, g_hcat); __half* hcat = (__half*)p;
    cudaGetSymbolAddress(&p, g_h1);   float*  h1   = (float*)p;
    cudaGetSymbolAddress(&p, g_as);   float*  asb  = (float*)p;
    cudaGetSymbolAddress(&p, g_ad);   float*  adb  = (float*)p;
    cudaGetSymbolAddress(&p, g_cnt);  int*    cnt  = (int*)p;
    cudaGetSymbolAddress(&p, g_cur);  int*    cur  = (int*)p;
    cudaGetSymbolAddress(&p, g_off);  int*    off  = (int*)p;
    cudaGetSymbolAddress(&p, g_csr);  int*    csr  = (int*)p;

    cudaFuncSetAttribute(gemm_fused, cudaFuncAttributeMaxDynamicSharedMemorySize, GSMEM);

    dim3 ggrid((n + 127) / 128, 6);

    // order chosen so gemm_fused is the 4th launch (ncu lands there)
    init_all<<<(TT * n + 255) / 256, 256>>>(cnt, cur, asb, adb, TT * n);
    hist_kernel<<<(TT * ne + 255) / 256, 256>>>(ei, cnt, n, ne);
    scan_off<<<TT, 1024>>>(cnt, off, n);

    // ---- layer 1 GEMM + dots (4th launch) ----
    gemm_fused<<<ggrid, 256, GSMEM>>>(z, W1, hcat, as1, ad1, asb, adb, n);

    fill_kernel<<<(TT * ne + 255) / 256, 256>>>(ei, off, cur, csr, n, ne);

    agg_kernel<<<(n + 7) / 8, 256>>>(off, csr, hcat, asb, adb, b1,
                                     h1, Wh, bh, out, 0, n, ne);

    // ---- layer 2 ----
    zero_asad<<<(TT * n + 255) / 256, 256>>>(asb, adb, TT * n);
    gemm_fused<<<ggrid, 256, GSMEM>>>(h1, W2, hcat, as2, ad2, asb, adb, n);
    agg_kernel<<<(n + 7) / 8, 256>>>(off, csr, hcat, asb, adb, b2,
                                     h1 /*unused*/, Wh, bh, out, 1, n, ne);
}

// round 12
// speedup vs baseline: 1.4176x; 1.1628x over previous
#include <cuda_runtime.h>
#include <cuda_fp16.h>
#include <cstdint>

#define NMAX 50048
#define EMAX 250112
#define TT 3

// ---------------- scratch (static device globals; no allocation) ----------------
__device__ __half g_hcat[TT * NMAX * 256]; // per-type h = x @ W[t], fp16 (gather-only)
__device__ __half g_h1[NMAX * 256];        // layer-1 output (fp16: layer-2 GEMM input)
__device__ __half g_z16[NMAX * 256];       // z converted to fp16
__device__ __half g_wt16[2 * TT * 65536];  // W transposed+converted: [layer][t][n][k]
__device__ float  g_as[TT * NMAX];         // a_src per type (atomic-accumulated)
__device__ float  g_ad[TT * NMAX];         // a_dst per type
__device__ int    g_cnt[TT * NMAX];
__device__ int    g_cur[TT * NMAX];
__device__ int    g_off[TT * (NMAX + 1)];
__device__ int    g_csr[TT * EMAX];

// ---------------- small float4 helpers ----------------
__device__ __forceinline__ float4 f4add(float4 a, float4 b) {
    return make_float4(a.x + b.x, a.y + b.y, a.z + b.z, a.w + b.w);
}
__device__ __forceinline__ float4 f4fma(float4 a, float s, float4 c) {
    return make_float4(fmaf(a.x, s, c.x), fmaf(a.y, s, c.y),
                       fmaf(a.z, s, c.z), fmaf(a.w, s, c.w));
}
__device__ __forceinline__ float4 f4relu(float4 a) {
    return make_float4(fmaxf(a.x, 0.f), fmaxf(a.y, 0.f),
                       fmaxf(a.z, 0.f), fmaxf(a.w, 0.f));
}

// ============ converts ============
// z fp32 -> fp16, 8 elems/thread
__global__ void cvt_z(const float* __restrict__ X, __half* __restrict__ Y, int total8) {
    int i = blockIdx.x * blockDim.x + threadIdx.x;
    if (i >= total8) return;
    const float4* s = (const float4*)X + 2 * (size_t)i;
    float4 a = s[0], b = s[1];
    uint4 o;
    *(__half2*)&o.x = __floats2half2_rn(a.x, a.y);
    *(__half2*)&o.y = __floats2half2_rn(a.z, a.w);
    *(__half2*)&o.z = __floats2half2_rn(b.x, b.y);
    *(__half2*)&o.w = __floats2half2_rn(b.z, b.w);
    ((uint4*)Y)[i] = o;
}

// W[z][k][n] fp32 -> WT[z][n][k] fp16 (z = layer*3 + type)
__global__ void cvt_w(const float* __restrict__ Wa, const float* __restrict__ Wb,
                      __half* __restrict__ WT)
{
    __shared__ float tile[32][33];
    int z = blockIdx.z;
    const float* W = (z < TT ? Wa : Wb) + (size_t)(z % TT) * 65536;
    __half* O = WT + (size_t)z * 65536;
    int x  = blockIdx.x * 32 + threadIdx.x;
    int y0 = blockIdx.y * 32;
#pragma unroll
    for (int j = 0; j < 32; j += 8)
        tile[threadIdx.y + j][threadIdx.x] = W[(size_t)(y0 + threadIdx.y + j) * 256 + x];
    __syncthreads();
    int x2 = blockIdx.y * 32 + threadIdx.x;
    int y2 = blockIdx.x * 32;
#pragma unroll
    for (int j = 0; j < 32; j += 8)
        O[(size_t)(y2 + threadIdx.y + j) * 256 + x2] =
            __float2half_rn(tile[threadIdx.x][threadIdx.y + j]);
}

// ============ fused fp16 GEMM + attention dots ============
// hcat[t][n][256](fp16) = X16[n][256] @ W[t]; A fp16 [m][k], B fp16 transposed [n][k].
// BM=128, BN=128, BK=32, 2-stage cp.async, mma.sync.m16n8k16.f32.f16.f16.f32.
// 8 warps: 4 in M x 2 in N, warp tile 32x64. grid = (ceil(n/128), 6).
// Smem rows: 32 fp16 = 16 u32, padded to PITCH=20 u32 (80B; 16B-aligned, conflict-free frags).
#define PITCH  20
#define ATILE  (128 * PITCH)
#define BTILE  (128 * PITCH)
#define GSMEM  (2 * (ATILE + BTILE) * 4)   // 40960 B

__global__ __launch_bounds__(256) void gemm_fused(
    const __half* __restrict__ X, const __half* __restrict__ WT,
    __half* __restrict__ Hcat,
    const float* __restrict__ as_full, const float* __restrict__ ad_full,
    float* __restrict__ as_out, float* __restrict__ ad_out, int nrows)
{
    extern __shared__ uint32_t dsm[];
    uint32_t* As = dsm;               // [2][ATILE]  (rows = m)
    uint32_t* Bs = dsm + 2 * ATILE;   // [2][BTILE]  (rows = n, k-contiguous)

    int tid  = threadIdx.x;
    int lane = tid & 31, warp = tid >> 5;
    int wm = warp >> 1, wn = warp & 1;
    int g  = lane >> 2, tig = lane & 3;
    int bm = blockIdx.x * 128;
    int t  = blockIdx.y >> 1;
    int bn = (blockIdx.y & 1) * 128;
    const __half* Wt = WT + (size_t)t * 65536;
    __half* Hout = Hcat + (size_t)t * nrows * 256;

    // per chunk: A 128 rows x 2 chunks16B, B 128 rows x 2 chunks16B -> 512 cp.async, 2/thread each
    auto stage = [&](int st, int k0) {
#pragma unroll
        for (int p = 0; p < 2; p++) {
            int i = tid + p * 256;
            int r = i >> 2, c = i & 3;
            uint32_t d = (uint32_t)__cvta_generic_to_shared(
                &As[st * ATILE + r * PITCH + c * 4]);
            const __half* s = X + (size_t)(bm + r) * 256 + k0 + c * 8;
            int sz = (bm + r) < nrows ? 16 : 0;
            asm volatile("cp.async.ca.shared.global [%0], [%1], 16, %2;"
                         :: "r"(d), "l"(s), "r"(sz));
        }
#pragma unroll
        for (int p = 0; p < 2; p++) {
            int i = tid + p * 256;
            int r = i >> 2, c = i & 3;
            uint32_t d = (uint32_t)__cvta_generic_to_shared(
                &Bs[st * BTILE + r * PITCH + c * 4]);
            const __half* s = Wt + (size_t)(bn + r) * 256 + k0 + c * 8;
            asm volatile("cp.async.ca.shared.global [%0], [%1], 16;"
                         :: "r"(d), "l"(s));
        }
        asm volatile("cp.async.commit_group;");
    };

    float acc[2][8][4];
#pragma unroll
    for (int a = 0; a < 2; a++)
#pragma unroll
        for (int b = 0; b < 8; b++)
#pragma unroll
            for (int c = 0; c < 4; c++) acc[a][b][c] = 0.f;

    stage(0, 0);
    for (int k0 = 0; k0 < 256; k0 += 32) {
        int cur = (k0 >> 5) & 1;
        if (k0 + 32 < 256) {
            stage(cur ^ 1, k0 + 32);
            asm volatile("cp.async.wait_group 1;");
        } else {
            asm volatile("cp.async.wait_group 0;");
        }
        __syncthreads();

        const uint32_t* Ac = As + cur * ATILE;
        const uint32_t* Bc = Bs + cur * BTILE;
#pragma unroll
        for (int s = 0; s < 2; s++) {          // two K=16 steps per 32-chunk
            int kb = s * 8;                    // u32 offset within row
            uint32_t a[2][4], b[8][2];
#pragma unroll
            for (int mm = 0; mm < 2; mm++) {
                int row = wm * 32 + mm * 16 + g;
                a[mm][0] = Ac[row * PITCH + kb + tig];
                a[mm][1] = Ac[(row + 8) * PITCH + kb + tig];
                a[mm][2] = Ac[row * PITCH + kb + tig + 4];
                a[mm][3] = Ac[(row + 8) * PITCH + kb + tig + 4];
            }
#pragma unroll
            for (int nn = 0; nn < 8; nn++) {
                int col = wn * 64 + nn * 8 + g;
                b[nn][0] = Bc[col * PITCH + kb + tig];
                b[nn][1] = Bc[col * PITCH + kb + tig + 4];
            }
#pragma unroll
            for (int mm = 0; mm < 2; mm++)
#pragma unroll
                for (int nn = 0; nn < 8; nn++)
                    asm volatile(
                        "mma.sync.aligned.m16n8k16.row.col.f32.f16.f16.f32 "
                        "{%0,%1,%2,%3}, {%4,%5,%6,%7}, {%8,%9}, {%0,%1,%2,%3};"
                        : "+f"(acc[mm][nn][0]), "+f"(acc[mm][nn][1]),
                          "+f"(acc[mm][nn][2]), "+f"(acc[mm][nn][3])
                        : "r"(a[mm][0]), "r"(a[mm][1]), "r"(a[mm][2]), "r"(a[mm][3]),
                          "r"(b[nn][0]), "r"(b[nn][1]));
        }
        __syncthreads();
    }

    // ---- store H tile as fp16 ----
#pragma unroll
    for (int mm = 0; mm < 2; mm++)
#pragma unroll
        for (int nn = 0; nn < 8; nn++) {
            int row = bm + wm * 32 + mm * 16 + g;
            int col = bn + wn * 64 + nn * 8 + 2 * tig;
            if (row < nrows)
                *(__half2*)(Hout + (size_t)row * 256 + col) =
                    __floats2half2_rn(acc[mm][nn][0], acc[mm][nn][1]);
            if (row + 8 < nrows)
                *(__half2*)(Hout + (size_t)(row + 8) * 256 + col) =
                    __floats2half2_rn(acc[mm][nn][2], acc[mm][nn][3]);
        }

    // ---- fused attention dots: partial h.a_s / h.a_d over this CTA's 128 cols ----
    {
        const float* avs = as_full + t * 256;
        const float* avd = ad_full + t * 256;
        float ds[2][2] = {{0.f, 0.f}, {0.f, 0.f}};
        float dd[2][2] = {{0.f, 0.f}, {0.f, 0.f}};
#pragma unroll
        for (int mm = 0; mm < 2; mm++)
#pragma unroll
            for (int nn = 0; nn < 8; nn++) {
                int col = bn + wn * 64 + nn * 8 + 2 * tig;
                float a0 = __ldg(&avs[col]), a1 = __ldg(&avs[col + 1]);
                float d0 = __ldg(&avd[col]), d1 = __ldg(&avd[col + 1]);
                ds[mm][0] += acc[mm][nn][0] * a0 + acc[mm][nn][1] * a1;
                ds[mm][1] += acc[mm][nn][2] * a0 + acc[mm][nn][3] * a1;
                dd[mm][0] += acc[mm][nn][0] * d0 + acc[mm][nn][1] * d1;
                dd[mm][1] += acc[mm][nn][2] * d0 + acc[mm][nn][3] * d1;
            }
#pragma unroll
        for (int o = 1; o <= 2; o <<= 1)
#pragma unroll
            for (int mm = 0; mm < 2; mm++)
#pragma unroll
                for (int h = 0; h < 2; h++) {
                    ds[mm][h] += __shfl_xor_sync(0xffffffffu, ds[mm][h], o);
                    dd[mm][h] += __shfl_xor_sync(0xffffffffu, dd[mm][h], o);
                }
        if (tig == 0) {
            float* aso = as_out + (size_t)t * nrows;
            float* ado = ad_out + (size_t)t * nrows;
#pragma unroll
            for (int mm = 0; mm < 2; mm++)
#pragma unroll
                for (int h = 0; h < 2; h++) {
                    int row = bm + wm * 32 + mm * 16 + g + h * 8;
                    if (row < nrows) {
                        atomicAdd(&aso[row], ds[mm][h]);
                        atomicAdd(&ado[row], dd[mm][h]);
                    }
                }
        }
    }
}

// ============ init: counts + cursors + dot accumulators (layer 1) ============
__global__ void init_all(int* __restrict__ cnt, int* __restrict__ cur,
                         float* __restrict__ a, float* __restrict__ b, int total) {
    int i = blockIdx.x * blockDim.x + threadIdx.x;
    if (i < total) { cnt[i] = 0; cur[i] = 0; a[i] = 0.f; b[i] = 0.f; }
}

__global__ void zero_asad(float* __restrict__ a, float* __restrict__ b, int total) {
    int i = blockIdx.x * blockDim.x + threadIdx.x;
    if (i < total) { a[i] = 0.f; b[i] = 0.f; }
}

// ============ CSR build (once; graph shared by both layers) ============
__global__ void hist_kernel(const int* __restrict__ ei, int* __restrict__ cnt,
                            int n, int ne)
{
    int i = blockIdx.x * blockDim.x + threadIdx.x;
    if (i >= TT * ne) return;
    int t = i / ne, e = i - t * ne;
    int d = ei[(size_t)t * 2 * ne + ne + e];
    atomicAdd(&cnt[t * n + d], 1);
}

__global__ __launch_bounds__(1024) void scan_off(
    const int* __restrict__ cnt, int* __restrict__ off, int n)
{
    int t = blockIdx.x;
    const int* c = cnt + t * n;
    int* o = off + t * (n + 1);
    __shared__ int wsum[32];
    __shared__ int carry_sh;
    int tid = threadIdx.x, lane = tid & 31, wid = tid >> 5;
    if (tid == 0) carry_sh = 0;
    __syncthreads();
    for (int base = 0; base < n; base += 1024) {
        int i = base + tid;
        int v = (i < n) ? c[i] : 0;
        int x = v;
#pragma unroll
        for (int o2 = 1; o2 < 32; o2 <<= 1) {
            int y = __shfl_up_sync(0xffffffffu, x, o2);
            if (lane >= o2) x += y;
        }
        if (lane == 31) wsum[wid] = x;
        __syncthreads();
        if (wid == 0) {
            int s = wsum[lane];
#pragma unroll
            for (int o2 = 1; o2 < 32; o2 <<= 1) {
                int y = __shfl_up_sync(0xffffffffu, s, o2);
                if (lane >= o2) s += y;
            }
            wsum[lane] = s;
        }
        __syncthreads();
        int incl  = x + (wid > 0 ? wsum[wid - 1] : 0);
        int carry = carry_sh;
        if (i < n) o[i] = carry + incl - v;
        __syncthreads();
        if (tid == 1023) carry_sh = carry + wsum[31];
        __syncthreads();
    }
    if (threadIdx.x == 0) o[n] = carry_sh;
}

__global__ void fill_kernel(const int* __restrict__ ei, const int* __restrict__ off,
                            int* __restrict__ cur, int* __restrict__ csr,
                            int n, int ne)
{
    int i = blockIdx.x * blockDim.x + threadIdx.x;
    if (i >= TT * ne) return;
    int t = i / ne, e = i - t * ne;
    const int* base = ei + (size_t)t * 2 * ne;
    int s = base[e], d = base[ne + e];
    int pos = off[t * (n + 1) + d] + atomicAdd(&cur[t * n + d], 1);
    csr[t * ne + pos] = s;
}

// ============ fused softmax + aggregate + bias + relu (+ head) : warp per dst ============
// mode 0: outrow16[i] = fp16(relu(sum_t GAT_t(i) + bias))   (layer-2 GEMM input)
// mode 1: headout[i]  = sigmoid(relu(...) . Wh + bh)
__global__ __launch_bounds__(256) void agg_kernel(
    const int* __restrict__ off, const int* __restrict__ csr,
    const __half* __restrict__ hcat, const float* __restrict__ asb,
    const float* __restrict__ adb, const float* __restrict__ bias,
    __half* __restrict__ outrow, const float* __restrict__ Wh,
    const float* __restrict__ bh, float* __restrict__ headout,
    int mode, int n, int ne)
{
    int w    = (blockIdx.x * blockDim.x + threadIdx.x) >> 5;
    int lane = threadIdx.x & 31;
    if (w >= n) return;

    float4 a0 = make_float4(0.f, 0.f, 0.f, 0.f);   // cols 8*lane .. +3
    float4 a1 = make_float4(0.f, 0.f, 0.f, 0.f);   // cols 8*lane+4 .. +7

#pragma unroll
    for (int t = 0; t < TT; t++) {
        int o0 = off[t * (n + 1) + w];
        int deg = off[t * (n + 1) + w + 1] - o0;
        if (deg == 0) continue;
        float adt = adb[t * n + w];
        const __half* ht  = hcat + (size_t)t * n * 256;
        const float* ast  = asb + t * n;
        const int*   srcs = csr + (size_t)t * ne + o0;
        float4 t0 = make_float4(0.f, 0.f, 0.f, 0.f);
        float4 t1 = make_float4(0.f, 0.f, 0.f, 0.f);
        float den = 0.f;
        for (int base = 0; base < deg; base += 32) {
            int m = min(32, deg - base);
            int   sj = 0;
            float ex = 0.f;
            if (lane < m) {
                sj = srcs[base + lane];
                float e = ast[sj] + adt;
                e = e > 0.f ? e : 0.2f * e;      // leaky_relu 0.2
                ex = __expf(e);                   // shift-invariant: no max needed
            }
            float s = ex;
#pragma unroll
            for (int o = 16; o; o >>= 1) s += __shfl_xor_sync(0xffffffffu, s, o);
            den += s;
            for (int j = 0; j < m; j++) {
                int   sn = __shfl_sync(0xffffffffu, sj, j);
                float wt = __shfl_sync(0xffffffffu, ex, j);
                uint4 v = *(const uint4*)(ht + (size_t)sn * 256 + lane * 8);
                float2 f0 = __half22float2(*(__half2*)&v.x);
                float2 f1 = __half22float2(*(__half2*)&v.y);
                float2 f2 = __half22float2(*(__half2*)&v.z);
                float2 f3 = __half22float2(*(__half2*)&v.w);
                t0.x = fmaf(f0.x, wt, t0.x); t0.y = fmaf(f0.y, wt, t0.y);
                t0.z = fmaf(f1.x, wt, t0.z); t0.w = fmaf(f1.y, wt, t0.w);
                t1.x = fmaf(f2.x, wt, t1.x); t1.y = fmaf(f2.y, wt, t1.y);
                t1.z = fmaf(f3.x, wt, t1.z); t1.w = fmaf(f3.y, wt, t1.w);
            }
        }
        float inv = 1.f / den;
        a0 = f4fma(t0, inv, a0);
        a1 = f4fma(t1, inv, a1);
    }

    // bias sum over the 3 types ([3][64] float4 view), cols 8*lane -> float4 idx 2*lane
    const float4* bb = (const float4*)bias;
    float4 b0 = f4add(f4add(__ldg(&bb[2 * lane]), __ldg(&bb[64 + 2 * lane])),
                      __ldg(&bb[128 + 2 * lane]));
    float4 b1 = f4add(f4add(__ldg(&bb[2 * lane + 1]), __ldg(&bb[64 + 2 * lane + 1])),
                      __ldg(&bb[128 + 2 * lane + 1]));
    float4 r0 = f4relu(f4add(a0, b0));
    float4 r1 = f4relu(f4add(a1, b1));

    if (mode == 0) {
        uint4 o;
        *(__half2*)&o.x = __floats2half2_rn(r0.x, r0.y);
        *(__half2*)&o.y = __floats2half2_rn(r0.z, r0.w);
        *(__half2*)&o.z = __floats2half2_rn(r1.x, r1.y);
        *(__half2*)&o.w = __floats2half2_rn(r1.z, r1.w);
        *(uint4*)(outrow + (size_t)w * 256 + lane * 8) = o;
    } else {
        const float4* wh = (const float4*)Wh;
        float4 q0 = __ldg(&wh[2 * lane]);
        float4 q1 = __ldg(&wh[2 * lane + 1]);
        float s = r0.x * q0.x + r0.y * q0.y + r0.z * q0.z + r0.w * q0.w +
                  r1.x * q1.x + r1.y * q1.y + r1.z * q1.z + r1.w * q1.w;
#pragma unroll
        for (int o = 16; o; o >>= 1) s += __shfl_xor_sync(0xffffffffu, s, o);
        if (lane == 0) headout[w] = 1.f / (1.f + __expf(-(s + bh[0])));
    }
}

// ---------------- host orchestration ----------------
extern "C" void kernel_launch(void* const* d_in, const int* in_sizes, int n_in,
                              void* d_out, int out_size)
{
    const float* z   = (const float*)d_in[0];
    const int*   ei  = (const int*)d_in[1];
    const float* W1  = (const float*)d_in[2];
    const float* as1 = (const float*)d_in[3];
    const float* ad1 = (const float*)d_in[4];
    const float* b1  = (const float*)d_in[5];
    const float* W2  = (const float*)d_in[6];
    const float* as2 = (const float*)d_in[7];
    const float* ad2 = (const float*)d_in[8];
    const float* b2  = (const float*)d_in[9];
    const float* Wh  = (const float*)d_in[10];
    const float* bh  = (const float*)d_in[11];
    float* out = (float*)d_out;

    int n  = in_sizes[0] / 256;   // 50000
    int ne = in_sizes[1] / 6;     // 250000

    void* p;
    cudaGetSymbolAddress(&p, g_hcat); __half* hcat = (__half*)p;
    cudaGetSymbolAddress(&p, g_h1);   __half* h1   = (__half*)p;
    cudaGetSymbolAddress(&p, g_z16);  __half* z16  = (__half*)p;
    cudaGetSymbolAddress(&p, g_wt16); __half* wt16 = (__half*)p;
    cudaGetSymbolAddress(&p, g_as);   float*  asb  = (float*)p;
    cudaGetSymbolAddress(&p, g_ad);   float*  adb  = (float*)p;
    cudaGetSymbolAddress(&p, g_cnt);  int*    cnt  = (int*)p;
    cudaGetSymbolAddress(&p, g_cur);  int*    cur  = (int*)p;
    cudaGetSymbolAddress(&p, g_off);  int*    off  = (int*)p;
    cudaGetSymbolAddress(&p, g_csr);  int*    csr  = (int*)p;

    cudaFuncSetAttribute(gemm_fused, cudaFuncAttributeMaxDynamicSharedMemorySize, GSMEM);

    dim3 ggrid((n + 127) / 128, 6);

    // launch order keeps gemm_fused as the 4th launch (ncu -s 5 lands there)
    init_all<<<(TT * n + 255) / 256, 256>>>(cnt, cur, asb, adb, TT * n);
    cvt_w<<<dim3(8, 8, 2 * TT), dim3(32, 8)>>>(W1, W2, wt16);
    cvt_z<<<(n * 32 + 255) / 256, 256>>>(z, z16, n * 32);

    // ---- layer 1 GEMM + dots (4th launch) ----
    gemm_fused<<<ggrid, 256, GSMEM>>>(z16, wt16, hcat, as1, ad1, asb, adb, n);

    hist_kernel<<<(TT * ne + 255) / 256, 256>>>(ei, cnt, n, ne);
    scan_off<<<TT, 1024>>>(cnt, off, n);
    fill_kernel<<<(TT * ne + 255) / 256, 256>>>(ei, off, cur, csr, n, ne);

    agg_kernel<<<(n + 7) / 8, 256>>>(off, csr, hcat, asb, adb, b1,
                                     h1, Wh, bh, out, 0, n, ne);

    // ---- layer 2 ----
    zero_asad<<<(TT * n + 255) / 256, 256>>>(asb, adb, TT * n);
    gemm_fused<<<ggrid, 256, GSMEM>>>(h1, wt16 + (size_t)TT * 65536, hcat,
                                      as2, ad2, asb, adb, n);
    agg_kernel<<<(n + 7) / 8, 256>>>(off, csr, hcat, asb, adb, b2,
                                     h1 /*unused in mode 1*/, Wh, bh, out, 1, n, ne);
}

// round 13
// speedup vs baseline: 1.4447x; 1.0191x over previous
#include <cuda_runtime.h>
#include <cuda_fp16.h>
#include <cstdint>

#define NMAX 50048
#define EMAX 250112
#define TT 3

// ---------------- scratch (static device globals; no allocation) ----------------
__device__ __half g_hcat[TT * NMAX * 256]; // per-type h = x @ W[t], fp16 (gather-only)
__device__ __half g_h1[NMAX * 256];        // layer-1 output (fp16: layer-2 GEMM input)
__device__ __half g_z16[NMAX * 256];       // z converted to fp16
__device__ __half g_wt16[2 * TT * 65536];  // W transposed+converted: [layer][t][n][k]
__device__ float  g_as[2 * TT * NMAX];     // a_src per layer/type (atomic-accumulated)
__device__ float  g_ad[2 * TT * NMAX];     // a_dst per layer/type
__device__ int    g_cnt[TT * NMAX];
__device__ int    g_cur[TT * NMAX];
__device__ int    g_off[TT * (NMAX + 1)];
__device__ int    g_csr[TT * EMAX];

// ---------------- small float4 helpers ----------------
__device__ __forceinline__ float4 f4add(float4 a, float4 b) {
    return make_float4(a.x + b.x, a.y + b.y, a.z + b.z, a.w + b.w);
}
__device__ __forceinline__ float4 f4fma(float4 a, float s, float4 c) {
    return make_float4(fmaf(a.x, s, c.x), fmaf(a.y, s, c.y),
                       fmaf(a.z, s, c.z), fmaf(a.w, s, c.w));
}
__device__ __forceinline__ float4 f4relu(float4 a) {
    return make_float4(fmaxf(a.x, 0.f), fmaxf(a.y, 0.f),
                       fmaxf(a.z, 0.f), fmaxf(a.w, 0.f));
}

// ============ prep: z fp32->fp16 + zero counts/cursors/dot-accums ============
__global__ void prep(const float* __restrict__ X, __half* __restrict__ Y,
                     int* __restrict__ cnt, int* __restrict__ cur,
                     float* __restrict__ a, float* __restrict__ b, int n)
{
    int i = blockIdx.x * blockDim.x + threadIdx.x;
    int total8 = n * 32;
    if (i < total8) {
        const float4* s = (const float4*)X + 2 * (size_t)i;
        float4 p = s[0], q = s[1];
        uint4 o;
        *(__half2*)&o.x = __floats2half2_rn(p.x, p.y);
        *(__half2*)&o.y = __floats2half2_rn(p.z, p.w);
        *(__half2*)&o.z = __floats2half2_rn(q.x, q.y);
        *(__half2*)&o.w = __floats2half2_rn(q.z, q.w);
        ((uint4*)Y)[i] = o;
    }
    if (i < TT * n) { cnt[i] = 0; cur[i] = 0; }
    if (i < 2 * TT * n) { a[i] = 0.f; b[i] = 0.f; }
}

// W[z][k][n] fp32 -> WT[z][n][k] fp16 (z = layer*3 + type)
__global__ void cvt_w(const float* __restrict__ Wa, const float* __restrict__ Wb,
                      __half* __restrict__ WT)
{
    __shared__ float tile[32][33];
    int z = blockIdx.z;
    const float* W = (z < TT ? Wa : Wb) + (size_t)(z % TT) * 65536;
    __half* O = WT + (size_t)z * 65536;
    int x  = blockIdx.x * 32 + threadIdx.x;
    int y0 = blockIdx.y * 32;
#pragma unroll
    for (int j = 0; j < 32; j += 8)
        tile[threadIdx.y + j][threadIdx.x] = W[(size_t)(y0 + threadIdx.y + j) * 256 + x];
    __syncthreads();
    int x2 = blockIdx.y * 32 + threadIdx.x;
    int y2 = blockIdx.x * 32;
#pragma unroll
    for (int j = 0; j < 32; j += 8)
        O[(size_t)(y2 + threadIdx.y + j) * 256 + x2] =
            __float2half_rn(tile[threadIdx.x][threadIdx.y + j]);
}

// ============ fused fp16 GEMM + attention dots (ldmatrix fragments) ============
// hcat[t][n][256](fp16) = X16[n][256] @ W[t]; A fp16 [m][k], B fp16 transposed [n][k].
// BM=128, BN=128, BK=32, 2-stage cp.async, mma.sync.m16n8k16 + ldmatrix.x4.
// 8 warps: 4 in M x 2 in N, warp tile 32x64. grid = (ceil(n/128), 6).
#define PITCH  20
#define ATILE  (128 * PITCH)
#define BTILE  (128 * PITCH)
#define GSMEM  (2 * (ATILE + BTILE) * 4)   // 40960 B

#define LDSM_X4(r0, r1, r2, r3, addr) \
    asm volatile("ldmatrix.sync.aligned.m8n8.x4.shared.b16 {%0,%1,%2,%3}, [%4];" \
                 : "=r"(r0), "=r"(r1), "=r"(r2), "=r"(r3) : "r"(addr))

__global__ __launch_bounds__(256) void gemm_fused(
    const __half* __restrict__ X, const __half* __restrict__ WT,
    __half* __restrict__ Hcat,
    const float* __restrict__ as_full, const float* __restrict__ ad_full,
    float* __restrict__ as_out, float* __restrict__ ad_out, int nrows)
{
    extern __shared__ uint32_t dsm[];
    uint32_t* As = dsm;               // [2][ATILE]  (rows = m, k-contiguous)
    uint32_t* Bs = dsm + 2 * ATILE;   // [2][BTILE]  (rows = n, k-contiguous)

    int tid  = threadIdx.x;
    int lane = tid & 31, warp = tid >> 5;
    int wm = warp >> 1, wn = warp & 1;
    int g  = lane >> 2, tig = lane & 3;
    int bm = blockIdx.x * 128;
    int t  = blockIdx.y >> 1;
    int bn = (blockIdx.y & 1) * 128;
    const __half* Wt = WT + (size_t)t * 65536;
    __half* Hout = Hcat + (size_t)t * nrows * 256;

    uint32_t smem0 = (uint32_t)__cvta_generic_to_shared(dsm);

    // per-lane ldmatrix row/koff offsets (u32 units), hoisted out of the mainloop
    uint32_t offA[2], offB[4];
#pragma unroll
    for (int mm = 0; mm < 2; mm++)
        offA[mm] = (uint32_t)((wm * 32 + mm * 16 + (lane & 15)) * PITCH
                              + ((lane >> 4) << 2));
#pragma unroll
    for (int p = 0; p < 4; p++)
        offB[p] = (uint32_t)((wn * 64 + p * 16 + ((lane & 7) | ((lane >> 1) & 8))) * PITCH
                             + (((lane >> 3) & 1) << 2));

    auto stage = [&](int st, int k0) {
#pragma unroll
        for (int p = 0; p < 2; p++) {
            int i = tid + p * 256;
            int r = i >> 2, c = i & 3;
            uint32_t d = smem0 + (uint32_t)((st * ATILE + r * PITCH + c * 4) << 2);
            const __half* s = X + (size_t)(bm + r) * 256 + k0 + c * 8;
            int sz = (bm + r) < nrows ? 16 : 0;
            asm volatile("cp.async.ca.shared.global [%0], [%1], 16, %2;"
                         :: "r"(d), "l"(s), "r"(sz));
        }
#pragma unroll
        for (int p = 0; p < 2; p++) {
            int i = tid + p * 256;
            int r = i >> 2, c = i & 3;
            uint32_t d = smem0 + (uint32_t)((2 * ATILE + st * BTILE + r * PITCH + c * 4) << 2);
            const __half* s = Wt + (size_t)(bn + r) * 256 + k0 + c * 8;
            asm volatile("cp.async.ca.shared.global [%0], [%1], 16;"
                         :: "r"(d), "l"(s));
        }
        asm volatile("cp.async.commit_group;");
    };

    float acc[2][8][4];
#pragma unroll
    for (int a = 0; a < 2; a++)
#pragma unroll
        for (int b = 0; b < 8; b++)
#pragma unroll
            for (int c = 0; c < 4; c++) acc[a][b][c] = 0.f;

    stage(0, 0);
    for (int k0 = 0; k0 < 256; k0 += 32) {
        int cur = (k0 >> 5) & 1;
        if (k0 + 32 < 256) {
            stage(cur ^ 1, k0 + 32);
            asm volatile("cp.async.wait_group 1;");
        } else {
            asm volatile("cp.async.wait_group 0;");
        }
        __syncthreads();

        uint32_t abase = smem0 + (uint32_t)((cur * ATILE) << 2);
        uint32_t bbase = smem0 + (uint32_t)((2 * ATILE + cur * BTILE) << 2);
#pragma unroll
        for (int s = 0; s < 2; s++) {          // two K=16 steps per 32-chunk
            uint32_t kb = (uint32_t)(s * 8) << 2;   // byte offset within row
            uint32_t a[2][4], b[8][2];
#pragma unroll
            for (int mm = 0; mm < 2; mm++)
                LDSM_X4(a[mm][0], a[mm][1], a[mm][2], a[mm][3],
                        abase + (offA[mm] << 2) + kb);
#pragma unroll
            for (int p = 0; p < 4; p++)
                LDSM_X4(b[2 * p][0], b[2 * p][1], b[2 * p + 1][0], b[2 * p + 1][1],
                        bbase + (offB[p] << 2) + kb);
#pragma unroll
            for (int mm = 0; mm < 2; mm++)
#pragma unroll
                for (int nn = 0; nn < 8; nn++)
                    asm volatile(
                        "mma.sync.aligned.m16n8k16.row.col.f32.f16.f16.f32 "
                        "{%0,%1,%2,%3}, {%4,%5,%6,%7}, {%8,%9}, {%0,%1,%2,%3};"
                        : "+f"(acc[mm][nn][0]), "+f"(acc[mm][nn][1]),
                          "+f"(acc[mm][nn][2]), "+f"(acc[mm][nn][3])
                        : "r"(a[mm][0]), "r"(a[mm][1]), "r"(a[mm][2]), "r"(a[mm][3]),
                          "r"(b[nn][0]), "r"(b[nn][1]));
        }
        __syncthreads();
    }

    // ---- store H tile as fp16 ----
#pragma unroll
    for (int mm = 0; mm < 2; mm++)
#pragma unroll
        for (int nn = 0; nn < 8; nn++) {
            int row = bm + wm * 32 + mm * 16 + g;
            int col = bn + wn * 64 + nn * 8 + 2 * tig;
            if (row < nrows)
                *(__half2*)(Hout + (size_t)row * 256 + col) =
                    __floats2half2_rn(acc[mm][nn][0], acc[mm][nn][1]);
            if (row + 8 < nrows)
                *(__half2*)(Hout + (size_t)(row + 8) * 256 + col) =
                    __floats2half2_rn(acc[mm][nn][2], acc[mm][nn][3]);
        }

    // ---- fused attention dots: partial h.a_s / h.a_d over this CTA's 128 cols ----
    {
        const float* avs = as_full + t * 256;
        const float* avd = ad_full + t * 256;
        float ds[2][2] = {{0.f, 0.f}, {0.f, 0.f}};
        float dd[2][2] = {{0.f, 0.f}, {0.f, 0.f}};
#pragma unroll
        for (int mm = 0; mm < 2; mm++)
#pragma unroll
            for (int nn = 0; nn < 8; nn++) {
                int col = bn + wn * 64 + nn * 8 + 2 * tig;
                float a0 = __ldg(&avs[col]), a1 = __ldg(&avs[col + 1]);
                float d0 = __ldg(&avd[col]), d1 = __ldg(&avd[col + 1]);
                ds[mm][0] += acc[mm][nn][0] * a0 + acc[mm][nn][1] * a1;
                ds[mm][1] += acc[mm][nn][2] * a0 + acc[mm][nn][3] * a1;
                dd[mm][0] += acc[mm][nn][0] * d0 + acc[mm][nn][1] * d1;
                dd[mm][1] += acc[mm][nn][2] * d0 + acc[mm][nn][3] * d1;
            }
#pragma unroll
        for (int o = 1; o <= 2; o <<= 1)
#pragma unroll
            for (int mm = 0; mm < 2; mm++)
#pragma unroll
                for (int h = 0; h < 2; h++) {
                    ds[mm][h] += __shfl_xor_sync(0xffffffffu, ds[mm][h], o);
                    dd[mm][h] += __shfl_xor_sync(0xffffffffu, dd[mm][h], o);
                }
        if (tig == 0) {
            float* aso = as_out + (size_t)t * nrows;
            float* ado = ad_out + (size_t)t * nrows;
#pragma unroll
            for (int mm = 0; mm < 2; mm++)
#pragma unroll
                for (int h = 0; h < 2; h++) {
                    int row = bm + wm * 32 + mm * 16 + g + h * 8;
                    if (row < nrows) {
                        atomicAdd(&aso[row], ds[mm][h]);
                        atomicAdd(&ado[row], dd[mm][h]);
                    }
                }
        }
    }
}

// ============ CSR build (once; graph shared by both layers) ============
__global__ void hist_kernel(const int* __restrict__ ei, int* __restrict__ cnt,
                            int n, int ne)
{
    int i = blockIdx.x * blockDim.x + threadIdx.x;
    if (i >= TT * ne) return;
    int t = i / ne, e = i - t * ne;
    int d = ei[(size_t)t * 2 * ne + ne + e];
    atomicAdd(&cnt[t * n + d], 1);
}

__global__ __launch_bounds__(1024) void scan_off(
    const int* __restrict__ cnt, int* __restrict__ off, int n)
{
    int t = blockIdx.x;
    const int* c = cnt + t * n;
    int* o = off + t * (n + 1);
    __shared__ int wsum[32];
    __shared__ int carry_sh;
    int tid = threadIdx.x, lane = tid & 31, wid = tid >> 5;
    if (tid == 0) carry_sh = 0;
    __syncthreads();
    for (int base = 0; base < n; base += 1024) {
        int i = base + tid;
        int v = (i < n) ? c[i] : 0;
        int x = v;
#pragma unroll
        for (int o2 = 1; o2 < 32; o2 <<= 1) {
            int y = __shfl_up_sync(0xffffffffu, x, o2);
            if (lane >= o2) x += y;
        }
        if (lane == 31) wsum[wid] = x;
        __syncthreads();
        if (wid == 0) {
            int s = wsum[lane];
#pragma unroll
            for (int o2 = 1; o2 < 32; o2 <<= 1) {
                int y = __shfl_up_sync(0xffffffffu, s, o2);
                if (lane >= o2) s += y;
            }
            wsum[lane] = s;
        }
        __syncthreads();
        int incl  = x + (wid > 0 ? wsum[wid - 1] : 0);
        int carry = carry_sh;
        if (i < n) o[i] = carry + incl - v;
        __syncthreads();
        if (tid == 1023) carry_sh = carry + wsum[31];
        __syncthreads();
    }
    if (threadIdx.x == 0) o[n] = carry_sh;
}

__global__ void fill_kernel(const int* __restrict__ ei, const int* __restrict__ off,
                            int* __restrict__ cur, int* __restrict__ csr,
                            int n, int ne)
{
    int i = blockIdx.x * blockDim.x + threadIdx.x;
    if (i >= TT * ne) return;
    int t = i / ne, e = i - t * ne;
    const int* base = ei + (size_t)t * 2 * ne;
    int s = base[e], d = base[ne + e];
    int pos = off[t * (n + 1) + d] + atomicAdd(&cur[t * n + d], 1);
    csr[t * ne + pos] = s;
}

// ============ fused softmax + aggregate + bias + relu (+ head) : warp per dst ============
// mode 0: outrow16[i] = fp16(relu(sum_t GAT_t(i) + bias))   (layer-2 GEMM input)
// mode 1: headout[i]  = sigmoid(relu(...) . Wh + bh)
__global__ __launch_bounds__(256) void agg_kernel(
    const int* __restrict__ off, const int* __restrict__ csr,
    const __half* __restrict__ hcat, const float* __restrict__ asb,
    const float* __restrict__ adb, const float* __restrict__ bias,
    __half* __restrict__ outrow, const float* __restrict__ Wh,
    const float* __restrict__ bh, float* __restrict__ headout,
    int mode, int n, int ne)
{
    int w    = (blockIdx.x * blockDim.x + threadIdx.x) >> 5;
    int lane = threadIdx.x & 31;
    if (w >= n) return;

    float4 a0 = make_float4(0.f, 0.f, 0.f, 0.f);   // cols 8*lane .. +3
    float4 a1 = make_float4(0.f, 0.f, 0.f, 0.f);   // cols 8*lane+4 .. +7

#pragma unroll
    for (int t = 0; t < TT; t++) {
        int o0 = off[t * (n + 1) + w];
        int deg = off[t * (n + 1) + w + 1] - o0;
        if (deg == 0) continue;
        float adt = adb[t * n + w];
        const __half* ht  = hcat + (size_t)t * n * 256;
        const float* ast  = asb + t * n;
        const int*   srcs = csr + (size_t)t * ne + o0;
        float4 t0 = make_float4(0.f, 0.f, 0.f, 0.f);
        float4 t1 = make_float4(0.f, 0.f, 0.f, 0.f);
        float den = 0.f;
        for (int base = 0; base < deg; base += 32) {
            int m = min(32, deg - base);
            int   sj = 0;
            float ex = 0.f;
            if (lane < m) {
                sj = srcs[base + lane];
                float e = ast[sj] + adt;
                e = e > 0.f ? e : 0.2f * e;      // leaky_relu 0.2
                ex = __expf(e);                   // shift-invariant: no max needed
            }
            float s = ex;
#pragma unroll
            for (int o = 16; o; o >>= 1) s += __shfl_xor_sync(0xffffffffu, s, o);
            den += s;
            for (int j = 0; j < m; j++) {
                int   sn = __shfl_sync(0xffffffffu, sj, j);
                float wt = __shfl_sync(0xffffffffu, ex, j);
                uint4 v = *(const uint4*)(ht + (size_t)sn * 256 + lane * 8);
                float2 f0 = __half22float2(*(__half2*)&v.x);
                float2 f1 = __half22float2(*(__half2*)&v.y);
                float2 f2 = __half22float2(*(__half2*)&v.z);
                float2 f3 = __half22float2(*(__half2*)&v.w);
                t0.x = fmaf(f0.x, wt, t0.x); t0.y = fmaf(f0.y, wt, t0.y);
                t0.z = fmaf(f1.x, wt, t0.z); t0.w = fmaf(f1.y, wt, t0.w);
                t1.x = fmaf(f2.x, wt, t1.x); t1.y = fmaf(f2.y, wt, t1.y);
                t1.z = fmaf(f3.x, wt, t1.z); t1.w = fmaf(f3.y, wt, t1.w);
            }
        }
        float inv = 1.f / den;
        a0 = f4fma(t0, inv, a0);
        a1 = f4fma(t1, inv, a1);
    }

    // bias sum over the 3 types ([3][64] float4 view), cols 8*lane -> float4 idx 2*lane
    const float4* bb = (const float4*)bias;
    float4 b0 = f4add(f4add(__ldg(&bb[2 * lane]), __ldg(&bb[64 + 2 * lane])),
                      __ldg(&bb[128 + 2 * lane]));
    float4 b1 = f4add(f4add(__ldg(&bb[2 * lane + 1]), __ldg(&bb[64 + 2 * lane + 1])),
                      __ldg(&bb[128 + 2 * lane + 1]));
    float4 r0 = f4relu(f4add(a0, b0));
    float4 r1 = f4relu(f4add(a1, b1));

    if (mode == 0) {
        uint4 o;
        *(__half2*)&o.x = __floats2half2_rn(r0.x, r0.y);
        *(__half2*)&o.y = __floats2half2_rn(r0.z, r0.w);
        *(__half2*)&o.z = __floats2half2_rn(r1.x, r1.y);
        *(__half2*)&o.w = __floats2half2_rn(r1.z, r1.w);
        *(uint4*)(outrow + (size_t)w * 256 + lane * 8) = o;
    } else {
        const float4* wh = (const float4*)Wh;
        float4 q0 = __ldg(&wh[2 * lane]);
        float4 q1 = __ldg(&wh[2 * lane + 1]);
        float s = r0.x * q0.x + r0.y * q0.y + r0.z * q0.z + r0.w * q0.w +
                  r1.x * q1.x + r1.y * q1.y + r1.z * q1.z + r1.w * q1.w;
#pragma unroll
        for (int o = 16; o; o >>= 1) s += __shfl_xor_sync(0xffffffffu, s, o);
        if (lane == 0) headout[w] = 1.f / (1.f + __expf(-(s + bh[0])));
    }
}

// ---------------- host orchestration ----------------
extern "C" void kernel_launch(void* const* d_in, const int* in_sizes, int n_in,
                              void* d_out, int out_size)
{
    const float* z   = (const float*)d_in[0];
    const int*   ei  = (const int*)d_in[1];
    const float* W1  = (const float*)d_in[2];
    const float* as1 = (const float*)d_in[3];
    const float* ad1 = (const float*)d_in[4];
    const float* b1  = (const float*)d_in[5];
    const float* W2  = (const float*)d_in[6];
    const float* as2 = (const float*)d_in[7];
    const float* ad2 = (const float*)d_in[8];
    const float* b2  = (const float*)d_in[9];
    const float* Wh  = (const float*)d_in[10];
    const float* bh  = (const float*)d_in[11];
    float* out = (float*)d_out;

    int n  = in_sizes[0] / 256;   // 50000
    int ne = in_sizes[1] / 6;     // 250000

    void* p;
    cudaGetSymbolAddress(&p, g_hcat); __half* hcat = (__half*)p;
    cudaGetSymbolAddress(&p, g_h1);   __half* h1   = (__half*)p;
    cudaGetSymbolAddress(&p, g_z16);  __half* z16  = (__half*)p;
    cudaGetSymbolAddress(&p, g_wt16); __half* wt16 = (__half*)p;
    cudaGetSymbolAddress(&p, g_as);   float*  asb  = (float*)p;
    cudaGetSymbolAddress(&p, g_ad);   float*  adb  = (float*)p;
    cudaGetSymbolAddress(&p, g_cnt);  int*    cnt  = (int*)p;
    cudaGetSymbolAddress(&p, g_cur);  int*    cur  = (int*)p;
    cudaGetSymbolAddress(&p, g_off);  int*    off  = (int*)p;
    cudaGetSymbolAddress(&p, g_csr);  int*    csr  = (int*)p;

    cudaFuncSetAttribute(gemm_fused, cudaFuncAttributeMaxDynamicSharedMemorySize, GSMEM);

    dim3 ggrid((n + 127) / 128, 6);
    float* asb2 = asb + (size_t)TT * n;
    float* adb2 = adb + (size_t)TT * n;

    // launch order keeps gemm_fused as the 4th launch (ncu lands there)
    prep<<<(n * 32 + 255) / 256, 256>>>(z, z16, cnt, cur, asb, adb, n);
    cvt_w<<<dim3(8, 8, 2 * TT), dim3(32, 8)>>>(W1, W2, wt16);
    hist_kernel<<<(TT * ne + 255) / 256, 256>>>(ei, cnt, n, ne);

    // ---- layer 1 GEMM + dots (4th launch) ----
    gemm_fused<<<ggrid, 256, GSMEM>>>(z16, wt16, hcat, as1, ad1, asb, adb, n);

    scan_off<<<TT, 1024>>>(cnt, off, n);
    fill_kernel<<<(TT * ne + 255) / 256, 256>>>(ei, off, cur, csr, n, ne);

    agg_kernel<<<(n + 7) / 8, 256>>>(off, csr, hcat, asb, adb, b1,
                                     h1, Wh, bh, out, 0, n, ne);

    // ---- layer 2 ----
    gemm_fused<<<ggrid, 256, GSMEM>>>(h1, wt16 + (size_t)TT * 65536, hcat,
                                      as2, ad2, asb2, adb2, n);
    agg_kernel<<<(n + 7) / 8, 256>>>(off, csr, hcat, asb2, adb2, b2,
                                     h1 /*unused in mode 1*/, Wh, bh, out, 1, n, ne);
}

// round 14
// speedup vs baseline: 1.5760x; 1.0909x over previous
#include <cuda_runtime.h>
#include <cuda_fp16.h>
#include <cstdint>

#define NMAX 50048
#define EMAX 250112
#define TT 3

// ---------------- scratch (static device globals; no allocation) ----------------
__device__ __half g_hcat[TT * NMAX * 256]; // per-type h = x @ W[t], fp16 (gather-only)
__device__ __half g_h1[NMAX * 256];        // layer-1 output (fp16: layer-2 GEMM input)
__device__ __half g_z16[NMAX * 256];       // z converted to fp16
__device__ __half g_wt16[2 * TT * 65536];  // W transposed+converted: [layer][t][n][k]
__device__ float  g_as[2 * TT * NMAX];     // a_src per layer/type (atomic-accumulated)
__device__ float  g_ad[2 * TT * NMAX];     // a_dst per layer/type
__device__ int    g_cnt[TT * NMAX];
__device__ int    g_cur[TT * NMAX];
__device__ int    g_off[TT * (NMAX + 1)];
__device__ int    g_csr[TT * EMAX];

// ---------------- small float4 helpers ----------------
__device__ __forceinline__ float4 f4add(float4 a, float4 b) {
    return make_float4(a.x + b.x, a.y + b.y, a.z + b.z, a.w + b.w);
}
__device__ __forceinline__ float4 f4fma(float4 a, float s, float4 c) {
    return make_float4(fmaf(a.x, s, c.x), fmaf(a.y, s, c.y),
                       fmaf(a.z, s, c.z), fmaf(a.w, s, c.w));
}
__device__ __forceinline__ float4 f4relu(float4 a) {
    return make_float4(fmaxf(a.x, 0.f), fmaxf(a.y, 0.f),
                       fmaxf(a.z, 0.f), fmaxf(a.w, 0.f));
}
__device__ __forceinline__ void acc8(float4& t0, float4& t1, uint4 v, float wt) {
    float2 f0 = __half22float2(*(__half2*)&v.x);
    float2 f1 = __half22float2(*(__half2*)&v.y);
    float2 f2 = __half22float2(*(__half2*)&v.z);
    float2 f3 = __half22float2(*(__half2*)&v.w);
    t0.x = fmaf(f0.x, wt, t0.x); t0.y = fmaf(f0.y, wt, t0.y);
    t0.z = fmaf(f1.x, wt, t0.z); t0.w = fmaf(f1.y, wt, t0.w);
    t1.x = fmaf(f2.x, wt, t1.x); t1.y = fmaf(f2.y, wt, t1.y);
    t1.z = fmaf(f3.x, wt, t1.z); t1.w = fmaf(f3.y, wt, t1.w);
}

// ============ prep: z fp32->fp16 + zero counts/cursors/dot-accums ============
__global__ void prep(const float* __restrict__ X, __half* __restrict__ Y,
                     int* __restrict__ cnt, int* __restrict__ cur,
                     float* __restrict__ a, float* __restrict__ b, int n)
{
    int i = blockIdx.x * blockDim.x + threadIdx.x;
    int total8 = n * 32;
    if (i < total8) {
        const float4* s = (const float4*)X + 2 * (size_t)i;
        float4 p = s[0], q = s[1];
        uint4 o;
        *(__half2*)&o.x = __floats2half2_rn(p.x, p.y);
        *(__half2*)&o.y = __floats2half2_rn(p.z, p.w);
        *(__half2*)&o.z = __floats2half2_rn(q.x, q.y);
        *(__half2*)&o.w = __floats2half2_rn(q.z, q.w);
        ((uint4*)Y)[i] = o;
    }
    if (i < TT * n) { cnt[i] = 0; cur[i] = 0; }
    if (i < 2 * TT * n) { a[i] = 0.f; b[i] = 0.f; }
}

// W[z][k][n] fp32 -> WT[z][n][k] fp16 (z = layer*3 + type)
__global__ void cvt_w(const float* __restrict__ Wa, const float* __restrict__ Wb,
                      __half* __restrict__ WT)
{
    __shared__ float tile[32][33];
    int z = blockIdx.z;
    const float* W = (z < TT ? Wa : Wb) + (size_t)(z % TT) * 65536;
    __half* O = WT + (size_t)z * 65536;
    int x  = blockIdx.x * 32 + threadIdx.x;
    int y0 = blockIdx.y * 32;
#pragma unroll
    for (int j = 0; j < 32; j += 8)
        tile[threadIdx.y + j][threadIdx.x] = W[(size_t)(y0 + threadIdx.y + j) * 256 + x];
    __syncthreads();
    int x2 = blockIdx.y * 32 + threadIdx.x;
    int y2 = blockIdx.x * 32;
#pragma unroll
    for (int j = 0; j < 32; j += 8)
        O[(size_t)(y2 + threadIdx.y + j) * 256 + x2] =
            __float2half_rn(tile[threadIdx.x][threadIdx.y + j]);
}

// ============ fused fp16 GEMM + attention dots (ldmatrix, BK=64) ============
// hcat[t][n][256](fp16) = X16[n][256] @ W[t]; A fp16 [m][k], B fp16 transposed [n][k].
// BM=128, BN=128, BK=64, 2-stage cp.async, mma.sync.m16n8k16 + ldmatrix.x4.
// 8 warps: 4 in M x 2 in N, warp tile 32x64. grid = (ceil(n/128), 6).
#define PITCH  36
#define ATILE  (128 * PITCH)
#define BTILE  (128 * PITCH)
#define GSMEM  (2 * (ATILE + BTILE) * 4)   // 73728 B -> 2 CTAs/SM (144KB < 228KB)

#define LDSM_X4(r0, r1, r2, r3, addr) \
    asm volatile("ldmatrix.sync.aligned.m8n8.x4.shared.b16 {%0,%1,%2,%3}, [%4];" \
                 : "=r"(r0), "=r"(r1), "=r"(r2), "=r"(r3) : "r"(addr))

__global__ __launch_bounds__(256) void gemm_fused(
    const __half* __restrict__ X, const __half* __restrict__ WT,
    __half* __restrict__ Hcat,
    const float* __restrict__ as_full, const float* __restrict__ ad_full,
    float* __restrict__ as_out, float* __restrict__ ad_out, int nrows)
{
    extern __shared__ uint32_t dsm[];

    int tid  = threadIdx.x;
    int lane = tid & 31, warp = tid >> 5;
    int wm = warp >> 1, wn = warp & 1;
    int g  = lane >> 2, tig = lane & 3;
    int bm = blockIdx.x * 128;
    int t  = blockIdx.y >> 1;
    int bn = (blockIdx.y & 1) * 128;
    const __half* Wt = WT + (size_t)t * 65536;
    __half* Hout = Hcat + (size_t)t * nrows * 256;

    uint32_t smem0 = (uint32_t)__cvta_generic_to_shared(dsm);

    // per-lane ldmatrix offsets (u32 units), hoisted
    uint32_t offA[2], offB[4];
#pragma unroll
    for (int mm = 0; mm < 2; mm++)
        offA[mm] = (uint32_t)((wm * 32 + mm * 16 + (lane & 15)) * PITCH
                              + ((lane >> 4) << 2));
#pragma unroll
    for (int p = 0; p < 4; p++)
        offB[p] = (uint32_t)((wn * 64 + p * 16 + ((lane & 7) | ((lane >> 1) & 8))) * PITCH
                             + (((lane >> 3) & 1) << 2));

    // stage BK=64 chunk: A/B each 128 rows x 8 chunks of 16B = 1024 cp.async, 4/thread
    auto stage = [&](int st, int k0) {
#pragma unroll
        for (int p = 0; p < 4; p++) {
            int i = tid + p * 256;
            int r = i >> 3, c = i & 7;
            uint32_t d = smem0 + (uint32_t)((st * ATILE + r * PITCH + c * 4) << 2);
            const __half* s = X + (size_t)(bm + r) * 256 + k0 + c * 8;
            int sz = (bm + r) < nrows ? 16 : 0;
            asm volatile("cp.async.ca.shared.global [%0], [%1], 16, %2;"
                         :: "r"(d), "l"(s), "r"(sz));
        }
#pragma unroll
        for (int p = 0; p < 4; p++) {
            int i = tid + p * 256;
            int r = i >> 3, c = i & 7;
            uint32_t d = smem0 + (uint32_t)((2 * ATILE + st * BTILE + r * PITCH + c * 4) << 2);
            const __half* s = Wt + (size_t)(bn + r) * 256 + k0 + c * 8;
            asm volatile("cp.async.ca.shared.global [%0], [%1], 16;"
                         :: "r"(d), "l"(s));
        }
        asm volatile("cp.async.commit_group;");
    };

    float acc[2][8][4];
#pragma unroll
    for (int a = 0; a < 2; a++)
#pragma unroll
        for (int b = 0; b < 8; b++)
#pragma unroll
            for (int c = 0; c < 4; c++) acc[a][b][c] = 0.f;

    stage(0, 0);
    for (int k0 = 0; k0 < 256; k0 += 64) {
        int cur = (k0 >> 6) & 1;
        if (k0 + 64 < 256) {
            stage(cur ^ 1, k0 + 64);
            asm volatile("cp.async.wait_group 1;");
        } else {
            asm volatile("cp.async.wait_group 0;");
        }
        __syncthreads();

        uint32_t abase = smem0 + (uint32_t)((cur * ATILE) << 2);
        uint32_t bbase = smem0 + (uint32_t)((2 * ATILE + cur * BTILE) << 2);
#pragma unroll
        for (int s = 0; s < 4; s++) {          // four K=16 steps per 64-chunk
            uint32_t kb = (uint32_t)(s * 8) << 2;   // byte offset within row
            uint32_t a[2][4], b[8][2];
#pragma unroll
            for (int mm = 0; mm < 2; mm++)
                LDSM_X4(a[mm][0], a[mm][1], a[mm][2], a[mm][3],
                        abase + (offA[mm] << 2) + kb);
#pragma unroll
            for (int p = 0; p < 4; p++)
                LDSM_X4(b[2 * p][0], b[2 * p][1], b[2 * p + 1][0], b[2 * p + 1][1],
                        bbase + (offB[p] << 2) + kb);
#pragma unroll
            for (int mm = 0; mm < 2; mm++)
#pragma unroll
                for (int nn = 0; nn < 8; nn++)
                    asm volatile(
                        "mma.sync.aligned.m16n8k16.row.col.f32.f16.f16.f32 "
                        "{%0,%1,%2,%3}, {%4,%5,%6,%7}, {%8,%9}, {%0,%1,%2,%3};"
                        : "+f"(acc[mm][nn][0]), "+f"(acc[mm][nn][1]),
                          "+f"(acc[mm][nn][2]), "+f"(acc[mm][nn][3])
                        : "r"(a[mm][0]), "r"(a[mm][1]), "r"(a[mm][2]), "r"(a[mm][3]),
                          "r"(b[nn][0]), "r"(b[nn][1]));
        }
        __syncthreads();
    }

    // ---- store H tile as fp16 ----
#pragma unroll
    for (int mm = 0; mm < 2; mm++)
#pragma unroll
        for (int nn = 0; nn < 8; nn++) {
            int row = bm + wm * 32 + mm * 16 + g;
            int col = bn + wn * 64 + nn * 8 + 2 * tig;
            if (row < nrows)
                *(__half2*)(Hout + (size_t)row * 256 + col) =
                    __floats2half2_rn(acc[mm][nn][0], acc[mm][nn][1]);
            if (row + 8 < nrows)
                *(__half2*)(Hout + (size_t)(row + 8) * 256 + col) =
                    __floats2half2_rn(acc[mm][nn][2], acc[mm][nn][3]);
        }

    // ---- fused attention dots: partial h.a_s / h.a_d over this CTA's 128 cols ----
    {
        const float* avs = as_full + t * 256;
        const float* avd = ad_full + t * 256;
        float ds[2][2] = {{0.f, 0.f}, {0.f, 0.f}};
        float dd[2][2] = {{0.f, 0.f}, {0.f, 0.f}};
#pragma unroll
        for (int mm = 0; mm < 2; mm++)
#pragma unroll
            for (int nn = 0; nn < 8; nn++) {
                int col = bn + wn * 64 + nn * 8 + 2 * tig;
                float a0 = __ldg(&avs[col]), a1 = __ldg(&avs[col + 1]);
                float d0 = __ldg(&avd[col]), d1 = __ldg(&avd[col + 1]);
                ds[mm][0] += acc[mm][nn][0] * a0 + acc[mm][nn][1] * a1;
                ds[mm][1] += acc[mm][nn][2] * a0 + acc[mm][nn][3] * a1;
                dd[mm][0] += acc[mm][nn][0] * d0 + acc[mm][nn][1] * d1;
                dd[mm][1] += acc[mm][nn][2] * d0 + acc[mm][nn][3] * d1;
            }
#pragma unroll
        for (int o = 1; o <= 2; o <<= 1)
#pragma unroll
            for (int mm = 0; mm < 2; mm++)
#pragma unroll
                for (int h = 0; h < 2; h++) {
                    ds[mm][h] += __shfl_xor_sync(0xffffffffu, ds[mm][h], o);
                    dd[mm][h] += __shfl_xor_sync(0xffffffffu, dd[mm][h], o);
                }
        if (tig == 0) {
            float* aso = as_out + (size_t)t * nrows;
            float* ado = ad_out + (size_t)t * nrows;
#pragma unroll
            for (int mm = 0; mm < 2; mm++)
#pragma unroll
                for (int h = 0; h < 2; h++) {
                    int row = bm + wm * 32 + mm * 16 + g + h * 8;
                    if (row < nrows) {
                        atomicAdd(&aso[row], ds[mm][h]);
                        atomicAdd(&ado[row], dd[mm][h]);
                    }
                }
        }
    }
}

// ============ CSR build (once; graph shared by both layers) ============
__global__ void hist_kernel(const int* __restrict__ ei, int* __restrict__ cnt,
                            int n, int ne)
{
    int i = blockIdx.x * blockDim.x + threadIdx.x;
    if (i >= TT * ne) return;
    int t = i / ne, e = i - t * ne;
    int d = ei[(size_t)t * 2 * ne + ne + e];
    atomicAdd(&cnt[t * n + d], 1);
}

__global__ __launch_bounds__(1024) void scan_off(
    const int* __restrict__ cnt, int* __restrict__ off, int n)
{
    int t = blockIdx.x;
    const int* c = cnt + t * n;
    int* o = off + t * (n + 1);
    __shared__ int wsum[32];
    __shared__ int carry_sh;
    int tid = threadIdx.x, lane = tid & 31, wid = tid >> 5;
    if (tid == 0) carry_sh = 0;
    __syncthreads();
    for (int base = 0; base < n; base += 1024) {
        int i = base + tid;
        int v = (i < n) ? c[i] : 0;
        int x = v;
#pragma unroll
        for (int o2 = 1; o2 < 32; o2 <<= 1) {
            int y = __shfl_up_sync(0xffffffffu, x, o2);
            if (lane >= o2) x += y;
        }
        if (lane == 31) wsum[wid] = x;
        __syncthreads();
        if (wid == 0) {
            int s = wsum[lane];
#pragma unroll
            for (int o2 = 1; o2 < 32; o2 <<= 1) {
                int y = __shfl_up_sync(0xffffffffu, s, o2);
                if (lane >= o2) s += y;
            }
            wsum[lane] = s;
        }
        __syncthreads();
        int incl  = x + (wid > 0 ? wsum[wid - 1] : 0);
        int carry = carry_sh;
        if (i < n) o[i] = carry + incl - v;
        __syncthreads();
        if (tid == 1023) carry_sh = carry + wsum[31];
        __syncthreads();
    }
    if (threadIdx.x == 0) o[n] = carry_sh;
}

__global__ void fill_kernel(const int* __restrict__ ei, const int* __restrict__ off,
                            int* __restrict__ cur, int* __restrict__ csr,
                            int n, int ne)
{
    int i = blockIdx.x * blockDim.x + threadIdx.x;
    if (i >= TT * ne) return;
    int t = i / ne, e = i - t * ne;
    const int* base = ei + (size_t)t * 2 * ne;
    int s = base[e], d = base[ne + e];
    int pos = off[t * (n + 1) + d] + atomicAdd(&cur[t * n + d], 1);
    csr[t * ne + pos] = s;
}

// ============ fused softmax + aggregate + bias + relu (+ head) : warp per dst ============
// 4-way software-pipelined gather (MLP=4 on the random hcat row loads).
__global__ __launch_bounds__(256) void agg_kernel(
    const int* __restrict__ off, const int* __restrict__ csr,
    const __half* __restrict__ hcat, const float* __restrict__ asb,
    const float* __restrict__ adb, const float* __restrict__ bias,
    __half* __restrict__ outrow, const float* __restrict__ Wh,
    const float* __restrict__ bh, float* __restrict__ headout,
    int mode, int n, int ne)
{
    int w    = (blockIdx.x * blockDim.x + threadIdx.x) >> 5;
    int lane = threadIdx.x & 31;
    if (w >= n) return;

    float4 a0 = make_float4(0.f, 0.f, 0.f, 0.f);   // cols 8*lane .. +3
    float4 a1 = make_float4(0.f, 0.f, 0.f, 0.f);   // cols 8*lane+4 .. +7

#pragma unroll
    for (int t = 0; t < TT; t++) {
        int o0 = off[t * (n + 1) + w];
        int deg = off[t * (n + 1) + w + 1] - o0;
        if (deg == 0) continue;
        float adt = adb[t * n + w];
        const __half* ht  = hcat + (size_t)t * n * 256;
        const float* ast  = asb + t * n;
        const int*   srcs = csr + (size_t)t * ne + o0;
        float4 t0 = make_float4(0.f, 0.f, 0.f, 0.f);
        float4 t1 = make_float4(0.f, 0.f, 0.f, 0.f);
        float den = 0.f;
        for (int base = 0; base < deg; base += 32) {
            int m = min(32, deg - base);
            int   sj = 0;
            float ex = 0.f;
            if (lane < m) {
                sj = srcs[base + lane];
                float e = ast[sj] + adt;
                e = e > 0.f ? e : 0.2f * e;      // leaky_relu 0.2
                ex = __expf(e);                   // shift-invariant: no max needed
            }
            float s = ex;
#pragma unroll
            for (int o = 16; o; o >>= 1) s += __shfl_xor_sync(0xffffffffu, s, o);
            den += s;

            int j = 0;
            for (; j + 4 <= m; j += 4) {     // MLP=4: 4 independent 512B gathers
                int   s0 = __shfl_sync(0xffffffffu, sj, j);
                int   s1 = __shfl_sync(0xffffffffu, sj, j + 1);
                int   s2 = __shfl_sync(0xffffffffu, sj, j + 2);
                int   s3 = __shfl_sync(0xffffffffu, sj, j + 3);
                float w0 = __shfl_sync(0xffffffffu, ex, j);
                float w1 = __shfl_sync(0xffffffffu, ex, j + 1);
                float w2 = __shfl_sync(0xffffffffu, ex, j + 2);
                float w3 = __shfl_sync(0xffffffffu, ex, j + 3);
                uint4 v0 = *(const uint4*)(ht + (size_t)s0 * 256 + lane * 8);
                uint4 v1 = *(const uint4*)(ht + (size_t)s1 * 256 + lane * 8);
                uint4 v2 = *(const uint4*)(ht + (size_t)s2 * 256 + lane * 8);
                uint4 v3 = *(const uint4*)(ht + (size_t)s3 * 256 + lane * 8);
                acc8(t0, t1, v0, w0);
                acc8(t0, t1, v1, w1);
                acc8(t0, t1, v2, w2);
                acc8(t0, t1, v3, w3);
            }
            for (; j < m; j++) {
                int   sn = __shfl_sync(0xffffffffu, sj, j);
                float wt = __shfl_sync(0xffffffffu, ex, j);
                uint4 v = *(const uint4*)(ht + (size_t)sn * 256 + lane * 8);
                acc8(t0, t1, v, wt);
            }
        }
        float inv = 1.f / den;
        a0 = f4fma(t0, inv, a0);
        a1 = f4fma(t1, inv, a1);
    }

    // bias sum over the 3 types ([3][64] float4 view), cols 8*lane -> float4 idx 2*lane
    const float4* bb = (const float4*)bias;
    float4 b0 = f4add(f4add(__ldg(&bb[2 * lane]), __ldg(&bb[64 + 2 * lane])),
                      __ldg(&bb[128 + 2 * lane]));
    float4 b1 = f4add(f4add(__ldg(&bb[2 * lane + 1]), __ldg(&bb[64 + 2 * lane + 1])),
                      __ldg(&bb[128 + 2 * lane + 1]));
    float4 r0 = f4relu(f4add(a0, b0));
    float4 r1 = f4relu(f4add(a1, b1));

    if (mode == 0) {
        uint4 o;
        *(__half2*)&o.x = __floats2half2_rn(r0.x, r0.y);
        *(__half2*)&o.y = __floats2half2_rn(r0.z, r0.w);
        *(__half2*)&o.z = __floats2half2_rn(r1.x, r1.y);
        *(__half2*)&o.w = __floats2half2_rn(r1.z, r1.w);
        *(uint4*)(outrow + (size_t)w * 256 + lane * 8) = o;
    } else {
        const float4* wh = (const float4*)Wh;
        float4 q0 = __ldg(&wh[2 * lane]);
        float4 q1 = __ldg(&wh[2 * lane + 1]);
        float s = r0.x * q0.x + r0.y * q0.y + r0.z * q0.z + r0.w * q0.w +
                  r1.x * q1.x + r1.y * q1.y + r1.z * q1.z + r1.w * q1.w;
#pragma unroll
        for (int o = 16; o; o >>= 1) s += __shfl_xor_sync(0xffffffffu, s, o);
        if (lane == 0) headout[w] = 1.f / (1.f + __expf(-(s + bh[0])));
    }
}

// ---------------- host orchestration ----------------
extern "C" void kernel_launch(void* const* d_in, const int* in_sizes, int n_in,
                              void* d_out, int out_size)
{
    const float* z   = (const float*)d_in[0];
    const int*   ei  = (const int*)d_in[1];
    const float* W1  = (const float*)d_in[2];
    const float* as1 = (const float*)d_in[3];
    const float* ad1 = (const float*)d_in[4];
    const float* b1  = (const float*)d_in[5];
    const float* W2  = (const float*)d_in[6];
    const float* as2 = (const float*)d_in[7];
    const float* ad2 = (const float*)d_in[8];
    const float* b2  = (const float*)d_in[9];
    const float* Wh  = (const float*)d_in[10];
    const float* bh  = (const float*)d_in[11];
    float* out = (float*)d_out;

    int n  = in_sizes[0] / 256;   // 50000
    int ne = in_sizes[1] / 6;     // 250000

    void* p;
    cudaGetSymbolAddress(&p, g_hcat); __half* hcat = (__half*)p;
    cudaGetSymbolAddress(&p, g_h1);   __half* h1   = (__half*)p;
    cudaGetSymbolAddress(&p, g_z16);  __half* z16  = (__half*)p;
    cudaGetSymbolAddress(&p, g_wt16); __half* wt16 = (__half*)p;
    cudaGetSymbolAddress(&p, g_as);   float*  asb  = (float*)p;
    cudaGetSymbolAddress(&p, g_ad);   float*  adb  = (float*)p;
    cudaGetSymbolAddress(&p, g_cnt);  int*    cnt  = (int*)p;
    cudaGetSymbolAddress(&p, g_cur);  int*    cur  = (int*)p;
    cudaGetSymbolAddress(&p, g_off);  int*    off  = (int*)p;
    cudaGetSymbolAddress(&p, g_csr);  int*    csr  = (int*)p;

    cudaFuncSetAttribute(gemm_fused, cudaFuncAttributeMaxDynamicSharedMemorySize, GSMEM);

    dim3 ggrid((n + 127) / 128, 6);
    float* asb2 = asb + (size_t)TT * n;
    float* adb2 = adb + (size_t)TT * n;

    // launch order keeps gemm_fused as the 4th launch (ncu lands there)
    prep<<<(n * 32 + 255) / 256, 256>>>(z, z16, cnt, cur, asb, adb, n);
    cvt_w<<<dim3(8, 8, 2 * TT), dim3(32, 8)>>>(W1, W2, wt16);
    hist_kernel<<<(TT * ne + 255) / 256, 256>>>(ei, cnt, n, ne);

    // ---- layer 1 GEMM + dots (4th launch) ----
    gemm_fused<<<ggrid, 256, GSMEM>>>(z16, wt16, hcat, as1, ad1, asb, adb, n);

    scan_off<<<TT, 1024>>>(cnt, off, n);
    fill_kernel<<<(TT * ne + 255) / 256, 256>>>(ei, off, cur, csr, n, ne);

    agg_kernel<<<(n + 7) / 8, 256>>>(off, csr, hcat, asb, adb, b1,
                                     h1, Wh, bh, out, 0, n, ne);

    // ---- layer 2 ----
    gemm_fused<<<ggrid, 256, GSMEM>>>(h1, wt16 + (size_t)TT * 65536, hcat,
                                      as2, ad2, asb2, adb2, n);
    agg_kernel<<<(n + 7) / 8, 256>>>(off, csr, hcat, asb2, adb2, b2,
                                     h1 /*unused in mode 1*/, Wh, bh, out, 1, n, ne);
}

// round 15
// speedup vs baseline: 1.7077x; 1.0835x over previous
#include <cuda_runtime.h>
#include <cuda_fp16.h>
#include <cstdint>

#define NMAX 50048
#define EMAX 250112
#define TT 3

// ---------------- scratch (static device globals; no allocation) ----------------
__device__ __half g_hcat[TT * NMAX * 256]; // per-type h = x @ W[t], fp16 (gather-only)
__device__ __half g_h1[NMAX * 256];        // layer-1 output (fp16: layer-2 GEMM input)
__device__ __half g_z16[NMAX * 256];       // z converted to fp16
__device__ __half g_wt16[2 * TT * 65536];  // W transposed+converted: [layer][t][n][k]
__device__ float  g_as[2 * TT * NMAX];     // a_src per layer/type (atomic-accumulated)
__device__ float  g_ad[2 * TT * NMAX];     // a_dst per layer/type
__device__ int    g_cnt[TT * NMAX];
__device__ int    g_cur[TT * NMAX];
__device__ int    g_off[TT * (NMAX + 1)];
__device__ int    g_csr[TT * EMAX];

// ---------------- small float4 helpers ----------------
__device__ __forceinline__ float4 f4add(float4 a, float4 b) {
    return make_float4(a.x + b.x, a.y + b.y, a.z + b.z, a.w + b.w);
}
__device__ __forceinline__ float4 f4fma(float4 a, float s, float4 c) {
    return make_float4(fmaf(a.x, s, c.x), fmaf(a.y, s, c.y),
                       fmaf(a.z, s, c.z), fmaf(a.w, s, c.w));
}
__device__ __forceinline__ float4 f4relu(float4 a) {
    return make_float4(fmaxf(a.x, 0.f), fmaxf(a.y, 0.f),
                       fmaxf(a.z, 0.f), fmaxf(a.w, 0.f));
}
__device__ __forceinline__ void acc8(float4& t0, float4& t1, uint4 v, float wt) {
    float2 f0 = __half22float2(*(__half2*)&v.x);
    float2 f1 = __half22float2(*(__half2*)&v.y);
    float2 f2 = __half22float2(*(__half2*)&v.z);
    float2 f3 = __half22float2(*(__half2*)&v.w);
    t0.x = fmaf(f0.x, wt, t0.x); t0.y = fmaf(f0.y, wt, t0.y);
    t0.z = fmaf(f1.x, wt, t0.z); t0.w = fmaf(f1.y, wt, t0.w);
    t1.x = fmaf(f2.x, wt, t1.x); t1.y = fmaf(f2.y, wt, t1.y);
    t1.z = fmaf(f3.x, wt, t1.z); t1.w = fmaf(f3.y, wt, t1.w);
}

// ============ prep: z fp32->fp16 + zero counts/cursors/dot-accums ============
__global__ void prep(const float* __restrict__ X, __half* __restrict__ Y,
                     int* __restrict__ cnt, int* __restrict__ cur,
                     float* __restrict__ a, float* __restrict__ b, int n)
{
    int i = blockIdx.x * blockDim.x + threadIdx.x;
    int total8 = n * 32;
    if (i < total8) {
        const float4* s = (const float4*)X + 2 * (size_t)i;
        float4 p = s[0], q = s[1];
        uint4 o;
        *(__half2*)&o.x = __floats2half2_rn(p.x, p.y);
        *(__half2*)&o.y = __floats2half2_rn(p.z, p.w);
        *(__half2*)&o.z = __floats2half2_rn(q.x, q.y);
        *(__half2*)&o.w = __floats2half2_rn(q.z, q.w);
        ((uint4*)Y)[i] = o;
    }
    if (i < TT * n) { cnt[i] = 0; cur[i] = 0; }
    if (i < 2 * TT * n) { a[i] = 0.f; b[i] = 0.f; }
}

// W[z][k][n] fp32 -> WT[z][n][k] fp16 (z = layer*3 + type)
__global__ void cvt_w(const float* __restrict__ Wa, const float* __restrict__ Wb,
                      __half* __restrict__ WT)
{
    __shared__ float tile[32][33];
    int z = blockIdx.z;
    const float* W = (z < TT ? Wa : Wb) + (size_t)(z % TT) * 65536;
    __half* O = WT + (size_t)z * 65536;
    int x  = blockIdx.x * 32 + threadIdx.x;
    int y0 = blockIdx.y * 32;
#pragma unroll
    for (int j = 0; j < 32; j += 8)
        tile[threadIdx.y + j][threadIdx.x] = W[(size_t)(y0 + threadIdx.y + j) * 256 + x];
    __syncthreads();
    int x2 = blockIdx.y * 32 + threadIdx.x;
    int y2 = blockIdx.x * 32;
#pragma unroll
    for (int j = 0; j < 32; j += 8)
        O[(size_t)(y2 + threadIdx.y + j) * 256 + x2] =
            __float2half_rn(tile[threadIdx.x][threadIdx.y + j]);
}

// ============ fused fp16 GEMM + attention dots (ldmatrix, BK=64) ============
#define PITCH  36
#define ATILE  (128 * PITCH)
#define BTILE  (128 * PITCH)
#define GSMEM  (2 * (ATILE + BTILE) * 4)   // 73728 B

#define LDSM_X4(r0, r1, r2, r3, addr) \
    asm volatile("ldmatrix.sync.aligned.m8n8.x4.shared.b16 {%0,%1,%2,%3}, [%4];" \
                 : "=r"(r0), "=r"(r1), "=r"(r2), "=r"(r3) : "r"(addr))

__global__ __launch_bounds__(256) void gemm_fused(
    const __half* __restrict__ X, const __half* __restrict__ WT,
    __half* __restrict__ Hcat,
    const float* __restrict__ as_full, const float* __restrict__ ad_full,
    float* __restrict__ as_out, float* __restrict__ ad_out, int nrows)
{
    extern __shared__ uint32_t dsm[];

    int tid  = threadIdx.x;
    int lane = tid & 31, warp = tid >> 5;
    int wm = warp >> 1, wn = warp & 1;
    int g  = lane >> 2, tig = lane & 3;
    int bm = blockIdx.x * 128;
    int t  = blockIdx.y >> 1;
    int bn = (blockIdx.y & 1) * 128;
    const __half* Wt = WT + (size_t)t * 65536;
    __half* Hout = Hcat + (size_t)t * nrows * 256;

    uint32_t smem0 = (uint32_t)__cvta_generic_to_shared(dsm);

    uint32_t offA[2], offB[4];
#pragma unroll
    for (int mm = 0; mm < 2; mm++)
        offA[mm] = (uint32_t)((wm * 32 + mm * 16 + (lane & 15)) * PITCH
                              + ((lane >> 4) << 2));
#pragma unroll
    for (int p = 0; p < 4; p++)
        offB[p] = (uint32_t)((wn * 64 + p * 16 + ((lane & 7) | ((lane >> 1) & 8))) * PITCH
                             + (((lane >> 3) & 1) << 2));

    auto stage = [&](int st, int k0) {
#pragma unroll
        for (int p = 0; p < 4; p++) {
            int i = tid + p * 256;
            int r = i >> 3, c = i & 7;
            uint32_t d = smem0 + (uint32_t)((st * ATILE + r * PITCH + c * 4) << 2);
            const __half* s = X + (size_t)(bm + r) * 256 + k0 + c * 8;
            int sz = (bm + r) < nrows ? 16 : 0;
            asm volatile("cp.async.ca.shared.global [%0], [%1], 16, %2;"
                         :: "r"(d), "l"(s), "r"(sz));
        }
#pragma unroll
        for (int p = 0; p < 4; p++) {
            int i = tid + p * 256;
            int r = i >> 3, c = i & 7;
            uint32_t d = smem0 + (uint32_t)((2 * ATILE + st * BTILE + r * PITCH + c * 4) << 2);
            const __half* s = Wt + (size_t)(bn + r) * 256 + k0 + c * 8;
            asm volatile("cp.async.ca.shared.global [%0], [%1], 16;"
                         :: "r"(d), "l"(s));
        }
        asm volatile("cp.async.commit_group;");
    };

    float acc[2][8][4];
#pragma unroll
    for (int a = 0; a < 2; a++)
#pragma unroll
        for (int b = 0; b < 8; b++)
#pragma unroll
            for (int c = 0; c < 4; c++) acc[a][b][c] = 0.f;

    stage(0, 0);
    for (int k0 = 0; k0 < 256; k0 += 64) {
        int cur = (k0 >> 6) & 1;
        if (k0 + 64 < 256) {
            stage(cur ^ 1, k0 + 64);
            asm volatile("cp.async.wait_group 1;");
        } else {
            asm volatile("cp.async.wait_group 0;");
        }
        __syncthreads();

        uint32_t abase = smem0 + (uint32_t)((cur * ATILE) << 2);
        uint32_t bbase = smem0 + (uint32_t)((2 * ATILE + cur * BTILE) << 2);
#pragma unroll
        for (int s = 0; s < 4; s++) {
            uint32_t kb = (uint32_t)(s * 8) << 2;
            uint32_t a[2][4], b[8][2];
#pragma unroll
            for (int mm = 0; mm < 2; mm++)
                LDSM_X4(a[mm][0], a[mm][1], a[mm][2], a[mm][3],
                        abase + (offA[mm] << 2) + kb);
#pragma unroll
            for (int p = 0; p < 4; p++)
                LDSM_X4(b[2 * p][0], b[2 * p][1], b[2 * p + 1][0], b[2 * p + 1][1],
                        bbase + (offB[p] << 2) + kb);
#pragma unroll
            for (int mm = 0; mm < 2; mm++)
#pragma unroll
                for (int nn = 0; nn < 8; nn++)
                    asm volatile(
                        "mma.sync.aligned.m16n8k16.row.col.f32.f16.f16.f32 "
                        "{%0,%1,%2,%3}, {%4,%5,%6,%7}, {%8,%9}, {%0,%1,%2,%3};"
                        : "+f"(acc[mm][nn][0]), "+f"(acc[mm][nn][1]),
                          "+f"(acc[mm][nn][2]), "+f"(acc[mm][nn][3])
                        : "r"(a[mm][0]), "r"(a[mm][1]), "r"(a[mm][2]), "r"(a[mm][3]),
                          "r"(b[nn][0]), "r"(b[nn][1]));
        }
        __syncthreads();
    }

#pragma unroll
    for (int mm = 0; mm < 2; mm++)
#pragma unroll
        for (int nn = 0; nn < 8; nn++) {
            int row = bm + wm * 32 + mm * 16 + g;
            int col = bn + wn * 64 + nn * 8 + 2 * tig;
            if (row < nrows)
                *(__half2*)(Hout + (size_t)row * 256 + col) =
                    __floats2half2_rn(acc[mm][nn][0], acc[mm][nn][1]);
            if (row + 8 < nrows)
                *(__half2*)(Hout + (size_t)(row + 8) * 256 + col) =
                    __floats2half2_rn(acc[mm][nn][2], acc[mm][nn][3]);
        }

    // ---- fused attention dots ----
    {
        const float* avs = as_full + t * 256;
        const float* avd = ad_full + t * 256;
        float ds[2][2] = {{0.f, 0.f}, {0.f, 0.f}};
        float dd[2][2] = {{0.f, 0.f}, {0.f, 0.f}};
#pragma unroll
        for (int mm = 0; mm < 2; mm++)
#pragma unroll
            for (int nn = 0; nn < 8; nn++) {
                int col = bn + wn * 64 + nn * 8 + 2 * tig;
                float a0 = __ldg(&avs[col]), a1 = __ldg(&avs[col + 1]);
                float d0 = __ldg(&avd[col]), d1 = __ldg(&avd[col + 1]);
                ds[mm][0] += acc[mm][nn][0] * a0 + acc[mm][nn][1] * a1;
                ds[mm][1] += acc[mm][nn][2] * a0 + acc[mm][nn][3] * a1;
                dd[mm][0] += acc[mm][nn][0] * d0 + acc[mm][nn][1] * d1;
                dd[mm][1] += acc[mm][nn][2] * d0 + acc[mm][nn][3] * d1;
            }
#pragma unroll
        for (int o = 1; o <= 2; o <<= 1)
#pragma unroll
            for (int mm = 0; mm < 2; mm++)
#pragma unroll
                for (int h = 0; h < 2; h++) {
                    ds[mm][h] += __shfl_xor_sync(0xffffffffu, ds[mm][h], o);
                    dd[mm][h] += __shfl_xor_sync(0xffffffffu, dd[mm][h], o);
                }
        if (tig == 0) {
            float* aso = as_out + (size_t)t * nrows;
            float* ado = ad_out + (size_t)t * nrows;
#pragma unroll
            for (int mm = 0; mm < 2; mm++)
#pragma unroll
                for (int h = 0; h < 2; h++) {
                    int row = bm + wm * 32 + mm * 16 + g + h * 8;
                    if (row < nrows) {
                        atomicAdd(&aso[row], ds[mm][h]);
                        atomicAdd(&ado[row], dd[mm][h]);
                    }
                }
        }
    }
}

// ============ CSR build (once; graph shared by both layers) ============
__global__ void hist_kernel(const int* __restrict__ ei, int* __restrict__ cnt,
                            int n, int ne)
{
    int i = blockIdx.x * blockDim.x + threadIdx.x;
    if (i >= TT * ne) return;
    int t = i / ne, e = i - t * ne;
    int d = ei[(size_t)t * 2 * ne + ne + e];
    atomicAdd(&cnt[t * n + d], 1);
}

__global__ __launch_bounds__(1024) void scan_off(
    const int* __restrict__ cnt, int* __restrict__ off, int n)
{
    int t = blockIdx.x;
    const int* c = cnt + t * n;
    int* o = off + t * (n + 1);
    __shared__ int wsum[32];
    __shared__ int carry_sh;
    int tid = threadIdx.x, lane = tid & 31, wid = tid >> 5;
    if (tid == 0) carry_sh = 0;
    __syncthreads();
    for (int base = 0; base < n; base += 1024) {
        int i = base + tid;
        int v = (i < n) ? c[i] : 0;
        int x = v;
#pragma unroll
        for (int o2 = 1; o2 < 32; o2 <<= 1) {
            int y = __shfl_up_sync(0xffffffffu, x, o2);
            if (lane >= o2) x += y;
        }
        if (lane == 31) wsum[wid] = x;
        __syncthreads();
        if (wid == 0) {
            int s = wsum[lane];
#pragma unroll
            for (int o2 = 1; o2 < 32; o2 <<= 1) {
                int y = __shfl_up_sync(0xffffffffu, s, o2);
                if (lane >= o2) s += y;
            }
            wsum[lane] = s;
        }
        __syncthreads();
        int incl  = x + (wid > 0 ? wsum[wid - 1] : 0);
        int carry = carry_sh;
        if (i < n) o[i] = carry + incl - v;
        __syncthreads();
        if (tid == 1023) carry_sh = carry + wsum[31];
        __syncthreads();
    }
    if (threadIdx.x == 0) o[n] = carry_sh;
}

__global__ void fill_kernel(const int* __restrict__ ei, const int* __restrict__ off,
                            int* __restrict__ cur, int* __restrict__ csr,
                            int n, int ne)
{
    int i = blockIdx.x * blockDim.x + threadIdx.x;
    if (i >= TT * ne) return;
    int t = i / ne, e = i - t * ne;
    const int* base = ei + (size_t)t * 2 * ne;
    int s = base[e], d = base[ne + e];
    int pos = off[t * (n + 1) + d] + atomicAdd(&cur[t * n + d], 1);
    csr[t * ne + pos] = s;
}

// ============ fused softmax + aggregate + bias + relu (+ head) : warp per dst ============
// Fast path (deg<=32 per type, the common case): stage pre-scaled weights + global row
// ids in a per-warp smem queue, then one flat 8-deep pipelined gather over all types.
__global__ __launch_bounds__(256) void agg_kernel(
    const int* __restrict__ off, const int* __restrict__ csr,
    const __half* __restrict__ hcat, const float* __restrict__ asb,
    const float* __restrict__ adb, const float* __restrict__ bias,
    __half* __restrict__ outrow, const float* __restrict__ Wh,
    const float* __restrict__ bh, float* __restrict__ headout,
    int mode, int n, int ne)
{
    __shared__ int   s_sn[8][96];
    __shared__ float s_w[8][96];

    int wrp  = threadIdx.x >> 5;
    int w    = (blockIdx.x * blockDim.x + threadIdx.x) >> 5;
    int lane = threadIdx.x & 31;
    if (w >= n) return;

    float4 a0 = make_float4(0.f, 0.f, 0.f, 0.f);   // cols 8*lane .. +3
    float4 a1 = make_float4(0.f, 0.f, 0.f, 0.f);   // cols 8*lane+4 .. +7

    int o0[TT], dg[TT];
#pragma unroll
    for (int t = 0; t < TT; t++) {
        o0[t] = off[t * (n + 1) + w];
        dg[t] = off[t * (n + 1) + w + 1] - o0[t];
    }

    if (dg[0] <= 32 && dg[1] <= 32 && dg[2] <= 32) {
        // ---------- fast path ----------
        int cnt = 0;
#pragma unroll
        for (int t = 0; t < TT; t++) {
            if (dg[t] == 0) continue;
            float adt = adb[t * n + w];
            int   sj = 0;
            float ex = 0.f;
            if (lane < dg[t]) {
                sj = csr[(size_t)t * ne + o0[t] + lane];
                float e = asb[t * n + sj] + adt;
                e = e > 0.f ? e : 0.2f * e;       // leaky_relu 0.2
                ex = __expf(e);                    // shift-invariant
            }
            float s = ex;
#pragma unroll
            for (int o = 16; o; o >>= 1) s += __shfl_xor_sync(0xffffffffu, s, o);
            float inv = 1.f / s;
            if (lane < dg[t]) {
                s_sn[wrp][cnt + lane] = t * n + sj;   // global hcat row
                s_w[wrp][cnt + lane]  = ex * inv;     // pre-normalized alpha
            }
            cnt += dg[t];
        }
        __syncwarp();

        int i = 0;
        for (; i + 8 <= cnt; i += 8) {
            int   n0 = s_sn[wrp][i],     n1 = s_sn[wrp][i + 1];
            int   n2 = s_sn[wrp][i + 2], n3 = s_sn[wrp][i + 3];
            int   n4 = s_sn[wrp][i + 4], n5 = s_sn[wrp][i + 5];
            int   n6 = s_sn[wrp][i + 6], n7 = s_sn[wrp][i + 7];
            float q0 = s_w[wrp][i],     q1 = s_w[wrp][i + 1];
            float q2 = s_w[wrp][i + 2], q3 = s_w[wrp][i + 3];
            float q4 = s_w[wrp][i + 4], q5 = s_w[wrp][i + 5];
            float q6 = s_w[wrp][i + 6], q7 = s_w[wrp][i + 7];
            uint4 v0 = *(const uint4*)(hcat + (size_t)n0 * 256 + lane * 8);
            uint4 v1 = *(const uint4*)(hcat + (size_t)n1 * 256 + lane * 8);
            uint4 v2 = *(const uint4*)(hcat + (size_t)n2 * 256 + lane * 8);
            uint4 v3 = *(const uint4*)(hcat + (size_t)n3 * 256 + lane * 8);
            uint4 v4 = *(const uint4*)(hcat + (size_t)n4 * 256 + lane * 8);
            uint4 v5 = *(const uint4*)(hcat + (size_t)n5 * 256 + lane * 8);
            uint4 v6 = *(const uint4*)(hcat + (size_t)n6 * 256 + lane * 8);
            uint4 v7 = *(const uint4*)(hcat + (size_t)n7 * 256 + lane * 8);
            acc8(a0, a1, v0, q0); acc8(a0, a1, v1, q1);
            acc8(a0, a1, v2, q2); acc8(a0, a1, v3, q3);
            acc8(a0, a1, v4, q4); acc8(a0, a1, v5, q5);
            acc8(a0, a1, v6, q6); acc8(a0, a1, v7, q7);
        }
        for (; i + 4 <= cnt; i += 4) {
            int   n0 = s_sn[wrp][i],     n1 = s_sn[wrp][i + 1];
            int   n2 = s_sn[wrp][i + 2], n3 = s_sn[wrp][i + 3];
            float q0 = s_w[wrp][i],     q1 = s_w[wrp][i + 1];
            float q2 = s_w[wrp][i + 2], q3 = s_w[wrp][i + 3];
            uint4 v0 = *(const uint4*)(hcat + (size_t)n0 * 256 + lane * 8);
            uint4 v1 = *(const uint4*)(hcat + (size_t)n1 * 256 + lane * 8);
            uint4 v2 = *(const uint4*)(hcat + (size_t)n2 * 256 + lane * 8);
            uint4 v3 = *(const uint4*)(hcat + (size_t)n3 * 256 + lane * 8);
            acc8(a0, a1, v0, q0); acc8(a0, a1, v1, q1);
            acc8(a0, a1, v2, q2); acc8(a0, a1, v3, q3);
        }
        for (; i < cnt; i++) {
            int   n0 = s_sn[wrp][i];
            float q0 = s_w[wrp][i];
            uint4 v0 = *(const uint4*)(hcat + (size_t)n0 * 256 + lane * 8);
            acc8(a0, a1, v0, q0);
        }
    } else {
        // ---------- slow path (any deg > 32; rare) ----------
#pragma unroll
        for (int t = 0; t < TT; t++) {
            int deg = dg[t];
            if (deg == 0) continue;
            float adt = adb[t * n + w];
            const __half* ht  = hcat + (size_t)t * n * 256;
            const float* ast  = asb + t * n;
            const int*   srcs = csr + (size_t)t * ne + o0[t];
            float4 t0 = make_float4(0.f, 0.f, 0.f, 0.f);
            float4 t1 = make_float4(0.f, 0.f, 0.f, 0.f);
            float den = 0.f;
            for (int base = 0; base < deg; base += 32) {
                int m = min(32, deg - base);
                int   sj = 0;
                float ex = 0.f;
                if (lane < m) {
                    sj = srcs[base + lane];
                    float e = ast[sj] + adt;
                    e = e > 0.f ? e : 0.2f * e;
                    ex = __expf(e);
                }
                float s = ex;
#pragma unroll
                for (int o = 16; o; o >>= 1) s += __shfl_xor_sync(0xffffffffu, s, o);
                den += s;
                for (int j = 0; j < m; j++) {
                    int   sn = __shfl_sync(0xffffffffu, sj, j);
                    float wt = __shfl_sync(0xffffffffu, ex, j);
                    uint4 v = *(const uint4*)(ht + (size_t)sn * 256 + lane * 8);
                    acc8(t0, t1, v, wt);
                }
            }
            float inv = 1.f / den;
            a0 = f4fma(t0, inv, a0);
            a1 = f4fma(t1, inv, a1);
        }
    }

    // bias sum over the 3 types ([3][64] float4 view), cols 8*lane -> float4 idx 2*lane
    const float4* bb = (const float4*)bias;
    float4 b0 = f4add(f4add(__ldg(&bb[2 * lane]), __ldg(&bb[64 + 2 * lane])),
                      __ldg(&bb[128 + 2 * lane]));
    float4 b1 = f4add(f4add(__ldg(&bb[2 * lane + 1]), __ldg(&bb[64 + 2 * lane + 1])),
                      __ldg(&bb[128 + 2 * lane + 1]));
    float4 r0 = f4relu(f4add(a0, b0));
    float4 r1 = f4relu(f4add(a1, b1));

    if (mode == 0) {
        uint4 o;
        *(__half2*)&o.x = __floats2half2_rn(r0.x, r0.y);
        *(__half2*)&o.y = __floats2half2_rn(r0.z, r0.w);
        *(__half2*)&o.z = __floats2half2_rn(r1.x, r1.y);
        *(__half2*)&o.w = __floats2half2_rn(r1.z, r1.w);
        *(uint4*)(outrow + (size_t)w * 256 + lane * 8) = o;
    } else {
        const float4* wh = (const float4*)Wh;
        float4 q0 = __ldg(&wh[2 * lane]);
        float4 q1 = __ldg(&wh[2 * lane + 1]);
        float s = r0.x * q0.x + r0.y * q0.y + r0.z * q0.z + r0.w * q0.w +
                  r1.x * q1.x + r1.y * q1.y + r1.z * q1.z + r1.w * q1.w;
#pragma unroll
        for (int o = 16; o; o >>= 1) s += __shfl_xor_sync(0xffffffffu, s, o);
        if (lane == 0) headout[w] = 1.f / (1.f + __expf(-(s + bh[0])));
    }
}

// ---------------- host orchestration ----------------
extern "C" void kernel_launch(void* const* d_in, const int* in_sizes, int n_in,
                              void* d_out, int out_size)
{
    const float* z   = (const float*)d_in[0];
    const int*   ei  = (const int*)d_in[1];
    const float* W1  = (const float*)d_in[2];
    const float* as1 = (const float*)d_in[3];
    const float* ad1 = (const float*)d_in[4];
    const float* b1  = (const float*)d_in[5];
    const float* W2  = (const float*)d_in[6];
    const float* as2 = (const float*)d_in[7];
    const float* ad2 = (const float*)d_in[8];
    const float* b2  = (const float*)d_in[9];
    const float* Wh  = (const float*)d_in[10];
    const float* bh  = (const float*)d_in[11];
    float* out = (float*)d_out;

    int n  = in_sizes[0] / 256;   // 50000
    int ne = in_sizes[1] / 6;     // 250000

    void* p;
    cudaGetSymbolAddress(&p, g_hcat); __half* hcat = (__half*)p;
    cudaGetSymbolAddress(&p, g_h1);   __half* h1   = (__half*)p;
    cudaGetSymbolAddress(&p, g_z16);  __half* z16  = (__half*)p;
    cudaGetSymbolAddress(&p, g_wt16); __half* wt16 = (__half*)p;
    cudaGetSymbolAddress(&p, g_as);   float*  asb  = (float*)p;
    cudaGetSymbolAddress(&p, g_ad);   float*  adb  = (float*)p;
    cudaGetSymbolAddress(&p, g_cnt);  int*    cnt  = (int*)p;
    cudaGetSymbolAddress(&p, g_cur);  int*    cur  = (int*)p;
    cudaGetSymbolAddress(&p, g_off);  int*    off  = (int*)p;
    cudaGetSymbolAddress(&p, g_csr);  int*    csr  = (int*)p;

    cudaFuncSetAttribute(gemm_fused, cudaFuncAttributeMaxDynamicSharedMemorySize, GSMEM);

    dim3 ggrid((n + 127) / 128, 6);
    float* asb2 = asb + (size_t)TT * n;
    float* adb2 = adb + (size_t)TT * n;

    // launch order keeps gemm_fused as the 4th launch (ncu lands there)
    prep<<<(n * 32 + 255) / 256, 256>>>(z, z16, cnt, cur, asb, adb, n);
    cvt_w<<<dim3(8, 8, 2 * TT), dim3(32, 8)>>>(W1, W2, wt16);
    hist_kernel<<<(TT * ne + 255) / 256, 256>>>(ei, cnt, n, ne);

    // ---- layer 1 GEMM + dots (4th launch) ----
    gemm_fused<<<ggrid, 256, GSMEM>>>(z16, wt16, hcat, as1, ad1, asb, adb, n);

    scan_off<<<TT, 1024>>>(cnt, off, n);
    fill_kernel<<<(TT * ne + 255) / 256, 256>>>(ei, off, cur, csr, n, ne);

    agg_kernel<<<(n + 7) / 8, 256>>>(off, csr, hcat, asb, adb, b1,
                                     h1, Wh, bh, out, 0, n, ne);

    // ---- layer 2 ----
    gemm_fused<<<ggrid, 256, GSMEM>>>(h1, wt16 + (size_t)TT * 65536, hcat,
                                      as2, ad2, asb2, adb2, n);
    agg_kernel<<<(n + 7) / 8, 256>>>(off, csr, hcat, asb2, adb2, b2,
                                     h1 /*unused in mode 1*/, Wh, bh, out, 1, n, ne);
}

// round 16
// speedup vs baseline: 1.7527x; 1.0264x over previous
#include <cuda_runtime.h>
#include <cuda_fp16.h>
#include <cstdint>

#define NMAX 50048
#define EMAX 250112
#define TT 3

// ---------------- scratch (static device globals; no allocation) ----------------
__device__ __half g_hcat[TT * NMAX * 256]; // per-type h = x @ W[t], fp16 (gather-only)
__device__ __half g_h1[NMAX * 256];        // layer-1 output (fp16: layer-2 GEMM input)
__device__ __half g_z16[NMAX * 256];       // z converted to fp16
__device__ __half g_wt16[2 * TT * 65536];  // W transposed+converted: [layer][t][n][k]
__device__ float  g_as[2 * TT * NMAX];     // a_src per layer/type (atomic-accumulated)
__device__ float  g_ad[2 * TT * NMAX];     // a_dst per layer/type
__device__ int    g_cnt[TT * NMAX];
__device__ int    g_cur[TT * NMAX];
__device__ int    g_off[TT * (NMAX + 1)];
__device__ int    g_csr[TT * EMAX];

// ---------------- small float4 helpers ----------------
__device__ __forceinline__ float4 f4add(float4 a, float4 b) {
    return make_float4(a.x + b.x, a.y + b.y, a.z + b.z, a.w + b.w);
}
__device__ __forceinline__ float4 f4fma(float4 a, float s, float4 c) {
    return make_float4(fmaf(a.x, s, c.x), fmaf(a.y, s, c.y),
                       fmaf(a.z, s, c.z), fmaf(a.w, s, c.w));
}
__device__ __forceinline__ float4 f4relu(float4 a) {
    return make_float4(fmaxf(a.x, 0.f), fmaxf(a.y, 0.f),
                       fmaxf(a.z, 0.f), fmaxf(a.w, 0.f));
}
__device__ __forceinline__ void acc8(float4& t0, float4& t1, uint4 v, float wt) {
    float2 f0 = __half22float2(*(__half2*)&v.x);
    float2 f1 = __half22float2(*(__half2*)&v.y);
    float2 f2 = __half22float2(*(__half2*)&v.z);
    float2 f3 = __half22float2(*(__half2*)&v.w);
    t0.x = fmaf(f0.x, wt, t0.x); t0.y = fmaf(f0.y, wt, t0.y);
    t0.z = fmaf(f1.x, wt, t0.z); t0.w = fmaf(f1.y, wt, t0.w);
    t1.x = fmaf(f2.x, wt, t1.x); t1.y = fmaf(f2.y, wt, t1.y);
    t1.z = fmaf(f3.x, wt, t1.z); t1.w = fmaf(f3.y, wt, t1.w);
}

// ============ prep: z fp32->fp16 + zero counts/cursors/dot-accums ============
__global__ void prep(const float* __restrict__ X, __half* __restrict__ Y,
                     int* __restrict__ cnt, int* __restrict__ cur,
                     float* __restrict__ a, float* __restrict__ b, int n)
{
    int i = blockIdx.x * blockDim.x + threadIdx.x;
    int total8 = n * 32;
    if (i < total8) {
        const float4* s = (const float4*)X + 2 * (size_t)i;
        float4 p = s[0], q = s[1];
        uint4 o;
        *(__half2*)&o.x = __floats2half2_rn(p.x, p.y);
        *(__half2*)&o.y = __floats2half2_rn(p.z, p.w);
        *(__half2*)&o.z = __floats2half2_rn(q.x, q.y);
        *(__half2*)&o.w = __floats2half2_rn(q.z, q.w);
        ((uint4*)Y)[i] = o;
    }
    if (i < TT * n) { cnt[i] = 0; cur[i] = 0; }
    if (i < 2 * TT * n) { a[i] = 0.f; b[i] = 0.f; }
}

// W[z][k][n] fp32 -> WT[z][n][k] fp16 (z = layer*3 + type)
__global__ void cvt_w(const float* __restrict__ Wa, const float* __restrict__ Wb,
                      __half* __restrict__ WT)
{
    __shared__ float tile[32][33];
    int z = blockIdx.z;
    const float* W = (z < TT ? Wa : Wb) + (size_t)(z % TT) * 65536;
    __half* O = WT + (size_t)z * 65536;
    int x  = blockIdx.x * 32 + threadIdx.x;
    int y0 = blockIdx.y * 32;
#pragma unroll
    for (int j = 0; j < 32; j += 8)
        tile[threadIdx.y + j][threadIdx.x] = W[(size_t)(y0 + threadIdx.y + j) * 256 + x];
    __syncthreads();
    int x2 = blockIdx.y * 32 + threadIdx.x;
    int y2 = blockIdx.x * 32;
#pragma unroll
    for (int j = 0; j < 32; j += 8)
        O[(size_t)(y2 + threadIdx.y + j) * 256 + x2] =
            __float2half_rn(tile[threadIdx.x][threadIdx.y + j]);
}

// ============ fused fp16 GEMM + attention dots (ldmatrix, BK=64) ============
#define PITCH  36
#define ATILE  (128 * PITCH)
#define BTILE  (128 * PITCH)
#define GSMEM  (2 * (ATILE + BTILE) * 4)   // 73728 B

#define LDSM_X4(r0, r1, r2, r3, addr) \
    asm volatile("ldmatrix.sync.aligned.m8n8.x4.shared.b16 {%0,%1,%2,%3}, [%4];" \
                 : "=r"(r0), "=r"(r1), "=r"(r2), "=r"(r3) : "r"(addr))

__global__ __launch_bounds__(256) void gemm_fused(
    const __half* __restrict__ X, const __half* __restrict__ WT,
    __half* __restrict__ Hcat,
    const float* __restrict__ as_full, const float* __restrict__ ad_full,
    float* __restrict__ as_out, float* __restrict__ ad_out, int nrows)
{
    extern __shared__ uint32_t dsm[];

    int tid  = threadIdx.x;
    int lane = tid & 31, warp = tid >> 5;
    int wm = warp >> 1, wn = warp & 1;
    int g  = lane >> 2, tig = lane & 3;
    int bm = blockIdx.x * 128;
    int t  = blockIdx.y >> 1;
    int bn = (blockIdx.y & 1) * 128;
    const __half* Wt = WT + (size_t)t * 65536;
    __half* Hout = Hcat + (size_t)t * nrows * 256;

    uint32_t smem0 = (uint32_t)__cvta_generic_to_shared(dsm);

    uint32_t offA[2], offB[4];
#pragma unroll
    for (int mm = 0; mm < 2; mm++)
        offA[mm] = (uint32_t)((wm * 32 + mm * 16 + (lane & 15)) * PITCH
                              + ((lane >> 4) << 2));
#pragma unroll
    for (int p = 0; p < 4; p++)
        offB[p] = (uint32_t)((wn * 64 + p * 16 + ((lane & 7) | ((lane >> 1) & 8))) * PITCH
                             + (((lane >> 3) & 1) << 2));

    auto stage = [&](int st, int k0) {
#pragma unroll
        for (int p = 0; p < 4; p++) {
            int i = tid + p * 256;
            int r = i >> 3, c = i & 7;
            uint32_t d = smem0 + (uint32_t)((st * ATILE + r * PITCH + c * 4) << 2);
            const __half* s = X + (size_t)(bm + r) * 256 + k0 + c * 8;
            int sz = (bm + r) < nrows ? 16 : 0;
            asm volatile("cp.async.ca.shared.global [%0], [%1], 16, %2;"
                         :: "r"(d), "l"(s), "r"(sz));
        }
#pragma unroll
        for (int p = 0; p < 4; p++) {
            int i = tid + p * 256;
            int r = i >> 3, c = i & 7;
            uint32_t d = smem0 + (uint32_t)((2 * ATILE + st * BTILE + r * PITCH + c * 4) << 2);
            const __half* s = Wt + (size_t)(bn + r) * 256 + k0 + c * 8;
            asm volatile("cp.async.ca.shared.global [%0], [%1], 16;"
                         :: "r"(d), "l"(s));
        }
        asm volatile("cp.async.commit_group;");
    };

    float acc[2][8][4];
#pragma unroll
    for (int a = 0; a < 2; a++)
#pragma unroll
        for (int b = 0; b < 8; b++)
#pragma unroll
            for (int c = 0; c < 4; c++) acc[a][b][c] = 0.f;

    stage(0, 0);
    for (int k0 = 0; k0 < 256; k0 += 64) {
        int cur = (k0 >> 6) & 1;
        if (k0 + 64 < 256) {
            stage(cur ^ 1, k0 + 64);
            asm volatile("cp.async.wait_group 1;");
        } else {
            asm volatile("cp.async.wait_group 0;");
        }
        __syncthreads();

        uint32_t abase = smem0 + (uint32_t)((cur * ATILE) << 2);
        uint32_t bbase = smem0 + (uint32_t)((2 * ATILE + cur * BTILE) << 2);
#pragma unroll
        for (int s = 0; s < 4; s++) {
            uint32_t kb = (uint32_t)(s * 8) << 2;
            uint32_t a[2][4], b[8][2];
#pragma unroll
            for (int mm = 0; mm < 2; mm++)
                LDSM_X4(a[mm][0], a[mm][1], a[mm][2], a[mm][3],
                        abase + (offA[mm] << 2) + kb);
#pragma unroll
            for (int p = 0; p < 4; p++)
                LDSM_X4(b[2 * p][0], b[2 * p][1], b[2 * p + 1][0], b[2 * p + 1][1],
                        bbase + (offB[p] << 2) + kb);
#pragma unroll
            for (int mm = 0; mm < 2; mm++)
#pragma unroll
                for (int nn = 0; nn < 8; nn++)
                    asm volatile(
                        "mma.sync.aligned.m16n8k16.row.col.f32.f16.f16.f32 "
                        "{%0,%1,%2,%3}, {%4,%5,%6,%7}, {%8,%9}, {%0,%1,%2,%3};"
                        : "+f"(acc[mm][nn][0]), "+f"(acc[mm][nn][1]),
                          "+f"(acc[mm][nn][2]), "+f"(acc[mm][nn][3])
                        : "r"(a[mm][0]), "r"(a[mm][1]), "r"(a[mm][2]), "r"(a[mm][3]),
                          "r"(b[nn][0]), "r"(b[nn][1]));
        }
        __syncthreads();
    }

#pragma unroll
    for (int mm = 0; mm < 2; mm++)
#pragma unroll
        for (int nn = 0; nn < 8; nn++) {
            int row = bm + wm * 32 + mm * 16 + g;
            int col = bn + wn * 64 + nn * 8 + 2 * tig;
            if (row < nrows)
                *(__half2*)(Hout + (size_t)row * 256 + col) =
                    __floats2half2_rn(acc[mm][nn][0], acc[mm][nn][1]);
            if (row + 8 < nrows)
                *(__half2*)(Hout + (size_t)(row + 8) * 256 + col) =
                    __floats2half2_rn(acc[mm][nn][2], acc[mm][nn][3]);
        }

    // ---- fused attention dots ----
    {
        const float* avs = as_full + t * 256;
        const float* avd = ad_full + t * 256;
        float ds[2][2] = {{0.f, 0.f}, {0.f, 0.f}};
        float dd[2][2] = {{0.f, 0.f}, {0.f, 0.f}};
#pragma unroll
        for (int mm = 0; mm < 2; mm++)
#pragma unroll
            for (int nn = 0; nn < 8; nn++) {
                int col = bn + wn * 64 + nn * 8 + 2 * tig;
                float a0 = __ldg(&avs[col]), a1 = __ldg(&avs[col + 1]);
                float d0 = __ldg(&avd[col]), d1 = __ldg(&avd[col + 1]);
                ds[mm][0] += acc[mm][nn][0] * a0 + acc[mm][nn][1] * a1;
                ds[mm][1] += acc[mm][nn][2] * a0 + acc[mm][nn][3] * a1;
                dd[mm][0] += acc[mm][nn][0] * d0 + acc[mm][nn][1] * d1;
                dd[mm][1] += acc[mm][nn][2] * d0 + acc[mm][nn][3] * d1;
            }
#pragma unroll
        for (int o = 1; o <= 2; o <<= 1)
#pragma unroll
            for (int mm = 0; mm < 2; mm++)
#pragma unroll
                for (int h = 0; h < 2; h++) {
                    ds[mm][h] += __shfl_xor_sync(0xffffffffu, ds[mm][h], o);
                    dd[mm][h] += __shfl_xor_sync(0xffffffffu, dd[mm][h], o);
                }
        if (tig == 0) {
            float* aso = as_out + (size_t)t * nrows;
            float* ado = ad_out + (size_t)t * nrows;
#pragma unroll
            for (int mm = 0; mm < 2; mm++)
#pragma unroll
                for (int h = 0; h < 2; h++) {
                    int row = bm + wm * 32 + mm * 16 + g + h * 8;
                    if (row < nrows) {
                        atomicAdd(&aso[row], ds[mm][h]);
                        atomicAdd(&ado[row], dd[mm][h]);
                    }
                }
        }
    }
}

// ============ CSR build (once; graph shared by both layers) ============
__global__ void hist_kernel(const int* __restrict__ ei, int* __restrict__ cnt,
                            int n, int ne)
{
    int i = blockIdx.x * blockDim.x + threadIdx.x;
    if (i >= TT * ne) return;
    int t = i / ne, e = i - t * ne;
    int d = ei[(size_t)t * 2 * ne + ne + e];
    atomicAdd(&cnt[t * n + d], 1);
}

__global__ __launch_bounds__(1024) void scan_off(
    const int* __restrict__ cnt, int* __restrict__ off, int n)
{
    int t = blockIdx.x;
    const int* c = cnt + t * n;
    int* o = off + t * (n + 1);
    __shared__ int wsum[32];
    __shared__ int carry_sh;
    int tid = threadIdx.x, lane = tid & 31, wid = tid >> 5;
    if (tid == 0) carry_sh = 0;
    __syncthreads();
    for (int base = 0; base < n; base += 1024) {
        int i = base + tid;
        int v = (i < n) ? c[i] : 0;
        int x = v;
#pragma unroll
        for (int o2 = 1; o2 < 32; o2 <<= 1) {
            int y = __shfl_up_sync(0xffffffffu, x, o2);
            if (lane >= o2) x += y;
        }
        if (lane == 31) wsum[wid] = x;
        __syncthreads();
        if (wid == 0) {
            int s = wsum[lane];
#pragma unroll
            for (int o2 = 1; o2 < 32; o2 <<= 1) {
                int y = __shfl_up_sync(0xffffffffu, s, o2);
                if (lane >= o2) s += y;
            }
            wsum[lane] = s;
        }
        __syncthreads();
        int incl  = x + (wid > 0 ? wsum[wid - 1] : 0);
        int carry = carry_sh;
        if (i < n) o[i] = carry + incl - v;
        __syncthreads();
        if (tid == 1023) carry_sh = carry + wsum[31];
        __syncthreads();
    }
    if (threadIdx.x == 0) o[n] = carry_sh;
}

__global__ void fill_kernel(const int* __restrict__ ei, const int* __restrict__ off,
                            int* __restrict__ cur, int* __restrict__ csr,
                            int n, int ne)
{
    int i = blockIdx.x * blockDim.x + threadIdx.x;
    if (i >= TT * ne) return;
    int t = i / ne, e = i - t * ne;
    const int* base = ei + (size_t)t * 2 * ne;
    int s = base[e], d = base[ne + e];
    int pos = off[t * (n + 1) + d] + atomicAdd(&cur[t * n + d], 1);
    csr[t * ne + pos] = s;
}

// ============ fused softmax + aggregate + bias + relu (+ head) : warp per dst ============
__global__ __launch_bounds__(256) void agg_kernel(
    const int* __restrict__ off, const int* __restrict__ csr,
    const __half* __restrict__ hcat, const float* __restrict__ asb,
    const float* __restrict__ adb, const float* __restrict__ bias,
    __half* __restrict__ outrow, const float* __restrict__ Wh,
    const float* __restrict__ bh, float* __restrict__ headout,
    int mode, int n, int ne)
{
    __shared__ int   s_sn[8][96];
    __shared__ float s_w[8][96];

    int wrp  = threadIdx.x >> 5;
    int w    = (blockIdx.x * blockDim.x + threadIdx.x) >> 5;
    int lane = threadIdx.x & 31;
    if (w >= n) return;

    float4 a0 = make_float4(0.f, 0.f, 0.f, 0.f);   // cols 8*lane .. +3
    float4 a1 = make_float4(0.f, 0.f, 0.f, 0.f);   // cols 8*lane+4 .. +7

    int o0[TT], dg[TT];
#pragma unroll
    for (int t = 0; t < TT; t++) {
        o0[t] = off[t * (n + 1) + w];
        dg[t] = off[t * (n + 1) + w + 1] - o0[t];
    }

    if (dg[0] <= 32 && dg[1] <= 32 && dg[2] <= 32) {
        // ---------- fast path ----------
        int cnt = 0;
#pragma unroll
        for (int t = 0; t < TT; t++) {
            if (dg[t] == 0) continue;
            float adt = adb[t * n + w];
            int   sj = 0;
            float ex = 0.f;
            if (lane < dg[t]) {
                sj = csr[(size_t)t * ne + o0[t] + lane];
                float e = asb[t * n + sj] + adt;
                e = e > 0.f ? e : 0.2f * e;       // leaky_relu 0.2
                ex = __expf(e);                    // shift-invariant
            }
            float s = ex;
#pragma unroll
            for (int o = 16; o; o >>= 1) s += __shfl_xor_sync(0xffffffffu, s, o);
            float inv = 1.f / s;
            if (lane < dg[t]) {
                s_sn[wrp][cnt + lane] = t * n + sj;   // global hcat row
                s_w[wrp][cnt + lane]  = ex * inv;     // pre-normalized alpha
            }
            cnt += dg[t];
        }
        __syncwarp();

        int i = 0;
        for (; i + 8 <= cnt; i += 8) {
            int   n0 = s_sn[wrp][i],     n1 = s_sn[wrp][i + 1];
            int   n2 = s_sn[wrp][i + 2], n3 = s_sn[wrp][i + 3];
            int   n4 = s_sn[wrp][i + 4], n5 = s_sn[wrp][i + 5];
            int   n6 = s_sn[wrp][i + 6], n7 = s_sn[wrp][i + 7];
            float q0 = s_w[wrp][i],     q1 = s_w[wrp][i + 1];
            float q2 = s_w[wrp][i + 2], q3 = s_w[wrp][i + 3];
            float q4 = s_w[wrp][i + 4], q5 = s_w[wrp][i + 5];
            float q6 = s_w[wrp][i + 6], q7 = s_w[wrp][i + 7];
            uint4 v0 = *(const uint4*)(hcat + (size_t)n0 * 256 + lane * 8);
            uint4 v1 = *(const uint4*)(hcat + (size_t)n1 * 256 + lane * 8);
            uint4 v2 = *(const uint4*)(hcat + (size_t)n2 * 256 + lane * 8);
            uint4 v3 = *(const uint4*)(hcat + (size_t)n3 * 256 + lane * 8);
            uint4 v4 = *(const uint4*)(hcat + (size_t)n4 * 256 + lane * 8);
            uint4 v5 = *(const uint4*)(hcat + (size_t)n5 * 256 + lane * 8);
            uint4 v6 = *(const uint4*)(hcat + (size_t)n6 * 256 + lane * 8);
            uint4 v7 = *(const uint4*)(hcat + (size_t)n7 * 256 + lane * 8);
            acc8(a0, a1, v0, q0); acc8(a0, a1, v1, q1);
            acc8(a0, a1, v2, q2); acc8(a0, a1, v3, q3);
            acc8(a0, a1, v4, q4); acc8(a0, a1, v5, q5);
            acc8(a0, a1, v6, q6); acc8(a0, a1, v7, q7);
        }
        for (; i + 4 <= cnt; i += 4) {
            int   n0 = s_sn[wrp][i],     n1 = s_sn[wrp][i + 1];
            int   n2 = s_sn[wrp][i + 2], n3 = s_sn[wrp][i + 3];
            float q0 = s_w[wrp][i],     q1 = s_w[wrp][i + 1];
            float q2 = s_w[wrp][i + 2], q3 = s_w[wrp][i + 3];
            uint4 v0 = *(const uint4*)(hcat + (size_t)n0 * 256 + lane * 8);
            uint4 v1 = *(const uint4*)(hcat + (size_t)n1 * 256 + lane * 8);
            uint4 v2 = *(const uint4*)(hcat + (size_t)n2 * 256 + lane * 8);
            uint4 v3 = *(const uint4*)(hcat + (size_t)n3 * 256 + lane * 8);
            acc8(a0, a1, v0, q0); acc8(a0, a1, v1, q1);
            acc8(a0, a1, v2, q2); acc8(a0, a1, v3, q3);
        }
        for (; i < cnt; i++) {
            int   n0 = s_sn[wrp][i];
            float q0 = s_w[wrp][i];
            uint4 v0 = *(const uint4*)(hcat + (size_t)n0 * 256 + lane * 8);
            acc8(a0, a1, v0, q0);
        }
    } else {
        // ---------- slow path (any deg > 32; rare) ----------
#pragma unroll
        for (int t = 0; t < TT; t++) {
            int deg = dg[t];
            if (deg == 0) continue;
            float adt = adb[t * n + w];
            const __half* ht  = hcat + (size_t)t * n * 256;
            const float* ast  = asb + t * n;
            const int*   srcs = csr + (size_t)t * ne + o0[t];
            float4 t0 = make_float4(0.f, 0.f, 0.f, 0.f);
            float4 t1 = make_float4(0.f, 0.f, 0.f, 0.f);
            float den = 0.f;
            for (int base = 0; base < deg; base += 32) {
                int m = min(32, deg - base);
                int   sj = 0;
                float ex = 0.f;
                if (lane < m) {
                    sj = srcs[base + lane];
                    float e = ast[sj] + adt;
                    e = e > 0.f ? e : 0.2f * e;
                    ex = __expf(e);
                }
                float s = ex;
#pragma unroll
                for (int o = 16; o; o >>= 1) s += __shfl_xor_sync(0xffffffffu, s, o);
                den += s;
                for (int j = 0; j < m; j++) {
                    int   sn = __shfl_sync(0xffffffffu, sj, j);
                    float wt = __shfl_sync(0xffffffffu, ex, j);
                    uint4 v = *(const uint4*)(ht + (size_t)sn * 256 + lane * 8);
                    acc8(t0, t1, v, wt);
                }
            }
            float inv = 1.f / den;
            a0 = f4fma(t0, inv, a0);
            a1 = f4fma(t1, inv, a1);
        }
    }

    // bias sum over the 3 types ([3][64] float4 view), cols 8*lane -> float4 idx 2*lane
    const float4* bb = (const float4*)bias;
    float4 b0 = f4add(f4add(__ldg(&bb[2 * lane]), __ldg(&bb[64 + 2 * lane])),
                      __ldg(&bb[128 + 2 * lane]));
    float4 b1 = f4add(f4add(__ldg(&bb[2 * lane + 1]), __ldg(&bb[64 + 2 * lane + 1])),
                      __ldg(&bb[128 + 2 * lane + 1]));
    float4 r0 = f4relu(f4add(a0, b0));
    float4 r1 = f4relu(f4add(a1, b1));

    if (mode == 0) {
        uint4 o;
        *(__half2*)&o.x = __floats2half2_rn(r0.x, r0.y);
        *(__half2*)&o.y = __floats2half2_rn(r0.z, r0.w);
        *(__half2*)&o.z = __floats2half2_rn(r1.x, r1.y);
        *(__half2*)&o.w = __floats2half2_rn(r1.z, r1.w);
        *(uint4*)(outrow + (size_t)w * 256 + lane * 8) = o;
    } else {
        const float4* wh = (const float4*)Wh;
        float4 q0 = __ldg(&wh[2 * lane]);
        float4 q1 = __ldg(&wh[2 * lane + 1]);
        float s = r0.x * q0.x + r0.y * q0.y + r0.z * q0.z + r0.w * q0.w +
                  r1.x * q1.x + r1.y * q1.y + r1.z * q1.z + r1.w * q1.w;
#pragma unroll
        for (int o = 16; o; o >>= 1) s += __shfl_xor_sync(0xffffffffu, s, o);
        if (lane == 0) headout[w] = 1.f / (1.f + __expf(-(s + bh[0])));
    }
}

// ---------------- host orchestration ----------------
extern "C" void kernel_launch(void* const* d_in, const int* in_sizes, int n_in,
                              void* d_out, int out_size)
{
    const float* z   = (const float*)d_in[0];
    const int*   ei  = (const int*)d_in[1];
    const float* W1  = (const float*)d_in[2];
    const float* as1 = (const float*)d_in[3];
    const float* ad1 = (const float*)d_in[4];
    const float* b1  = (const float*)d_in[5];
    const float* W2  = (const float*)d_in[6];
    const float* as2 = (const float*)d_in[7];
    const float* ad2 = (const float*)d_in[8];
    const float* b2  = (const float*)d_in[9];
    const float* Wh  = (const float*)d_in[10];
    const float* bh  = (const float*)d_in[11];
    float* out = (float*)d_out;

    int n  = in_sizes[0] / 256;   // 50000
    int ne = in_sizes[1] / 6;     // 250000

    void* p;
    cudaGetSymbolAddress(&p, g_hcat); __half* hcat = (__half*)p;
    cudaGetSymbolAddress(&p, g_h1);   __half* h1   = (__half*)p;
    cudaGetSymbolAddress(&p, g_z16);  __half* z16  = (__half*)p;
    cudaGetSymbolAddress(&p, g_wt16); __half* wt16 = (__half*)p;
    cudaGetSymbolAddress(&p, g_as);   float*  asb  = (float*)p;
    cudaGetSymbolAddress(&p, g_ad);   float*  adb  = (float*)p;
    cudaGetSymbolAddress(&p, g_cnt);  int*    cnt  = (int*)p;
    cudaGetSymbolAddress(&p, g_cur);  int*    cur  = (int*)p;
    cudaGetSymbolAddress(&p, g_off);  int*    off  = (int*)p;
    cudaGetSymbolAddress(&p, g_csr);  int*    csr  = (int*)p;

    cudaFuncSetAttribute(gemm_fused, cudaFuncAttributeMaxDynamicSharedMemorySize, GSMEM);

    // one-time side stream + fork/join events (host objects; created on the
    // correctness call, reused during graph capture)
    static cudaStream_t s_side = nullptr;
    static cudaEvent_t  ev_fork = nullptr, ev_join = nullptr;
    if (!s_side) {
        cudaStreamCreateWithFlags(&s_side, cudaStreamNonBlocking);
        cudaEventCreateWithFlags(&ev_fork, cudaEventDisableTiming);
        cudaEventCreateWithFlags(&ev_join, cudaEventDisableTiming);
    }
    cudaStream_t s0 = 0;

    dim3 ggrid((n + 127) / 128, 6);
    float* asb2 = asb + (size_t)TT * n;
    float* adb2 = adb + (size_t)TT * n;

    // main: prep(1), cvt_w(2) -> gemm1(4th submitted; ncu lands there)
    prep<<<(n * 32 + 255) / 256, 256, 0, s0>>>(z, z16, cnt, cur, asb, adb, n);
    cvt_w<<<dim3(8, 8, 2 * TT), dim3(32, 8), 0, s0>>>(W1, W2, wt16);

    // fork: CSR chain on the side stream, overlapped with layer-1 GEMM
    cudaEventRecord(ev_fork, s0);
    cudaStreamWaitEvent(s_side, ev_fork, 0);
    hist_kernel<<<(TT * ne + 255) / 256, 256, 0, s_side>>>(ei, cnt, n, ne);   // (3)

    gemm_fused<<<ggrid, 256, GSMEM, s0>>>(z16, wt16, hcat, as1, ad1, asb, adb, n); // (4)

    scan_off<<<TT, 1024, 0, s_side>>>(cnt, off, n);                           // (5)
    fill_kernel<<<(TT * ne + 255) / 256, 256, 0, s_side>>>(ei, off, cur, csr, n, ne); // (6)
    cudaEventRecord(ev_join, s_side);

    // join before aggregation
    cudaStreamWaitEvent(s0, ev_join, 0);
    agg_kernel<<<(n + 7) / 8, 256, 0, s0>>>(off, csr, hcat, asb, adb, b1,
                                            h1, Wh, bh, out, 0, n, ne);

    // ---- layer 2 ----
    gemm_fused<<<ggrid, 256, GSMEM, s0>>>(h1, wt16 + (size_t)TT * 65536, hcat,
                                          as2, ad2, asb2, adb2, n);
    agg_kernel<<<(n + 7) / 8, 256, 0, s0>>>(off, csr, hcat, asb2, adb2, b2,
                                            h1 /*unused in mode 1*/, Wh, bh, out, 1, n, ne);
}

// round 17
// speedup vs baseline: 1.8763x; 1.0705x over previous
#include <cuda_runtime.h>
#include <cuda_fp16.h>
#include <cstdint>

#define NMAX 50048
#define EMAX 250112
#define TT 3

// ---------------- scratch (static device globals; no allocation) ----------------
__device__ __half g_hcat[TT * NMAX * 256]; // per-type h = x @ W[t], fp16 (gather-only)
__device__ __half g_h1[NMAX * 256];        // layer-1 output (fp16: layer-2 GEMM input)
__device__ __half g_z16[NMAX * 256];       // z converted to fp16
__device__ __half g_wt16[2 * TT * 65536];  // W transposed+converted: [layer][t][n][k]
__device__ float  g_as[2 * TT * NMAX];     // a_src per layer/type (atomic-accumulated)
__device__ float  g_ad[2 * TT * NMAX];     // a_dst per layer/type
__device__ int    g_cnt[TT * NMAX];
__device__ int    g_cur[TT * NMAX];
__device__ int    g_off[TT * (NMAX + 1)];
__device__ int    g_csr[TT * EMAX];

// ---------------- small float4 helpers ----------------
__device__ __forceinline__ float4 f4add(float4 a, float4 b) {
    return make_float4(a.x + b.x, a.y + b.y, a.z + b.z, a.w + b.w);
}
__device__ __forceinline__ float4 f4fma(float4 a, float s, float4 c) {
    return make_float4(fmaf(a.x, s, c.x), fmaf(a.y, s, c.y),
                       fmaf(a.z, s, c.z), fmaf(a.w, s, c.w));
}
__device__ __forceinline__ float4 f4relu(float4 a) {
    return make_float4(fmaxf(a.x, 0.f), fmaxf(a.y, 0.f),
                       fmaxf(a.z, 0.f), fmaxf(a.w, 0.f));
}
__device__ __forceinline__ void acc8(float4& t0, float4& t1, uint4 v, float wt) {
    float2 f0 = __half22float2(*(__half2*)&v.x);
    float2 f1 = __half22float2(*(__half2*)&v.y);
    float2 f2 = __half22float2(*(__half2*)&v.z);
    float2 f3 = __half22float2(*(__half2*)&v.w);
    t0.x = fmaf(f0.x, wt, t0.x); t0.y = fmaf(f0.y, wt, t0.y);
    t0.z = fmaf(f1.x, wt, t0.z); t0.w = fmaf(f1.y, wt, t0.w);
    t1.x = fmaf(f2.x, wt, t1.x); t1.y = fmaf(f2.y, wt, t1.y);
    t1.z = fmaf(f3.x, wt, t1.z); t1.w = fmaf(f3.y, wt, t1.w);
}

// ============ prep: z fp32->fp16 + zero counts/cursors/dot-accums ============
__global__ void prep(const float* __restrict__ X, __half* __restrict__ Y,
                     int* __restrict__ cnt, int* __restrict__ cur,
                     float* __restrict__ a, float* __restrict__ b, int n)
{
    int i = blockIdx.x * blockDim.x + threadIdx.x;
    int total8 = n * 32;
    if (i < total8) {
        const float4* s = (const float4*)X + 2 * (size_t)i;
        float4 p = s[0], q = s[1];
        uint4 o;
        *(__half2*)&o.x = __floats2half2_rn(p.x, p.y);
        *(__half2*)&o.y = __floats2half2_rn(p.z, p.w);
        *(__half2*)&o.z = __floats2half2_rn(q.x, q.y);
        *(__half2*)&o.w = __floats2half2_rn(q.z, q.w);
        ((uint4*)Y)[i] = o;
    }
    if (i < TT * n) { cnt[i] = 0; cur[i] = 0; }
    if (i < 2 * TT * n) { a[i] = 0.f; b[i] = 0.f; }
}

// W[z][k][n] fp32 -> WT[z][n][k] fp16 (z = layer*3 + type)
__global__ void cvt_w(const float* __restrict__ Wa, const float* __restrict__ Wb,
                      __half* __restrict__ WT)
{
    __shared__ float tile[32][33];
    int z = blockIdx.z;
    const float* W = (z < TT ? Wa : Wb) + (size_t)(z % TT) * 65536;
    __half* O = WT + (size_t)z * 65536;
    int x  = blockIdx.x * 32 + threadIdx.x;
    int y0 = blockIdx.y * 32;
#pragma unroll
    for (int j = 0; j < 32; j += 8)
        tile[threadIdx.y + j][threadIdx.x] = W[(size_t)(y0 + threadIdx.y + j) * 256 + x];
    __syncthreads();
    int x2 = blockIdx.y * 32 + threadIdx.x;
    int y2 = blockIdx.x * 32;
#pragma unroll
    for (int j = 0; j < 32; j += 8)
        O[(size_t)(y2 + threadIdx.y + j) * 256 + x2] =
            __float2half_rn(tile[threadIdx.x][threadIdx.y + j]);
}

// ============ fused fp16 GEMM + attention dots (ldmatrix, BK=64) ============
#define PITCH  36
#define ATILE  (128 * PITCH)
#define BTILE  (128 * PITCH)
#define GSMEM  (2 * (ATILE + BTILE) * 4)   // 73728 B

#define LDSM_X4(r0, r1, r2, r3, addr) \
    asm volatile("ldmatrix.sync.aligned.m8n8.x4.shared.b16 {%0,%1,%2,%3}, [%4];" \
                 : "=r"(r0), "=r"(r1), "=r"(r2), "=r"(r3) : "r"(addr))

__global__ __launch_bounds__(256) void gemm_fused(
    const __half* __restrict__ X, const __half* __restrict__ WT,
    __half* __restrict__ Hcat,
    const float* __restrict__ as_full, const float* __restrict__ ad_full,
    float* __restrict__ as_out, float* __restrict__ ad_out, int nrows)
{
    extern __shared__ uint32_t dsm[];

    int tid  = threadIdx.x;
    int lane = tid & 31, warp = tid >> 5;
    int wm = warp >> 1, wn = warp & 1;
    int g  = lane >> 2, tig = lane & 3;
    int bm = blockIdx.x * 128;
    int t  = blockIdx.y >> 1;
    int bn = (blockIdx.y & 1) * 128;
    const __half* Wt = WT + (size_t)t * 65536;
    __half* Hout = Hcat + (size_t)t * nrows * 256;

    uint32_t smem0 = (uint32_t)__cvta_generic_to_shared(dsm);

    uint32_t offA[2], offB[4];
#pragma unroll
    for (int mm = 0; mm < 2; mm++)
        offA[mm] = (uint32_t)((wm * 32 + mm * 16 + (lane & 15)) * PITCH
                              + ((lane >> 4) << 2));
#pragma unroll
    for (int p = 0; p < 4; p++)
        offB[p] = (uint32_t)((wn * 64 + p * 16 + ((lane & 7) | ((lane >> 1) & 8))) * PITCH
                             + (((lane >> 3) & 1) << 2));

    auto stage = [&](int st, int k0) {
#pragma unroll
        for (int p = 0; p < 4; p++) {
            int i = tid + p * 256;
            int r = i >> 3, c = i & 7;
            uint32_t d = smem0 + (uint32_t)((st * ATILE + r * PITCH + c * 4) << 2);
            const __half* s = X + (size_t)(bm + r) * 256 + k0 + c * 8;
            int sz = (bm + r) < nrows ? 16 : 0;
            asm volatile("cp.async.ca.shared.global [%0], [%1], 16, %2;"
                         :: "r"(d), "l"(s), "r"(sz));
        }
#pragma unroll
        for (int p = 0; p < 4; p++) {
            int i = tid + p * 256;
            int r = i >> 3, c = i & 7;
            uint32_t d = smem0 + (uint32_t)((2 * ATILE + st * BTILE + r * PITCH + c * 4) << 2);
            const __half* s = Wt + (size_t)(bn + r) * 256 + k0 + c * 8;
            asm volatile("cp.async.ca.shared.global [%0], [%1], 16;"
                         :: "r"(d), "l"(s));
        }
        asm volatile("cp.async.commit_group;");
    };

    float acc[2][8][4];
#pragma unroll
    for (int a = 0; a < 2; a++)
#pragma unroll
        for (int b = 0; b < 8; b++)
#pragma unroll
            for (int c = 0; c < 4; c++) acc[a][b][c] = 0.f;

    stage(0, 0);
    for (int k0 = 0; k0 < 256; k0 += 64) {
        int cur = (k0 >> 6) & 1;
        if (k0 + 64 < 256) {
            stage(cur ^ 1, k0 + 64);
            asm volatile("cp.async.wait_group 1;");
        } else {
            asm volatile("cp.async.wait_group 0;");
        }
        __syncthreads();

        uint32_t abase = smem0 + (uint32_t)((cur * ATILE) << 2);
        uint32_t bbase = smem0 + (uint32_t)((2 * ATILE + cur * BTILE) << 2);
#pragma unroll
        for (int s = 0; s < 4; s++) {
            uint32_t kb = (uint32_t)(s * 8) << 2;
            uint32_t a[2][4], b[8][2];
#pragma unroll
            for (int mm = 0; mm < 2; mm++)
                LDSM_X4(a[mm][0], a[mm][1], a[mm][2], a[mm][3],
                        abase + (offA[mm] << 2) + kb);
#pragma unroll
            for (int p = 0; p < 4; p++)
                LDSM_X4(b[2 * p][0], b[2 * p][1], b[2 * p + 1][0], b[2 * p + 1][1],
                        bbase + (offB[p] << 2) + kb);
#pragma unroll
            for (int mm = 0; mm < 2; mm++)
#pragma unroll
                for (int nn = 0; nn < 8; nn++)
                    asm volatile(
                        "mma.sync.aligned.m16n8k16.row.col.f32.f16.f16.f32 "
                        "{%0,%1,%2,%3}, {%4,%5,%6,%7}, {%8,%9}, {%0,%1,%2,%3};"
                        : "+f"(acc[mm][nn][0]), "+f"(acc[mm][nn][1]),
                          "+f"(acc[mm][nn][2]), "+f"(acc[mm][nn][3])
                        : "r"(a[mm][0]), "r"(a[mm][1]), "r"(a[mm][2]), "r"(a[mm][3]),
                          "r"(b[nn][0]), "r"(b[nn][1]));
        }
        __syncthreads();
    }

#pragma unroll
    for (int mm = 0; mm < 2; mm++)
#pragma unroll
        for (int nn = 0; nn < 8; nn++) {
            int row = bm + wm * 32 + mm * 16 + g;
            int col = bn + wn * 64 + nn * 8 + 2 * tig;
            if (row < nrows)
                *(__half2*)(Hout + (size_t)row * 256 + col) =
                    __floats2half2_rn(acc[mm][nn][0], acc[mm][nn][1]);
            if (row + 8 < nrows)
                *(__half2*)(Hout + (size_t)(row + 8) * 256 + col) =
                    __floats2half2_rn(acc[mm][nn][2], acc[mm][nn][3]);
        }

    // ---- fused attention dots ----
    {
        const float* avs = as_full + t * 256;
        const float* avd = ad_full + t * 256;
        float ds[2][2] = {{0.f, 0.f}, {0.f, 0.f}};
        float dd[2][2] = {{0.f, 0.f}, {0.f, 0.f}};
#pragma unroll
        for (int mm = 0; mm < 2; mm++)
#pragma unroll
            for (int nn = 0; nn < 8; nn++) {
                int col = bn + wn * 64 + nn * 8 + 2 * tig;
                float a0 = __ldg(&avs[col]), a1 = __ldg(&avs[col + 1]);
                float d0 = __ldg(&avd[col]), d1 = __ldg(&avd[col + 1]);
                ds[mm][0] += acc[mm][nn][0] * a0 + acc[mm][nn][1] * a1;
                ds[mm][1] += acc[mm][nn][2] * a0 + acc[mm][nn][3] * a1;
                dd[mm][0] += acc[mm][nn][0] * d0 + acc[mm][nn][1] * d1;
                dd[mm][1] += acc[mm][nn][2] * d0 + acc[mm][nn][3] * d1;
            }
#pragma unroll
        for (int o = 1; o <= 2; o <<= 1)
#pragma unroll
            for (int mm = 0; mm < 2; mm++)
#pragma unroll
                for (int h = 0; h < 2; h++) {
                    ds[mm][h] += __shfl_xor_sync(0xffffffffu, ds[mm][h], o);
                    dd[mm][h] += __shfl_xor_sync(0xffffffffu, dd[mm][h], o);
                }
        if (tig == 0) {
            float* aso = as_out + (size_t)t * nrows;
            float* ado = ad_out + (size_t)t * nrows;
#pragma unroll
            for (int mm = 0; mm < 2; mm++)
#pragma unroll
                for (int h = 0; h < 2; h++) {
                    int row = bm + wm * 32 + mm * 16 + g + h * 8;
                    if (row < nrows) {
                        atomicAdd(&aso[row], ds[mm][h]);
                        atomicAdd(&ado[row], dd[mm][h]);
                    }
                }
        }
    }
}

// ============ CSR build (once; graph shared by both layers) ============
__global__ void hist_kernel(const int* __restrict__ ei, int* __restrict__ cnt,
                            int n, int ne)
{
    int i = blockIdx.x * blockDim.x + threadIdx.x;
    if (i >= TT * ne) return;
    int t = i / ne, e = i - t * ne;
    int d = ei[(size_t)t * 2 * ne + ne + e];
    atomicAdd(&cnt[t * n + d], 1);
}

__global__ __launch_bounds__(1024) void scan_off(
    const int* __restrict__ cnt, int* __restrict__ off, int n)
{
    int t = blockIdx.x;
    const int* c = cnt + t * n;
    int* o = off + t * (n + 1);
    __shared__ int wsum[32];
    __shared__ int carry_sh;
    int tid = threadIdx.x, lane = tid & 31, wid = tid >> 5;
    if (tid == 0) carry_sh = 0;
    __syncthreads();
    for (int base = 0; base < n; base += 1024) {
        int i = base + tid;
        int v = (i < n) ? c[i] : 0;
        int x = v;
#pragma unroll
        for (int o2 = 1; o2 < 32; o2 <<= 1) {
            int y = __shfl_up_sync(0xffffffffu, x, o2);
            if (lane >= o2) x += y;
        }
        if (lane == 31) wsum[wid] = x;
        __syncthreads();
        if (wid == 0) {
            int s = wsum[lane];
#pragma unroll
            for (int o2 = 1; o2 < 32; o2 <<= 1) {
                int y = __shfl_up_sync(0xffffffffu, s, o2);
                if (lane >= o2) s += y;
            }
            wsum[lane] = s;
        }
        __syncthreads();
        int incl  = x + (wid > 0 ? wsum[wid - 1] : 0);
        int carry = carry_sh;
        if (i < n) o[i] = carry + incl - v;
        __syncthreads();
        if (tid == 1023) carry_sh = carry + wsum[31];
        __syncthreads();
    }
    if (threadIdx.x == 0) o[n] = carry_sh;
}

__global__ void fill_kernel(const int* __restrict__ ei, const int* __restrict__ off,
                            int* __restrict__ cur, int* __restrict__ csr,
                            int n, int ne)
{
    int i = blockIdx.x * blockDim.x + threadIdx.x;
    if (i >= TT * ne) return;
    int t = i / ne, e = i - t * ne;
    const int* base = ei + (size_t)t * 2 * ne;
    int s = base[e], d = base[ne + e];
    int pos = off[t * (n + 1) + d] + atomicAdd(&cur[t * n + d], 1);
    csr[t * ne + pos] = s;
}

// ============ fused softmax + aggregate + bias + relu (+ head) : warp per dst ============
// Fast path prologue batched across types: all csr loads, then all score gathers
// (MLP=3 each), then 3 interleaved warp reductions.
__global__ __launch_bounds__(256) void agg_kernel(
    const int* __restrict__ off, const int* __restrict__ csr,
    const __half* __restrict__ hcat, const float* __restrict__ asb,
    const float* __restrict__ adb, const float* __restrict__ bias,
    __half* __restrict__ outrow, const float* __restrict__ Wh,
    const float* __restrict__ bh, float* __restrict__ headout,
    int mode, int n, int ne)
{
    __shared__ int   s_sn[8][96];
    __shared__ float s_w[8][96];

    int wrp  = threadIdx.x >> 5;
    int w    = (blockIdx.x * blockDim.x + threadIdx.x) >> 5;
    int lane = threadIdx.x & 31;
    if (w >= n) return;

    float4 a0 = make_float4(0.f, 0.f, 0.f, 0.f);   // cols 8*lane .. +3
    float4 a1 = make_float4(0.f, 0.f, 0.f, 0.f);   // cols 8*lane+4 .. +7

    int o0[TT], dg[TT];
#pragma unroll
    for (int t = 0; t < TT; t++) {
        o0[t] = off[t * (n + 1) + w];
        dg[t] = off[t * (n + 1) + w + 1] - o0[t];
    }

    if (dg[0] <= 32 && dg[1] <= 32 && dg[2] <= 32) {
        // ---------- fast path ----------
        // 1) batched independent loads: adb[t], csr rows (MLP=3)
        float adt[TT];
#pragma unroll
        for (int t = 0; t < TT; t++) adt[t] = adb[t * n + w];
        int sj[TT];
#pragma unroll
        for (int t = 0; t < TT; t++)
            sj[t] = (lane < dg[t]) ? csr[(size_t)t * ne + o0[t] + lane] : 0;
        // 2) batched dependent score gathers (MLP=3)
        float ex[TT];
#pragma unroll
        for (int t = 0; t < TT; t++) {
            float e = 0.f;
            if (lane < dg[t]) e = asb[t * n + sj[t]] + adt[t];
            e = e > 0.f ? e : 0.2f * e;            // leaky_relu 0.2
            ex[t] = (lane < dg[t]) ? __expf(e) : 0.f;   // shift-invariant
        }
        // 3) three interleaved warp reductions (independent shfl chains)
        float sum[TT] = {ex[0], ex[1], ex[2]};
#pragma unroll
        for (int o = 16; o; o >>= 1)
#pragma unroll
            for (int t = 0; t < TT; t++)
                sum[t] += __shfl_xor_sync(0xffffffffu, sum[t], o);
        // 4) stage pre-normalized weights + global rows
        int cnt = 0;
#pragma unroll
        for (int t = 0; t < TT; t++) {
            if (lane < dg[t]) {
                s_sn[wrp][cnt + lane] = t * n + sj[t];
                s_w[wrp][cnt + lane]  = ex[t] * (1.f / sum[t]);
            }
            cnt += dg[t];
        }
        __syncwarp();

        int i = 0;
        for (; i + 8 <= cnt; i += 8) {
            int   n0 = s_sn[wrp][i],     n1 = s_sn[wrp][i + 1];
            int   n2 = s_sn[wrp][i + 2], n3 = s_sn[wrp][i + 3];
            int   n4 = s_sn[wrp][i + 4], n5 = s_sn[wrp][i + 5];
            int   n6 = s_sn[wrp][i + 6], n7 = s_sn[wrp][i + 7];
            float q0 = s_w[wrp][i],     q1 = s_w[wrp][i + 1];
            float q2 = s_w[wrp][i + 2], q3 = s_w[wrp][i + 3];
            float q4 = s_w[wrp][i + 4], q5 = s_w[wrp][i + 5];
            float q6 = s_w[wrp][i + 6], q7 = s_w[wrp][i + 7];
            uint4 v0 = *(const uint4*)(hcat + (size_t)n0 * 256 + lane * 8);
            uint4 v1 = *(const uint4*)(hcat + (size_t)n1 * 256 + lane * 8);
            uint4 v2 = *(const uint4*)(hcat + (size_t)n2 * 256 + lane * 8);
            uint4 v3 = *(const uint4*)(hcat + (size_t)n3 * 256 + lane * 8);
            uint4 v4 = *(const uint4*)(hcat + (size_t)n4 * 256 + lane * 8);
            uint4 v5 = *(const uint4*)(hcat + (size_t)n5 * 256 + lane * 8);
            uint4 v6 = *(const uint4*)(hcat + (size_t)n6 * 256 + lane * 8);
            uint4 v7 = *(const uint4*)(hcat + (size_t)n7 * 256 + lane * 8);
            acc8(a0, a1, v0, q0); acc8(a0, a1, v1, q1);
            acc8(a0, a1, v2, q2); acc8(a0, a1, v3, q3);
            acc8(a0, a1, v4, q4); acc8(a0, a1, v5, q5);
            acc8(a0, a1, v6, q6); acc8(a0, a1, v7, q7);
        }
        for (; i + 4 <= cnt; i += 4) {
            int   n0 = s_sn[wrp][i],     n1 = s_sn[wrp][i + 1];
            int   n2 = s_sn[wrp][i + 2], n3 = s_sn[wrp][i + 3];
            float q0 = s_w[wrp][i],     q1 = s_w[wrp][i + 1];
            float q2 = s_w[wrp][i + 2], q3 = s_w[wrp][i + 3];
            uint4 v0 = *(const uint4*)(hcat + (size_t)n0 * 256 + lane * 8);
            uint4 v1 = *(const uint4*)(hcat + (size_t)n1 * 256 + lane * 8);
            uint4 v2 = *(const uint4*)(hcat + (size_t)n2 * 256 + lane * 8);
            uint4 v3 = *(const uint4*)(hcat + (size_t)n3 * 256 + lane * 8);
            acc8(a0, a1, v0, q0); acc8(a0, a1, v1, q1);
            acc8(a0, a1, v2, q2); acc8(a0, a1, v3, q3);
        }
        for (; i < cnt; i++) {
            int   n0 = s_sn[wrp][i];
            float q0 = s_w[wrp][i];
            uint4 v0 = *(const uint4*)(hcat + (size_t)n0 * 256 + lane * 8);
            acc8(a0, a1, v0, q0);
        }
    } else {
        // ---------- slow path (any deg > 32; rare) ----------
#pragma unroll
        for (int t = 0; t < TT; t++) {
            int deg = dg[t];
            if (deg == 0) continue;
            float adt = adb[t * n + w];
            const __half* ht  = hcat + (size_t)t * n * 256;
            const float* ast  = asb + t * n;
            const int*   srcs = csr + (size_t)t * ne + o0[t];
            float4 t0 = make_float4(0.f, 0.f, 0.f, 0.f);
            float4 t1 = make_float4(0.f, 0.f, 0.f, 0.f);
            float den = 0.f;
            for (int base = 0; base < deg; base += 32) {
                int m = min(32, deg - base);
                int   sj = 0;
                float ex = 0.f;
                if (lane < m) {
                    sj = srcs[base + lane];
                    float e = ast[sj] + adt;
                    e = e > 0.f ? e : 0.2f * e;
                    ex = __expf(e);
                }
                float s = ex;
#pragma unroll
                for (int o = 16; o; o >>= 1) s += __shfl_xor_sync(0xffffffffu, s, o);
                den += s;
                for (int j = 0; j < m; j++) {
                    int   sn = __shfl_sync(0xffffffffu, sj, j);
                    float wt = __shfl_sync(0xffffffffu, ex, j);
                    uint4 v = *(const uint4*)(ht + (size_t)sn * 256 + lane * 8);
                    acc8(t0, t1, v, wt);
                }
            }
            float inv = 1.f / den;
            a0 = f4fma(t0, inv, a0);
            a1 = f4fma(t1, inv, a1);
        }
    }

    // bias sum over the 3 types ([3][64] float4 view), cols 8*lane -> float4 idx 2*lane
    const float4* bb = (const float4*)bias;
    float4 b0 = f4add(f4add(__ldg(&bb[2 * lane]), __ldg(&bb[64 + 2 * lane])),
                      __ldg(&bb[128 + 2 * lane]));
    float4 b1 = f4add(f4add(__ldg(&bb[2 * lane + 1]), __ldg(&bb[64 + 2 * lane + 1])),
                      __ldg(&bb[128 + 2 * lane + 1]));
    float4 r0 = f4relu(f4add(a0, b0));
    float4 r1 = f4relu(f4add(a1, b1));

    if (mode == 0) {
        uint4 o;
        *(__half2*)&o.x = __floats2half2_rn(r0.x, r0.y);
        *(__half2*)&o.y = __floats2half2_rn(r0.z, r0.w);
        *(__half2*)&o.z = __floats2half2_rn(r1.x, r1.y);
        *(__half2*)&o.w = __floats2half2_rn(r1.z, r1.w);
        *(uint4*)(outrow + (size_t)w * 256 + lane * 8) = o;
    } else {
        const float4* wh = (const float4*)Wh;
        float4 q0 = __ldg(&wh[2 * lane]);
        float4 q1 = __ldg(&wh[2 * lane + 1]);
        float s = r0.x * q0.x + r0.y * q0.y + r0.z * q0.z + r0.w * q0.w +
                  r1.x * q1.x + r1.y * q1.y + r1.z * q1.z + r1.w * q1.w;
#pragma unroll
        for (int o = 16; o; o >>= 1) s += __shfl_xor_sync(0xffffffffu, s, o);
        if (lane == 0) headout[w] = 1.f / (1.f + __expf(-(s + bh[0])));
    }
}

// ---------------- host orchestration ----------------
extern "C" void kernel_launch(void* const* d_in, const int* in_sizes, int n_in,
                              void* d_out, int out_size)
{
    const float* z   = (const float*)d_in[0];
    const int*   ei  = (const int*)d_in[1];
    const float* W1  = (const float*)d_in[2];
    const float* as1 = (const float*)d_in[3];
    const float* ad1 = (const float*)d_in[4];
    const float* b1  = (const float*)d_in[5];
    const float* W2  = (const float*)d_in[6];
    const float* as2 = (const float*)d_in[7];
    const float* ad2 = (const float*)d_in[8];
    const float* b2  = (const float*)d_in[9];
    const float* Wh  = (const float*)d_in[10];
    const float* bh  = (const float*)d_in[11];
    float* out = (float*)d_out;

    int n  = in_sizes[0] / 256;   // 50000
    int ne = in_sizes[1] / 6;     // 250000

    void* p;
    cudaGetSymbolAddress(&p, g_hcat); __half* hcat = (__half*)p;
    cudaGetSymbolAddress(&p, g_h1);   __half* h1   = (__half*)p;
    cudaGetSymbolAddress(&p, g_z16);  __half* z16  = (__half*)p;
    cudaGetSymbolAddress(&p, g_wt16); __half* wt16 = (__half*)p;
    cudaGetSymbolAddress(&p, g_as);   float*  asb  = (float*)p;
    cudaGetSymbolAddress(&p, g_ad);   float*  adb  = (float*)p;
    cudaGetSymbolAddress(&p, g_cnt);  int*    cnt  = (int*)p;
    cudaGetSymbolAddress(&p, g_cur);  int*    cur  = (int*)p;
    cudaGetSymbolAddress(&p, g_off);  int*    off  = (int*)p;
    cudaGetSymbolAddress(&p, g_csr);  int*    csr  = (int*)p;

    cudaFuncSetAttribute(gemm_fused, cudaFuncAttributeMaxDynamicSharedMemorySize, GSMEM);

    // one-time side stream + fork/join events (host objects; created on the
    // correctness call, reused during graph capture)
    static cudaStream_t s_side = nullptr;
    static cudaEvent_t  ev_fork = nullptr, ev_join = nullptr;
    if (!s_side) {
        cudaStreamCreateWithFlags(&s_side, cudaStreamNonBlocking);
        cudaEventCreateWithFlags(&ev_fork, cudaEventDisableTiming);
        cudaEventCreateWithFlags(&ev_join, cudaEventDisableTiming);
    }
    cudaStream_t s0 = 0;

    dim3 ggrid((n + 127) / 128, 6);
    float* asb2 = asb + (size_t)TT * n;
    float* adb2 = adb + (size_t)TT * n;

    // main: prep(1), cvt_w(2) -> gemm1(4th submitted; ncu lands there)
    prep<<<(n * 32 + 255) / 256, 256, 0, s0>>>(z, z16, cnt, cur, asb, adb, n);
    cvt_w<<<dim3(8, 8, 2 * TT), dim3(32, 8), 0, s0>>>(W1, W2, wt16);

    // fork: CSR chain on the side stream, overlapped with layer-1 GEMM
    cudaEventRecord(ev_fork, s0);
    cudaStreamWaitEvent(s_side, ev_fork, 0);
    hist_kernel<<<(TT * ne + 255) / 256, 256, 0, s_side>>>(ei, cnt, n, ne);   // (3)

    gemm_fused<<<ggrid, 256, GSMEM, s0>>>(z16, wt16, hcat, as1, ad1, asb, adb, n); // (4)

    scan_off<<<TT, 1024, 0, s_side>>>(cnt, off, n);                           // (5)
    fill_kernel<<<(TT * ne + 255) / 256, 256, 0, s_side>>>(ei, off, cur, csr, n, ne); // (6)
    cudaEventRecord(ev_join, s_side);

    // join before aggregation
    cudaStreamWaitEvent(s0, ev_join, 0);
    agg_kernel<<<(n + 7) / 8, 256, 0, s0>>>(off, csr, hcat, asb, adb, b1,
                                            h1, Wh, bh, out, 0, n, ne);

    // ---- layer 2 ----
    gemm_fused<<<ggrid, 256, GSMEM, s0>>>(h1, wt16 + (size_t)TT * 65536, hcat,
                                          as2, ad2, asb2, adb2, n);
    agg_kernel<<<(n + 7) / 8, 256, 0, s0>>>(off, csr, hcat, asb2, adb2, b2,
                                            h1 /*unused in mode 1*/, Wh, bh, out, 1, n, ne);
}